// round 1
// baseline (speedup 1.0000x reference)
#include <cuda_runtime.h>
#include <math.h>

#define DD     1024
#define HH     2048
#define EE     8
#define NTOK   8192
#define KTOP   2
#define NP     (NTOK*KTOP)      // 16384 token-expert pairs
#define BM     128
#define MAXPAD (NP + EE*BM)     // 17408 (static worst-case padded rows)
#define MAXTILES (MAXPAD/BM)    // 136

// ---------------- device scratch (no allocations allowed) ----------------
__device__ int   g_pair_tok[MAXPAD];
__device__ float g_pair_w[MAXPAD];
__device__ int   g_pair_slot[NP];      // token,k -> slot
__device__ int   g_topk_idx[NP];
__device__ float g_topk_val[NP];
__device__ float g_scores[NTOK*EE];
__device__ int   g_counts[EE];
__device__ int   g_cursor[EE];
__device__ int   g_pstart[EE+1];
__device__ int   g_tile_expert[MAXTILES];
__device__ float g_h [(size_t)MAXPAD*HH];   // ~143 MB
__device__ float g_eo[(size_t)MAXPAD*DD];   // ~71 MB

// ---------------- init ----------------
__global__ void init_kernel() {
    int i = blockIdx.x*blockDim.x + threadIdx.x;
    if (i < MAXPAD) { g_pair_tok[i] = -1; g_pair_w[i] = 0.f; }
    if (i < EE)     { g_counts[i] = 0; g_cursor[i] = 0; }
}

// ---------------- gating: one warp per token ----------------
__global__ void gate_kernel(const float* __restrict__ x, const float* __restrict__ Wg) {
    int warp = threadIdx.x >> 5;
    int lane = threadIdx.x & 31;
    int n = blockIdx.x*8 + warp;
    if (n >= NTOK) return;

    const float* xr = x + (size_t)n*DD;
    float sc[EE];
    #pragma unroll
    for (int e = 0; e < EE; e++) {
        const float* wr = Wg + (size_t)e*DD;
        float p = 0.f;
        for (int d = lane; d < DD; d += 32) p += xr[d]*wr[d];
        #pragma unroll
        for (int off = 16; off; off >>= 1) p += __shfl_xor_sync(0xffffffffu, p, off);
        sc[e] = p;   // all lanes hold the sum
    }
    // softmax (all lanes redundantly)
    float m = sc[0];
    #pragma unroll
    for (int e = 1; e < EE; e++) m = fmaxf(m, sc[e]);
    float s = 0.f;
    float pr[EE];
    #pragma unroll
    for (int e = 0; e < EE; e++) { pr[e] = __expf(sc[e]-m); s += pr[e]; }
    float inv = 1.f/s;
    #pragma unroll
    for (int e = 0; e < EE; e++) pr[e] *= inv;

    // top-2, strict '>' keeps lowest index on ties (matches lax.top_k)
    int i1 = 0; float v1 = pr[0];
    #pragma unroll
    for (int e = 1; e < EE; e++) if (pr[e] > v1) { v1 = pr[e]; i1 = e; }
    int i2 = -1; float v2 = -1.f;
    #pragma unroll
    for (int e = 0; e < EE; e++) if (e != i1 && pr[e] > v2) { v2 = pr[e]; i2 = e; }

    if (lane == 0) {
        #pragma unroll
        for (int e = 0; e < EE; e++) g_scores[(size_t)n*EE + e] = pr[e];
        g_topk_idx[2*n]   = i1; g_topk_val[2*n]   = v1;
        g_topk_idx[2*n+1] = i2; g_topk_val[2*n+1] = v2;
        atomicAdd(&g_counts[i1], 1);
        atomicAdd(&g_counts[i2], 1);
    }
}

// ---------------- setup: padded offsets + tile->expert map ----------------
__global__ void setup_kernel() {
    int off = 0;
    for (int e = 0; e < EE; e++) {
        g_pstart[e] = off;
        off = (off + g_counts[e] + BM - 1)/BM*BM;
    }
    g_pstart[EE] = off;
    for (int t = 0; t < MAXTILES; t++) g_tile_expert[t] = -1;
    for (int e = 0; e < EE; e++) {
        int t0 = g_pstart[e]/BM;
        int t1 = (g_pstart[e] + g_counts[e] + BM - 1)/BM;
        for (int t = t0; t < t1; t++) g_tile_expert[t] = e;
    }
}

// ---------------- assign pairs into padded per-expert segments ----------------
__global__ void assign_kernel() {
    int n = blockIdx.x*blockDim.x + threadIdx.x;
    if (n >= NTOK) return;
    #pragma unroll
    for (int k = 0; k < KTOP; k++) {
        int e = g_topk_idx[2*n+k];
        int pos = atomicAdd(&g_cursor[e], 1);
        int slot = g_pstart[e] + pos;
        g_pair_tok[slot] = n;
        g_pair_w[slot]   = g_topk_val[2*n+k];
        g_pair_slot[2*n+k] = slot;
    }
}

// ---------------- GEMM1: h = silu(X@W1+b1) * (X@W3+b3), gathered rows ----------------
// BM=128 rows x BN=64 cols(H), BK=8. 256 thr, per-thread 8x4 for BOTH matrices.
__global__ void __launch_bounds__(256) gemm1_kernel(
    const float* __restrict__ x,
    const float* __restrict__ W1, const float* __restrict__ b1,
    const float* __restrict__ W3, const float* __restrict__ b3)
{
    int e = g_tile_expert[blockIdx.y];
    if (e < 0) return;
    int row0 = blockIdx.y * BM;
    int n0   = blockIdx.x * 64;

    __shared__ float Xs[8][132];
    __shared__ float W1s[8][64];
    __shared__ float W3s[8][64];
    __shared__ int   s_tok[BM];

    int tid = threadIdx.x;
    if (tid < BM) s_tok[tid] = g_pair_tok[row0 + tid];
    __syncthreads();

    const float* W1e = W1 + (size_t)e*DD*HH;
    const float* W3e = W3 + (size_t)e*DD*HH;

    int lrow = tid >> 1, lkq = tid & 1;           // X tile loader
    int wkk  = (tid & 127) >> 4, wnq = tid & 15;  // W tile loader
    int xtok = s_tok[lrow];
    const float* xrow = (xtok >= 0) ? x + (size_t)xtok*DD : 0;

    int tx = tid & 15, ty = tid >> 4;

    float acc1[8][4], acc3[8][4];
    #pragma unroll
    for (int i = 0; i < 8; i++)
        #pragma unroll
        for (int j = 0; j < 4; j++) { acc1[i][j] = 0.f; acc3[i][j] = 0.f; }

    for (int k0 = 0; k0 < DD; k0 += 8) {
        float4 xv = make_float4(0.f,0.f,0.f,0.f);
        if (xrow) xv = *(const float4*)(xrow + k0 + lkq*4);
        float4 wv;
        if (tid < 128) wv = *(const float4*)(W1e + (size_t)(k0+wkk)*HH + n0 + wnq*4);
        else           wv = *(const float4*)(W3e + (size_t)(k0+wkk)*HH + n0 + wnq*4);

        __syncthreads();
        Xs[lkq*4+0][lrow] = xv.x; Xs[lkq*4+1][lrow] = xv.y;
        Xs[lkq*4+2][lrow] = xv.z; Xs[lkq*4+3][lrow] = xv.w;
        if (tid < 128) {
            W1s[wkk][wnq*4+0] = wv.x; W1s[wkk][wnq*4+1] = wv.y;
            W1s[wkk][wnq*4+2] = wv.z; W1s[wkk][wnq*4+3] = wv.w;
        } else {
            W3s[wkk][wnq*4+0] = wv.x; W3s[wkk][wnq*4+1] = wv.y;
            W3s[wkk][wnq*4+2] = wv.z; W3s[wkk][wnq*4+3] = wv.w;
        }
        __syncthreads();

        #pragma unroll
        for (int kk = 0; kk < 8; kk++) {
            float a[8], f1[4], f3[4];
            *(float4*)&a[0] = *(const float4*)&Xs[kk][ty*4];
            *(float4*)&a[4] = *(const float4*)&Xs[kk][64 + ty*4];
            *(float4*)&f1[0] = *(const float4*)&W1s[kk][tx*4];
            *(float4*)&f3[0] = *(const float4*)&W3s[kk][tx*4];
            #pragma unroll
            for (int i = 0; i < 8; i++)
                #pragma unroll
                for (int j = 0; j < 4; j++) {
                    acc1[i][j] += a[i]*f1[j];
                    acc3[i][j] += a[i]*f3[j];
                }
        }
    }

    float bb1[4], bb3[4];
    #pragma unroll
    for (int j = 0; j < 4; j++) {
        int c = n0 + tx*4 + j;
        bb1[j] = b1[e*HH + c];
        bb3[j] = b3[e*HH + c];
    }
    #pragma unroll
    for (int i = 0; i < 8; i++) {
        int lr = (i < 4) ? (ty*4 + i) : (64 + ty*4 + i - 4);
        int r  = row0 + lr;
        float hv[4];
        #pragma unroll
        for (int j = 0; j < 4; j++) {
            float z1 = acc1[i][j] + bb1[j];
            float z3 = acc3[i][j] + bb3[j];
            float sv = z1 / (1.f + __expf(-z1));
            hv[j] = sv * z3;
        }
        *(float4*)(g_h + (size_t)r*HH + n0 + tx*4) = *(float4*)hv;
    }
}

// ---------------- GEMM2: eo = (h @ W2 + b2) * route_weight ----------------
// BM=128 x BN=128(D), BK=8. 256 thr, per-thread 8x8.
__global__ void __launch_bounds__(256) gemm2_kernel(
    const float* __restrict__ W2, const float* __restrict__ b2)
{
    int e = g_tile_expert[blockIdx.y];
    if (e < 0) return;
    int row0 = blockIdx.y * BM;
    int n0   = blockIdx.x * 128;

    __shared__ float Hs[8][132];
    __shared__ float Ws[8][132];
    __shared__ float s_w[BM];

    int tid = threadIdx.x;
    if (tid < BM) s_w[tid] = g_pair_w[row0 + tid];
    __syncthreads();

    const float* W2e = W2 + (size_t)e*HH*DD;

    int lrow = tid >> 1, lkq = tid & 1;   // H tile loader
    int wkk  = tid >> 5, wnq = tid & 31;  // W2 tile loader
    const float* hrow = g_h + (size_t)(row0 + lrow)*HH;

    int tx = tid & 15, ty = tid >> 4;

    float acc[8][8];
    #pragma unroll
    for (int i = 0; i < 8; i++)
        #pragma unroll
        for (int j = 0; j < 8; j++) acc[i][j] = 0.f;

    for (int k0 = 0; k0 < HH; k0 += 8) {
        float4 hv = *(const float4*)(hrow + k0 + lkq*4);
        float4 wv = *(const float4*)(W2e + (size_t)(k0+wkk)*DD + n0 + wnq*4);

        __syncthreads();
        Hs[lkq*4+0][lrow] = hv.x; Hs[lkq*4+1][lrow] = hv.y;
        Hs[lkq*4+2][lrow] = hv.z; Hs[lkq*4+3][lrow] = hv.w;
        Ws[wkk][wnq*4+0] = wv.x; Ws[wkk][wnq*4+1] = wv.y;
        Ws[wkk][wnq*4+2] = wv.z; Ws[wkk][wnq*4+3] = wv.w;
        __syncthreads();

        #pragma unroll
        for (int kk = 0; kk < 8; kk++) {
            float a[8], b[8];
            *(float4*)&a[0] = *(const float4*)&Hs[kk][ty*4];
            *(float4*)&a[4] = *(const float4*)&Hs[kk][64 + ty*4];
            *(float4*)&b[0] = *(const float4*)&Ws[kk][tx*4];
            *(float4*)&b[4] = *(const float4*)&Ws[kk][64 + tx*4];
            #pragma unroll
            for (int i = 0; i < 8; i++)
                #pragma unroll
                for (int j = 0; j < 8; j++) acc[i][j] += a[i]*b[j];
        }
    }

    float bb2[8];
    #pragma unroll
    for (int j = 0; j < 8; j++) {
        int c = n0 + ((j < 4) ? (tx*4 + j) : (64 + tx*4 + j - 4));
        bb2[j] = b2[e*DD + c];
    }
    #pragma unroll
    for (int i = 0; i < 8; i++) {
        int lr = (i < 4) ? (ty*4 + i) : (64 + ty*4 + i - 4);
        int r  = row0 + lr;
        float w = s_w[lr];
        float v0[4], v1[4];
        #pragma unroll
        for (int j = 0; j < 4; j++) v0[j] = (acc[i][j]   + bb2[j])   * w;
        #pragma unroll
        for (int j = 0; j < 4; j++) v1[j] = (acc[i][j+4] + bb2[j+4]) * w;
        *(float4*)(g_eo + (size_t)r*DD + n0 + tx*4)      = *(float4*)v0;
        *(float4*)(g_eo + (size_t)r*DD + n0 + 64 + tx*4) = *(float4*)v1;
    }
}

// ---------------- combine: y[n] = eo[slot(n,0)] + eo[slot(n,1)] ----------------
__global__ void combine_kernel(float* __restrict__ out) {
    int idx = blockIdx.x*blockDim.x + threadIdx.x;    // over NTOK * (DD/4)
    int n = idx >> 8;                                  // DD/4 = 256
    int q = idx & 255;
    if (n >= NTOK) return;
    int p0 = g_pair_slot[2*n];
    int p1 = g_pair_slot[2*n+1];
    const float4* eo = (const float4*)g_eo;
    float4 a = eo[(size_t)p0*256 + q];
    float4 b = eo[(size_t)p1*256 + q];
    float4 r = make_float4(a.x+b.x, a.y+b.y, a.z+b.z, a.w+b.w);
    ((float4*)out)[idx] = r;
}

// ---------------- aux loss (deterministic fixed-order reduction) ----------------
__global__ void aux_kernel(float* __restrict__ out, int has_aux) {
    __shared__ float red[64];
    int tid = threadIdx.x;
    int e = tid & 7;
    float p = 0.f;
    for (int n = tid >> 3; n < NTOK; n += 8) p += g_scores[(size_t)n*EE + e];
    red[tid] = p;
    __syncthreads();
    for (int s = 32; s >= 8; s >>= 1) {
        if (tid < s) red[tid] += red[tid + s];
        __syncthreads();
    }
    if (tid == 0 && has_aux) {
        float aux = 0.f;
        for (int ee = 0; ee < EE; ee++) {
            float f = (float)g_counts[ee] / (float)(NTOK*KTOP);
            float P = red[ee] / (float)NTOK;
            aux += f*P;
        }
        out[(size_t)NTOK*DD] = 0.01f * (float)EE * aux;
    }
}

// ---------------- launch ----------------
extern "C" void kernel_launch(void* const* d_in, const int* in_sizes, int n_in,
                              void* d_out, int out_size) {
    const float* x  = (const float*)d_in[0];
    const float* Wg = (const float*)d_in[1];
    const float* W1 = (const float*)d_in[2];
    const float* b1 = (const float*)d_in[3];
    const float* W2 = (const float*)d_in[4];
    const float* b2 = (const float*)d_in[5];
    const float* W3 = (const float*)d_in[6];
    const float* b3 = (const float*)d_in[7];
    float* out = (float*)d_out;

    init_kernel<<<(MAXPAD + 255)/256, 256>>>();
    gate_kernel<<<NTOK/8, 256>>>(x, Wg);
    setup_kernel<<<1, 1>>>();
    assign_kernel<<<NTOK/256, 256>>>();
    gemm1_kernel<<<dim3(HH/64,  MAXTILES), 256>>>(x, W1, b1, W3, b3);
    gemm2_kernel<<<dim3(DD/128, MAXTILES), 256>>>(W2, b2);
    combine_kernel<<<(NTOK*(DD/4))/256, 256>>>(out);
    aux_kernel<<<1, 64>>>(out, out_size > NTOK*DD ? 1 : 0);
}

// round 3
// speedup vs baseline: 1.9254x; 1.9254x over previous
#include <cuda_runtime.h>
#include <cuda_bf16.h>
#include <math.h>
#include <stdint.h>

#define DD     1024
#define HH     2048
#define EE     8
#define NTOK   8192
#define KTOP   2
#define NP     (NTOK*KTOP)      // 16384
#define BM     128
#define MAXPAD (NP + EE*BM)     // 17408
#define MAXTILES (MAXPAD/BM)    // 136

#define STRB   80               // smem row stride bytes (32 bf16 = 64B data + 16B pad)
#define TILEB  (128*STRB)       // 10240 bytes per 128-row tile

// ---------------- device scratch ----------------
__device__ int   g_pair_tok[MAXPAD];
__device__ float g_pair_w[MAXPAD];
__device__ int   g_pair_slot[NP];
__device__ int   g_topk_idx[NP];
__device__ float g_topk_val[NP];
__device__ float g_scores[NTOK*EE];
__device__ int   g_counts[EE];
__device__ int   g_cursor[EE];
__device__ int   g_pstart[EE+1];
__device__ int   g_tile_expert[MAXTILES];

__device__ __align__(16) __nv_bfloat16 g_xg_hi[(size_t)MAXPAD*DD];
__device__ __align__(16) __nv_bfloat16 g_xg_lo[(size_t)MAXPAD*DD];
__device__ __align__(16) __nv_bfloat16 g_w1t_hi[(size_t)EE*HH*DD];  // [E][H][D]
__device__ __align__(16) __nv_bfloat16 g_w1t_lo[(size_t)EE*HH*DD];
__device__ __align__(16) __nv_bfloat16 g_w3t_hi[(size_t)EE*HH*DD];
__device__ __align__(16) __nv_bfloat16 g_w3t_lo[(size_t)EE*HH*DD];
__device__ __align__(16) __nv_bfloat16 g_w2t_hi[(size_t)EE*DD*HH];  // [E][D][H]
__device__ __align__(16) __nv_bfloat16 g_w2t_lo[(size_t)EE*DD*HH];
__device__ __align__(16) __nv_bfloat16 g_h_hi[(size_t)MAXPAD*HH];
__device__ __align__(16) __nv_bfloat16 g_h_lo[(size_t)MAXPAD*HH];
__device__ __align__(16) float g_eo[(size_t)MAXPAD*DD];

// ---------------- PTX helpers (baseline PTX only: sm_80-class) ----------------
__device__ __forceinline__ uint32_t smem_u32(const void* p){
    uint32_t a;
    asm("{ .reg .u64 t; cvta.to.shared.u64 t, %1; cvt.u32.u64 %0, t; }" : "=r"(a) : "l"(p));
    return a;
}
__device__ __forceinline__ void cpasync16(uint32_t dst, const void* src){
    asm volatile("cp.async.cg.shared.global [%0], [%1], 16;" :: "r"(dst), "l"(src));
}
#define CP_COMMIT() asm volatile("cp.async.commit_group;" ::: "memory")
#define CP_WAIT2()  asm volatile("cp.async.wait_group 2;" ::: "memory")

__device__ __forceinline__ void ldmx4(uint32_t (&r)[4], uint32_t addr){
    asm volatile("ldmatrix.sync.aligned.m8n8.x4.shared.b16 {%0,%1,%2,%3}, [%4];"
        : "=r"(r[0]), "=r"(r[1]), "=r"(r[2]), "=r"(r[3]) : "r"(addr));
}
__device__ __forceinline__ void mma16816(float (&c)[4], const uint32_t (&a)[4],
                                         uint32_t b0, uint32_t b1){
    asm volatile(
        "mma.sync.aligned.m16n8k16.row.col.f32.bf16.bf16.f32 "
        "{%0,%1,%2,%3}, {%4,%5,%6,%7}, {%8,%9}, {%0,%1,%2,%3};"
        : "+f"(c[0]), "+f"(c[1]), "+f"(c[2]), "+f"(c[3])
        : "r"(a[0]), "r"(a[1]), "r"(a[2]), "r"(a[3]), "r"(b0), "r"(b1));
}

// ---------------- init ----------------
__global__ void init_kernel() {
    int i = blockIdx.x*blockDim.x + threadIdx.x;
    if (i < MAXPAD) { g_pair_tok[i] = -1; g_pair_w[i] = 0.f; }
    if (i < EE)     { g_counts[i] = 0; g_cursor[i] = 0; }
}

// ---------------- gating: one warp per token ----------------
__global__ void gate_kernel(const float* __restrict__ x, const float* __restrict__ Wg) {
    int warp = threadIdx.x >> 5;
    int lane = threadIdx.x & 31;
    int n = blockIdx.x*8 + warp;
    if (n >= NTOK) return;

    const float* xr = x + (size_t)n*DD;
    float sc[EE];
    #pragma unroll
    for (int e = 0; e < EE; e++) {
        const float* wr = Wg + (size_t)e*DD;
        float p = 0.f;
        for (int d = lane; d < DD; d += 32) p += xr[d]*wr[d];
        #pragma unroll
        for (int off = 16; off; off >>= 1) p += __shfl_xor_sync(0xffffffffu, p, off);
        sc[e] = p;
    }
    float m = sc[0];
    #pragma unroll
    for (int e = 1; e < EE; e++) m = fmaxf(m, sc[e]);
    float s = 0.f, pr[EE];
    #pragma unroll
    for (int e = 0; e < EE; e++) { pr[e] = __expf(sc[e]-m); s += pr[e]; }
    float inv = 1.f/s;
    #pragma unroll
    for (int e = 0; e < EE; e++) pr[e] *= inv;

    int i1 = 0; float v1 = pr[0];
    #pragma unroll
    for (int e = 1; e < EE; e++) if (pr[e] > v1) { v1 = pr[e]; i1 = e; }
    int i2 = -1; float v2 = -1.f;
    #pragma unroll
    for (int e = 0; e < EE; e++) if (e != i1 && pr[e] > v2) { v2 = pr[e]; i2 = e; }

    if (lane == 0) {
        #pragma unroll
        for (int e = 0; e < EE; e++) g_scores[(size_t)n*EE + e] = pr[e];
        g_topk_idx[2*n]   = i1; g_topk_val[2*n]   = v1;
        g_topk_idx[2*n+1] = i2; g_topk_val[2*n+1] = v2;
        atomicAdd(&g_counts[i1], 1);
        atomicAdd(&g_counts[i2], 1);
    }
}

// ---------------- setup ----------------
__global__ void setup_kernel() {
    int off = 0;
    for (int e = 0; e < EE; e++) {
        g_pstart[e] = off;
        off = (off + g_counts[e] + BM - 1)/BM*BM;
    }
    g_pstart[EE] = off;
    for (int t = 0; t < MAXTILES; t++) g_tile_expert[t] = -1;
    for (int e = 0; e < EE; e++) {
        int t0 = g_pstart[e]/BM;
        int t1 = (g_pstart[e] + g_counts[e] + BM - 1)/BM;
        for (int t = t0; t < t1; t++) g_tile_expert[t] = e;
    }
}

// ---------------- assign ----------------
__global__ void assign_kernel() {
    int n = blockIdx.x*blockDim.x + threadIdx.x;
    if (n >= NTOK) return;
    #pragma unroll
    for (int k = 0; k < KTOP; k++) {
        int e = g_topk_idx[2*n+k];
        int pos = atomicAdd(&g_cursor[e], 1);
        int slot = g_pstart[e] + pos;
        g_pair_tok[slot] = n;
        g_pair_w[slot]   = g_topk_val[2*n+k];
        g_pair_slot[2*n+k] = slot;
    }
}

// ---------------- gather + bf16 hi/lo split of x ----------------
__global__ void gatherx_kernel(const float* __restrict__ x) {
    int slot = blockIdx.x;
    int tok = g_pair_tok[slot];
    int t = threadIdx.x;               // 0..255, float4 index
    float4 v = make_float4(0.f,0.f,0.f,0.f);
    if (tok >= 0) v = ((const float4*)(x + (size_t)tok*DD))[t];
    float a[4] = {v.x, v.y, v.z, v.w};
    __nv_bfloat16 hi[4], lo[4];
    #pragma unroll
    for (int i = 0; i < 4; i++) {
        hi[i] = __float2bfloat16(a[i]);
        lo[i] = __float2bfloat16(a[i] - __bfloat162float(hi[i]));
    }
    __nv_bfloat162* dh = (__nv_bfloat162*)(g_xg_hi + (size_t)slot*DD) + 2*t;
    __nv_bfloat162* dl = (__nv_bfloat162*)(g_xg_lo + (size_t)slot*DD) + 2*t;
    __nv_bfloat162 p;
    p.x = hi[0]; p.y = hi[1]; dh[0] = p;
    p.x = hi[2]; p.y = hi[3]; dh[1] = p;
    p.x = lo[0]; p.y = lo[1]; dl[0] = p;
    p.x = lo[2]; p.y = lo[3]; dl[1] = p;
}

// ---------------- transpose-convert W1/W3: [E][D][H] -> [E][H][D] bf16 hi/lo ----------------
__global__ void convw13_kernel(const float* __restrict__ W1, const float* __restrict__ W3) {
    __shared__ float t[32][33];
    int m = blockIdx.z & 1, e = blockIdx.z >> 1;
    const float* src = (m ? W3 : W1) + (size_t)e*DD*HH;
    __nv_bfloat16* dhi = (m ? g_w3t_hi : g_w1t_hi) + (size_t)e*HH*DD;
    __nv_bfloat16* dlo = (m ? g_w3t_lo : g_w1t_lo) + (size_t)e*HH*DD;
    int h0 = blockIdx.x*32, d0 = blockIdx.y*32;
    int tx = threadIdx.x, ty = threadIdx.y;   // 32x8
    #pragma unroll
    for (int k = 0; k < 32; k += 8)
        t[ty+k][tx] = src[(size_t)(d0+ty+k)*HH + h0 + tx];
    __syncthreads();
    #pragma unroll
    for (int k = 0; k < 32; k += 8) {
        float v = t[tx][ty+k];
        __nv_bfloat16 hi = __float2bfloat16(v);
        dhi[(size_t)(h0+ty+k)*DD + d0 + tx] = hi;
        dlo[(size_t)(h0+ty+k)*DD + d0 + tx] = __float2bfloat16(v - __bfloat162float(hi));
    }
}

// ---------------- transpose-convert W2: [E][H][D] -> [E][D][H] bf16 hi/lo ----------------
__global__ void convw2_kernel(const float* __restrict__ W2) {
    __shared__ float t[32][33];
    int e = blockIdx.z;
    const float* src = W2 + (size_t)e*HH*DD;
    __nv_bfloat16* dhi = g_w2t_hi + (size_t)e*DD*HH;
    __nv_bfloat16* dlo = g_w2t_lo + (size_t)e*DD*HH;
    int d0 = blockIdx.x*32, h0 = blockIdx.y*32;
    int tx = threadIdx.x, ty = threadIdx.y;
    #pragma unroll
    for (int k = 0; k < 32; k += 8)
        t[ty+k][tx] = src[(size_t)(h0+ty+k)*DD + d0 + tx];
    __syncthreads();
    #pragma unroll
    for (int k = 0; k < 32; k += 8) {
        float v = t[tx][ty+k];
        __nv_bfloat16 hi = __float2bfloat16(v);
        dhi[(size_t)(d0+ty+k)*HH + h0 + tx] = hi;
        dlo[(size_t)(d0+ty+k)*HH + h0 + tx] = __float2bfloat16(v - __bfloat162float(hi));
    }
}

// ============================================================================
// GEMM1 (mma.sync bf16, hi/lo split):
//   z1 = X @ W1t^T, z3 = X @ W3t^T;  h = silu(z1+b1)*(z3+b3) -> bf16 hi/lo
// CTA: 128(M) x 128(N of H), BK=32, 3-stage cp.async pipeline.
// 8 warps as 2(M) x 4(N); warp tile 64x32.
// smem tiles (per stage, 6): A_hi, A_lo, W1h, W1l, W3h, W3l; row stride 80B.
// ============================================================================
__global__ void __launch_bounds__(256) gemm1_kernel(const float* __restrict__ b1,
                                                    const float* __restrict__ b3) {
    int e = g_tile_expert[blockIdx.y];
    if (e < 0) return;
    int row0 = blockIdx.y * BM;
    int n0   = blockIdx.x * 128;

    extern __shared__ __align__(1024) char smem[];
    uint32_t sb = smem_u32(smem);

    int tid  = threadIdx.x;
    int lane = tid & 31;
    int wid  = tid >> 5;
    int wm   = wid >> 2;      // 0..1
    int wn   = wid & 3;       // 0..3

    size_t aoff = (size_t)row0*DD;
    size_t woff = ((size_t)e*HH + n0)*DD;
    const __nv_bfloat16* s0 = g_xg_hi  + aoff;
    const __nv_bfloat16* s1 = g_xg_lo  + aoff;
    const __nv_bfloat16* s2 = g_w1t_hi + woff;
    const __nv_bfloat16* s3 = g_w1t_lo + woff;
    const __nv_bfloat16* s4 = g_w3t_hi + woff;
    const __nv_bfloat16* s5 = g_w3t_lo + woff;

    // per-thread loader coords: 2 halves x 6 tiles; idx in [0,512): row=idx>>2, kc=idx&3
    #define G1_LOAD(stage, it) do { \
        uint32_t bs = sb + (uint32_t)(stage)*(6*TILEB); \
        int k0 = (it)*32; \
        _Pragma("unroll") \
        for (int half = 0; half < 2; half++) { \
            int idx = half*256 + tid; \
            int row = idx >> 2, kc = idx & 3; \
            uint32_t so = (uint32_t)row*STRB + kc*16; \
            size_t gi = (size_t)row*DD + k0 + kc*8; \
            cpasync16(bs + 0*TILEB + so, s0 + gi); \
            cpasync16(bs + 1*TILEB + so, s1 + gi); \
            cpasync16(bs + 2*TILEB + so, s2 + gi); \
            cpasync16(bs + 3*TILEB + so, s3 + gi); \
            cpasync16(bs + 4*TILEB + so, s4 + gi); \
            cpasync16(bs + 5*TILEB + so, s5 + gi); \
        } \
    } while (0)

    float acc1[4][4][4], acc3[4][4][4];
    #pragma unroll
    for (int i = 0; i < 4; i++)
        #pragma unroll
        for (int j = 0; j < 4; j++)
            #pragma unroll
            for (int q = 0; q < 4; q++) { acc1[i][j][q] = 0.f; acc3[i][j][q] = 0.f; }

    int lr = (lane & 7) + 8*((lane >> 3) & 1);   // 0..15
    int lk = (lane >> 4) * 16;                   // 0 or 16 (bytes)

    const int NIT = DD/32;   // 32
    G1_LOAD(0, 0); CP_COMMIT();
    G1_LOAD(1, 1); CP_COMMIT();

    for (int it = 0; it < NIT; it++) {
        if (it + 2 < NIT) G1_LOAD((it+2)%3, it+2);
        CP_COMMIT();
        CP_WAIT2();
        __syncthreads();

        uint32_t bs = sb + (uint32_t)(it%3)*(6*TILEB);
        uint32_t aAh = bs + 0*TILEB + (uint32_t)(wm*64 + lr)*STRB + lk;
        uint32_t aAl = bs + 1*TILEB + (uint32_t)(wm*64 + lr)*STRB + lk;
        uint32_t aB  =      (uint32_t)(wn*32 + lr)*STRB + lk;

        #pragma unroll
        for (int h16 = 0; h16 < 2; h16++) {
            uint32_t ko = h16*32;
            uint32_t Ah[4][4], Al[4][4];
            #pragma unroll
            for (int mt = 0; mt < 4; mt++) {
                ldmx4(Ah[mt], aAh + mt*(16*STRB) + ko);
                ldmx4(Al[mt], aAl + mt*(16*STRB) + ko);
            }
            // W1
            #pragma unroll
            for (int np = 0; np < 2; np++) {
                uint32_t bh[4], bl[4];
                ldmx4(bh, bs + 2*TILEB + aB + np*(16*STRB) + ko);
                ldmx4(bl, bs + 3*TILEB + aB + np*(16*STRB) + ko);
                #pragma unroll
                for (int s = 0; s < 2; s++) {
                    int nt = np*2 + s;
                    #pragma unroll
                    for (int mt = 0; mt < 4; mt++) {
                        mma16816(acc1[mt][nt], Ah[mt], bh[s], bh[2+s]);
                        mma16816(acc1[mt][nt], Ah[mt], bl[s], bl[2+s]);
                        mma16816(acc1[mt][nt], Al[mt], bh[s], bh[2+s]);
                    }
                }
            }
            // W3
            #pragma unroll
            for (int np = 0; np < 2; np++) {
                uint32_t bh[4], bl[4];
                ldmx4(bh, bs + 4*TILEB + aB + np*(16*STRB) + ko);
                ldmx4(bl, bs + 5*TILEB + aB + np*(16*STRB) + ko);
                #pragma unroll
                for (int s = 0; s < 2; s++) {
                    int nt = np*2 + s;
                    #pragma unroll
                    for (int mt = 0; mt < 4; mt++) {
                        mma16816(acc3[mt][nt], Ah[mt], bh[s], bh[2+s]);
                        mma16816(acc3[mt][nt], Ah[mt], bl[s], bl[2+s]);
                        mma16816(acc3[mt][nt], Al[mt], bh[s], bh[2+s]);
                    }
                }
            }
        }
        __syncthreads();
    }

    // epilogue: h = silu(z1+b1)*(z3+b3), split to bf16 hi/lo
    int qrow = lane >> 2, qcol = lane & 3;
    #pragma unroll
    for (int nt = 0; nt < 4; nt++) {
        int col = n0 + wn*32 + nt*8 + qcol*2;
        float2 bb1 = *(const float2*)(b1 + e*HH + col);
        float2 bb3 = *(const float2*)(b3 + e*HH + col);
        #pragma unroll
        for (int mt = 0; mt < 4; mt++) {
            #pragma unroll
            for (int hrow = 0; hrow < 2; hrow++) {
                int r = row0 + wm*64 + mt*16 + qrow + hrow*8;
                float z1a = acc1[mt][nt][2*hrow]   + bb1.x;
                float z1b = acc1[mt][nt][2*hrow+1] + bb1.y;
                float z3a = acc3[mt][nt][2*hrow]   + bb3.x;
                float z3b = acc3[mt][nt][2*hrow+1] + bb3.y;
                float ha = (z1a / (1.f + __expf(-z1a))) * z3a;
                float hb = (z1b / (1.f + __expf(-z1b))) * z3b;
                __nv_bfloat16 hia = __float2bfloat16(ha);
                __nv_bfloat16 hib = __float2bfloat16(hb);
                __nv_bfloat16 loa = __float2bfloat16(ha - __bfloat162float(hia));
                __nv_bfloat16 lob = __float2bfloat16(hb - __bfloat162float(hib));
                __nv_bfloat162 ph; ph.x = hia; ph.y = hib;
                __nv_bfloat162 pl; pl.x = loa; pl.y = lob;
                *reinterpret_cast<__nv_bfloat162*>(g_h_hi + (size_t)r*HH + col) = ph;
                *reinterpret_cast<__nv_bfloat162*>(g_h_lo + (size_t)r*HH + col) = pl;
            }
        }
    }
}

// ============================================================================
// GEMM2 (mma.sync bf16, hi/lo split): eo = (h @ W2t^T + b2) * route_w
// CTA: 128 x 128(D), BK=32, 3-stage cp.async. Warp tile 64x32.
// smem tiles (per stage, 4): H_hi, H_lo, W2h, W2l.
// ============================================================================
__global__ void __launch_bounds__(256) gemm2_kernel(const float* __restrict__ b2) {
    int e = g_tile_expert[blockIdx.y];
    if (e < 0) return;
    int row0 = blockIdx.y * BM;
    int n0   = blockIdx.x * 128;

    extern __shared__ __align__(1024) char smem[];
    uint32_t sb = smem_u32(smem);

    int tid  = threadIdx.x;
    int lane = tid & 31;
    int wid  = tid >> 5;
    int wm   = wid >> 2;
    int wn   = wid & 3;

    size_t aoff = (size_t)row0*HH;
    size_t woff = ((size_t)e*DD + n0)*HH;
    const __nv_bfloat16* s0 = g_h_hi   + aoff;
    const __nv_bfloat16* s1 = g_h_lo   + aoff;
    const __nv_bfloat16* s2 = g_w2t_hi + woff;
    const __nv_bfloat16* s3 = g_w2t_lo + woff;

    #define G2_LOAD(stage, it) do { \
        uint32_t bs = sb + (uint32_t)(stage)*(4*TILEB); \
        int k0 = (it)*32; \
        _Pragma("unroll") \
        for (int half = 0; half < 2; half++) { \
            int idx = half*256 + tid; \
            int row = idx >> 2, kc = idx & 3; \
            uint32_t so = (uint32_t)row*STRB + kc*16; \
            size_t gi = (size_t)row*HH + k0 + kc*8; \
            cpasync16(bs + 0*TILEB + so, s0 + gi); \
            cpasync16(bs + 1*TILEB + so, s1 + gi); \
            cpasync16(bs + 2*TILEB + so, s2 + gi); \
            cpasync16(bs + 3*TILEB + so, s3 + gi); \
        } \
    } while (0)

    float acc[4][4][4];
    #pragma unroll
    for (int i = 0; i < 4; i++)
        #pragma unroll
        for (int j = 0; j < 4; j++)
            #pragma unroll
            for (int q = 0; q < 4; q++) acc[i][j][q] = 0.f;

    int lr = (lane & 7) + 8*((lane >> 3) & 1);
    int lk = (lane >> 4) * 16;

    const int NIT = HH/32;   // 64
    G2_LOAD(0, 0); CP_COMMIT();
    G2_LOAD(1, 1); CP_COMMIT();

    for (int it = 0; it < NIT; it++) {
        if (it + 2 < NIT) G2_LOAD((it+2)%3, it+2);
        CP_COMMIT();
        CP_WAIT2();
        __syncthreads();

        uint32_t bs = sb + (uint32_t)(it%3)*(4*TILEB);
        uint32_t aAh = bs + 0*TILEB + (uint32_t)(wm*64 + lr)*STRB + lk;
        uint32_t aAl = bs + 1*TILEB + (uint32_t)(wm*64 + lr)*STRB + lk;
        uint32_t aB  =      (uint32_t)(wn*32 + lr)*STRB + lk;

        #pragma unroll
        for (int h16 = 0; h16 < 2; h16++) {
            uint32_t ko = h16*32;
            uint32_t Ah[4][4], Al[4][4];
            #pragma unroll
            for (int mt = 0; mt < 4; mt++) {
                ldmx4(Ah[mt], aAh + mt*(16*STRB) + ko);
                ldmx4(Al[mt], aAl + mt*(16*STRB) + ko);
            }
            #pragma unroll
            for (int np = 0; np < 2; np++) {
                uint32_t bh[4], bl[4];
                ldmx4(bh, bs + 2*TILEB + aB + np*(16*STRB) + ko);
                ldmx4(bl, bs + 3*TILEB + aB + np*(16*STRB) + ko);
                #pragma unroll
                for (int s = 0; s < 2; s++) {
                    int nt = np*2 + s;
                    #pragma unroll
                    for (int mt = 0; mt < 4; mt++) {
                        mma16816(acc[mt][nt], Ah[mt], bh[s], bh[2+s]);
                        mma16816(acc[mt][nt], Ah[mt], bl[s], bl[2+s]);
                        mma16816(acc[mt][nt], Al[mt], bh[s], bh[2+s]);
                    }
                }
            }
        }
        __syncthreads();
    }

    // epilogue: (acc + b2) * route_w
    int qrow = lane >> 2, qcol = lane & 3;
    #pragma unroll
    for (int mt = 0; mt < 4; mt++) {
        #pragma unroll
        for (int hrow = 0; hrow < 2; hrow++) {
            int r = row0 + wm*64 + mt*16 + qrow + hrow*8;
            float wv = g_pair_w[r];
            #pragma unroll
            for (int nt = 0; nt < 4; nt++) {
                int col = n0 + wn*32 + nt*8 + qcol*2;
                float2 bb = *(const float2*)(b2 + e*DD + col);
                float2 o;
                o.x = (acc[mt][nt][2*hrow]   + bb.x) * wv;
                o.y = (acc[mt][nt][2*hrow+1] + bb.y) * wv;
                *(float2*)(g_eo + (size_t)r*DD + col) = o;
            }
        }
    }
}

// ---------------- combine ----------------
__global__ void combine_kernel(float* __restrict__ out) {
    int idx = blockIdx.x*blockDim.x + threadIdx.x;
    int n = idx >> 8;
    int q = idx & 255;
    if (n >= NTOK) return;
    int p0 = g_pair_slot[2*n];
    int p1 = g_pair_slot[2*n+1];
    const float4* eo = (const float4*)g_eo;
    float4 a = eo[(size_t)p0*256 + q];
    float4 b = eo[(size_t)p1*256 + q];
    ((float4*)out)[idx] = make_float4(a.x+b.x, a.y+b.y, a.z+b.z, a.w+b.w);
}

// ---------------- aux loss ----------------
__global__ void aux_kernel(float* __restrict__ out, int has_aux) {
    __shared__ float red[64];
    int tid = threadIdx.x;
    int e = tid & 7;
    float p = 0.f;
    for (int n = tid >> 3; n < NTOK; n += 8) p += g_scores[(size_t)n*EE + e];
    red[tid] = p;
    __syncthreads();
    for (int s = 32; s >= 8; s >>= 1) {
        if (tid < s) red[tid] += red[tid + s];
        __syncthreads();
    }
    if (tid == 0 && has_aux) {
        float aux = 0.f;
        for (int ee = 0; ee < EE; ee++) {
            float f = (float)g_counts[ee] / (float)(NTOK*KTOP);
            float P = red[ee] / (float)NTOK;
            aux += f*P;
        }
        out[(size_t)NTOK*DD] = 0.01f * (float)EE * aux;
    }
}

// ---------------- launch ----------------
extern "C" void kernel_launch(void* const* d_in, const int* in_sizes, int n_in,
                              void* d_out, int out_size) {
    const float* x  = (const float*)d_in[0];
    const float* Wg = (const float*)d_in[1];
    const float* W1 = (const float*)d_in[2];
    const float* b1 = (const float*)d_in[3];
    const float* W2 = (const float*)d_in[4];
    const float* b2 = (const float*)d_in[5];
    const float* W3 = (const float*)d_in[6];
    const float* b3 = (const float*)d_in[7];
    float* out = (float*)d_out;

    const int G1_SMEM = 3*6*TILEB;   // 184320
    const int G2_SMEM = 3*4*TILEB;   // 122880
    cudaFuncSetAttribute(gemm1_kernel, cudaFuncAttributeMaxDynamicSharedMemorySize, G1_SMEM);
    cudaFuncSetAttribute(gemm2_kernel, cudaFuncAttributeMaxDynamicSharedMemorySize, G2_SMEM);

    init_kernel<<<(MAXPAD + 255)/256, 256>>>();
    gate_kernel<<<NTOK/8, 256>>>(x, Wg);
    setup_kernel<<<1, 1>>>();
    assign_kernel<<<NTOK/256, 256>>>();
    gatherx_kernel<<<MAXPAD, 256>>>(x);
    convw13_kernel<<<dim3(HH/32, DD/32, EE*2), dim3(32, 8)>>>(W1, W3);
    convw2_kernel<<<dim3(DD/32, HH/32, EE), dim3(32, 8)>>>(W2);
    gemm1_kernel<<<dim3(HH/128, MAXTILES), 256, G1_SMEM>>>(b1, b3);
    gemm2_kernel<<<dim3(DD/128, MAXTILES), 256, G2_SMEM>>>(b2);
    combine_kernel<<<(NTOK*(DD/4))/256, 256>>>(out);
    aux_kernel<<<1, 64>>>(out, out_size > NTOK*DD ? 1 : 0);
}

// round 4
// speedup vs baseline: 2.6602x; 1.3817x over previous
#include <cuda_runtime.h>
#include <cuda_bf16.h>
#include <cuda_fp16.h>
#include <math.h>
#include <stdint.h>

#define DD     1024
#define HH     2048
#define EE     8
#define NTOK   8192
#define KTOP   2
#define NP     (NTOK*KTOP)      // 16384
#define BM     128
#define MAXPAD (NP + EE*BM)     // 17408
#define MAXTILES (MAXPAD/BM)    // 136

#define STRB   80               // smem row stride bytes (32 fp16 = 64B data + 16B pad)
#define TILEB  (128*STRB)       // 10240 bytes per 128-row tile

// ---------------- device scratch ----------------
__device__ int   g_pair_tok[MAXPAD];
__device__ float g_pair_w[MAXPAD];
__device__ int   g_pair_slot[NP];
__device__ int   g_topk_idx[NP];
__device__ float g_topk_val[NP];
__device__ float g_scores[NTOK*EE];
__device__ int   g_counts[EE];
__device__ int   g_cursor[EE];
__device__ int   g_pstart[EE+1];
__device__ int   g_tile_expert[MAXTILES];

__device__ __align__(16) __half g_xg    [(size_t)MAXPAD*DD];      // fp16 hi of x (gathered)
__device__ __align__(16) __half g_w1t_hi[(size_t)EE*HH*DD];       // [E][H][D]
__device__ __align__(16) __half g_w1t_lo[(size_t)EE*HH*DD];       // (w - hi)*2^10
__device__ __align__(16) __half g_w3t_hi[(size_t)EE*HH*DD];
__device__ __align__(16) __half g_w3t_lo[(size_t)EE*HH*DD];
__device__ __align__(16) __half g_w2t_hi[(size_t)EE*DD*HH];       // [E][D][H]
__device__ __align__(16) __half g_w2t_lo[(size_t)EE*DD*HH];
__device__ __align__(16) __half g_h     [(size_t)MAXPAD*HH];      // fp16 h
__device__ __align__(16) float  g_eo    [(size_t)MAXPAD*DD];

// ---------------- PTX helpers (baseline PTX only: sm_80-class) ----------------
__device__ __forceinline__ uint32_t smem_u32(const void* p){
    uint32_t a;
    asm("{ .reg .u64 t; cvta.to.shared.u64 t, %1; cvt.u32.u64 %0, t; }" : "=r"(a) : "l"(p));
    return a;
}
__device__ __forceinline__ void cpasync16(uint32_t dst, const void* src){
    asm volatile("cp.async.cg.shared.global [%0], [%1], 16;" :: "r"(dst), "l"(src));
}
#define CP_COMMIT() asm volatile("cp.async.commit_group;" ::: "memory")
#define CP_WAIT2()  asm volatile("cp.async.wait_group 2;" ::: "memory")

__device__ __forceinline__ void ldmx4(uint32_t (&r)[4], uint32_t addr){
    asm volatile("ldmatrix.sync.aligned.m8n8.x4.shared.b16 {%0,%1,%2,%3}, [%4];"
        : "=r"(r[0]), "=r"(r[1]), "=r"(r[2]), "=r"(r[3]) : "r"(addr));
}
__device__ __forceinline__ void mma16816(float (&c)[4], const uint32_t (&a)[4],
                                         uint32_t b0, uint32_t b1){
    asm volatile(
        "mma.sync.aligned.m16n8k16.row.col.f32.f16.f16.f32 "
        "{%0,%1,%2,%3}, {%4,%5,%6,%7}, {%8,%9}, {%0,%1,%2,%3};"
        : "+f"(c[0]), "+f"(c[1]), "+f"(c[2]), "+f"(c[3])
        : "r"(a[0]), "r"(a[1]), "r"(a[2]), "r"(a[3]), "r"(b0), "r"(b1));
}
// multiply packed fp16x2 by 2^-10 (0x1400) — exact exponent shift for normal values
__device__ __forceinline__ uint32_t hscale(uint32_t v){
    uint32_t r;
    asm("mul.rn.f16x2 %0, %1, %2;" : "=r"(r) : "r"(v), "r"(0x14001400u));
    return r;
}

// ---------------- init ----------------
__global__ void init_kernel() {
    int i = blockIdx.x*blockDim.x + threadIdx.x;
    if (i < MAXPAD) { g_pair_tok[i] = -1; g_pair_w[i] = 0.f; }
    if (i < EE)     { g_counts[i] = 0; g_cursor[i] = 0; }
}

// ---------------- gating: one warp per token ----------------
__global__ void gate_kernel(const float* __restrict__ x, const float* __restrict__ Wg) {
    int warp = threadIdx.x >> 5;
    int lane = threadIdx.x & 31;
    int n = blockIdx.x*8 + warp;
    if (n >= NTOK) return;

    const float* xr = x + (size_t)n*DD;
    float sc[EE];
    #pragma unroll
    for (int e = 0; e < EE; e++) {
        const float* wr = Wg + (size_t)e*DD;
        float p = 0.f;
        for (int d = lane; d < DD; d += 32) p += xr[d]*wr[d];
        #pragma unroll
        for (int off = 16; off; off >>= 1) p += __shfl_xor_sync(0xffffffffu, p, off);
        sc[e] = p;
    }
    float m = sc[0];
    #pragma unroll
    for (int e = 1; e < EE; e++) m = fmaxf(m, sc[e]);
    float s = 0.f, pr[EE];
    #pragma unroll
    for (int e = 0; e < EE; e++) { pr[e] = __expf(sc[e]-m); s += pr[e]; }
    float inv = 1.f/s;
    #pragma unroll
    for (int e = 0; e < EE; e++) pr[e] *= inv;

    int i1 = 0; float v1 = pr[0];
    #pragma unroll
    for (int e = 1; e < EE; e++) if (pr[e] > v1) { v1 = pr[e]; i1 = e; }
    int i2 = -1; float v2 = -1.f;
    #pragma unroll
    for (int e = 0; e < EE; e++) if (e != i1 && pr[e] > v2) { v2 = pr[e]; i2 = e; }

    if (lane == 0) {
        #pragma unroll
        for (int e = 0; e < EE; e++) g_scores[(size_t)n*EE + e] = pr[e];
        g_topk_idx[2*n]   = i1; g_topk_val[2*n]   = v1;
        g_topk_idx[2*n+1] = i2; g_topk_val[2*n+1] = v2;
        atomicAdd(&g_counts[i1], 1);
        atomicAdd(&g_counts[i2], 1);
    }
}

// ---------------- setup ----------------
__global__ void setup_kernel() {
    int off = 0;
    for (int e = 0; e < EE; e++) {
        g_pstart[e] = off;
        off = (off + g_counts[e] + BM - 1)/BM*BM;
    }
    g_pstart[EE] = off;
    for (int t = 0; t < MAXTILES; t++) g_tile_expert[t] = -1;
    for (int e = 0; e < EE; e++) {
        int t0 = g_pstart[e]/BM;
        int t1 = (g_pstart[e] + g_counts[e] + BM - 1)/BM;
        for (int t = t0; t < t1; t++) g_tile_expert[t] = e;
    }
}

// ---------------- assign ----------------
__global__ void assign_kernel() {
    int n = blockIdx.x*blockDim.x + threadIdx.x;
    if (n >= NTOK) return;
    #pragma unroll
    for (int k = 0; k < KTOP; k++) {
        int e = g_topk_idx[2*n+k];
        int pos = atomicAdd(&g_cursor[e], 1);
        int slot = g_pstart[e] + pos;
        g_pair_tok[slot] = n;
        g_pair_w[slot]   = g_topk_val[2*n+k];
        g_pair_slot[2*n+k] = slot;
    }
}

// ---------------- gather x -> fp16 ----------------
__global__ void gatherx_kernel(const float* __restrict__ x) {
    int slot = blockIdx.x;
    int tok = g_pair_tok[slot];
    int t = threadIdx.x;               // 0..255, float4 index
    float4 v = make_float4(0.f,0.f,0.f,0.f);
    if (tok >= 0) v = ((const float4*)(x + (size_t)tok*DD))[t];
    __half2* dh = (__half2*)(g_xg + (size_t)slot*DD) + 2*t;
    dh[0] = __floats2half2_rn(v.x, v.y);
    dh[1] = __floats2half2_rn(v.z, v.w);
}

// ---------------- transpose-convert W1/W3: [E][D][H] -> [E][H][D] fp16 hi/lo' ----------------
__global__ void convw13_kernel(const float* __restrict__ W1, const float* __restrict__ W3) {
    __shared__ float t[32][33];
    int m = blockIdx.z & 1, e = blockIdx.z >> 1;
    const float* src = (m ? W3 : W1) + (size_t)e*DD*HH;
    __half* dhi = (m ? g_w3t_hi : g_w1t_hi) + (size_t)e*HH*DD;
    __half* dlo = (m ? g_w3t_lo : g_w1t_lo) + (size_t)e*HH*DD;
    int h0 = blockIdx.x*32, d0 = blockIdx.y*32;
    int tx = threadIdx.x, ty = threadIdx.y;   // 32x8
    #pragma unroll
    for (int k = 0; k < 32; k += 8)
        t[ty+k][tx] = src[(size_t)(d0+ty+k)*HH + h0 + tx];
    __syncthreads();
    #pragma unroll
    for (int k = 0; k < 32; k += 8) {
        float v = t[tx][ty+k];
        __half hi = __float2half_rn(v);
        dhi[(size_t)(h0+ty+k)*DD + d0 + tx] = hi;
        dlo[(size_t)(h0+ty+k)*DD + d0 + tx] = __float2half_rn((v - __half2float(hi))*1024.f);
    }
}

// ---------------- transpose-convert W2: [E][H][D] -> [E][D][H] fp16 hi/lo' ----------------
__global__ void convw2_kernel(const float* __restrict__ W2) {
    __shared__ float t[32][33];
    int e = blockIdx.z;
    const float* src = W2 + (size_t)e*HH*DD;
    __half* dhi = g_w2t_hi + (size_t)e*DD*HH;
    __half* dlo = g_w2t_lo + (size_t)e*DD*HH;
    int d0 = blockIdx.x*32, h0 = blockIdx.y*32;
    int tx = threadIdx.x, ty = threadIdx.y;
    #pragma unroll
    for (int k = 0; k < 32; k += 8)
        t[ty+k][tx] = src[(size_t)(h0+ty+k)*DD + d0 + tx];
    __syncthreads();
    #pragma unroll
    for (int k = 0; k < 32; k += 8) {
        float v = t[tx][ty+k];
        __half hi = __float2half_rn(v);
        dhi[(size_t)(d0+ty+k)*HH + h0 + tx] = hi;
        dlo[(size_t)(d0+ty+k)*HH + h0 + tx] = __float2half_rn((v - __half2float(hi))*1024.f);
    }
}

// ============================================================================
// GEMM1 (mma.sync fp16, 2-term): z = a_hi*b_hi + (a_hi*2^-10)*(b_lo*2^10)
//   z1 = X @ W1t^T, z3 = X @ W3t^T;  h = silu(z1+b1)*(z3+b3) -> fp16
// CTA: 128(M) x 128(N of H), BK=32, 3-stage cp.async pipeline.
// 8 warps as 2(M) x 4(N); warp tile 64x32.
// smem tiles per stage (5): A, W1h, W1l, W3h, W3l; row stride 80B.
// ============================================================================
__global__ void __launch_bounds__(256) gemm1_kernel(const float* __restrict__ b1,
                                                    const float* __restrict__ b3) {
    int e = g_tile_expert[blockIdx.y];
    if (e < 0) return;
    int row0 = blockIdx.y * BM;
    int n0   = blockIdx.x * 128;

    extern __shared__ __align__(1024) char smem[];
    uint32_t sb = smem_u32(smem);

    int tid  = threadIdx.x;
    int lane = tid & 31;
    int wid  = tid >> 5;
    int wm   = wid >> 2;      // 0..1
    int wn   = wid & 3;       // 0..3

    size_t aoff = (size_t)row0*DD;
    size_t woff = ((size_t)e*HH + n0)*DD;
    const __half* s0 = g_xg     + aoff;
    const __half* s1 = g_w1t_hi + woff;
    const __half* s2 = g_w1t_lo + woff;
    const __half* s3 = g_w3t_hi + woff;
    const __half* s4 = g_w3t_lo + woff;

    #define G1_LOAD(stage, it) do { \
        uint32_t bs = sb + (uint32_t)(stage)*(5*TILEB); \
        int k0 = (it)*32; \
        _Pragma("unroll") \
        for (int half = 0; half < 2; half++) { \
            int idx = half*256 + tid; \
            int row = idx >> 2, kc = idx & 3; \
            uint32_t so = (uint32_t)row*STRB + kc*16; \
            size_t gi = (size_t)row*DD + k0 + kc*8; \
            cpasync16(bs + 0*TILEB + so, s0 + gi); \
            cpasync16(bs + 1*TILEB + so, s1 + gi); \
            cpasync16(bs + 2*TILEB + so, s2 + gi); \
            cpasync16(bs + 3*TILEB + so, s3 + gi); \
            cpasync16(bs + 4*TILEB + so, s4 + gi); \
        } \
    } while (0)

    float acc1[4][4][4], acc3[4][4][4];
    #pragma unroll
    for (int i = 0; i < 4; i++)
        #pragma unroll
        for (int j = 0; j < 4; j++)
            #pragma unroll
            for (int q = 0; q < 4; q++) { acc1[i][j][q] = 0.f; acc3[i][j][q] = 0.f; }

    int lr = (lane & 7) + 8*((lane >> 3) & 1);   // 0..15
    int lk = (lane >> 4) * 16;                   // 0 or 16 (bytes)

    const int NIT = DD/32;   // 32
    G1_LOAD(0, 0); CP_COMMIT();
    G1_LOAD(1, 1); CP_COMMIT();

    for (int it = 0; it < NIT; it++) {
        if (it + 2 < NIT) G1_LOAD((it+2)%3, it+2);
        CP_COMMIT();
        CP_WAIT2();
        __syncthreads();

        uint32_t bs = sb + (uint32_t)(it%3)*(5*TILEB);
        uint32_t aA = bs + 0*TILEB + (uint32_t)(wm*64 + lr)*STRB + lk;
        uint32_t aB =      (uint32_t)(wn*32 + lr)*STRB + lk;

        #pragma unroll
        for (int h16 = 0; h16 < 2; h16++) {
            uint32_t ko = h16*32;
            uint32_t Ah[4][4], As[4][4];
            #pragma unroll
            for (int mt = 0; mt < 4; mt++) {
                ldmx4(Ah[mt], aA + mt*(16*STRB) + ko);
                #pragma unroll
                for (int q = 0; q < 4; q++) As[mt][q] = hscale(Ah[mt][q]);
            }
            // W1
            #pragma unroll
            for (int np = 0; np < 2; np++) {
                uint32_t bh[4], bl[4];
                ldmx4(bh, bs + 1*TILEB + aB + np*(16*STRB) + ko);
                ldmx4(bl, bs + 2*TILEB + aB + np*(16*STRB) + ko);
                #pragma unroll
                for (int s = 0; s < 2; s++) {
                    int nt = np*2 + s;
                    #pragma unroll
                    for (int mt = 0; mt < 4; mt++) {
                        mma16816(acc1[mt][nt], Ah[mt], bh[s], bh[2+s]);
                        mma16816(acc1[mt][nt], As[mt], bl[s], bl[2+s]);
                    }
                }
            }
            // W3
            #pragma unroll
            for (int np = 0; np < 2; np++) {
                uint32_t bh[4], bl[4];
                ldmx4(bh, bs + 3*TILEB + aB + np*(16*STRB) + ko);
                ldmx4(bl, bs + 4*TILEB + aB + np*(16*STRB) + ko);
                #pragma unroll
                for (int s = 0; s < 2; s++) {
                    int nt = np*2 + s;
                    #pragma unroll
                    for (int mt = 0; mt < 4; mt++) {
                        mma16816(acc3[mt][nt], Ah[mt], bh[s], bh[2+s]);
                        mma16816(acc3[mt][nt], As[mt], bl[s], bl[2+s]);
                    }
                }
            }
        }
        __syncthreads();
    }

    // epilogue: h = silu(z1+b1)*(z3+b3) -> fp16
    int qrow = lane >> 2, qcol = lane & 3;
    #pragma unroll
    for (int nt = 0; nt < 4; nt++) {
        int col = n0 + wn*32 + nt*8 + qcol*2;
        float2 bb1 = *(const float2*)(b1 + e*HH + col);
        float2 bb3 = *(const float2*)(b3 + e*HH + col);
        #pragma unroll
        for (int mt = 0; mt < 4; mt++) {
            #pragma unroll
            for (int hrow = 0; hrow < 2; hrow++) {
                int r = row0 + wm*64 + mt*16 + qrow + hrow*8;
                float z1a = acc1[mt][nt][2*hrow]   + bb1.x;
                float z1b = acc1[mt][nt][2*hrow+1] + bb1.y;
                float z3a = acc3[mt][nt][2*hrow]   + bb3.x;
                float z3b = acc3[mt][nt][2*hrow+1] + bb3.y;
                float ha = (z1a / (1.f + __expf(-z1a))) * z3a;
                float hb = (z1b / (1.f + __expf(-z1b))) * z3b;
                *reinterpret_cast<__half2*>(g_h + (size_t)r*HH + col) =
                    __floats2half2_rn(ha, hb);
            }
        }
    }
}

// ============================================================================
// GEMM2 (mma.sync fp16, 2-term): eo = (h @ W2t^T + b2) * route_w
// CTA: 128 x 128(D), BK=32, 3-stage cp.async. Warp tile 64x32.
// smem tiles per stage (3): H, W2h, W2l.
// ============================================================================
__global__ void __launch_bounds__(256) gemm2_kernel(const float* __restrict__ b2) {
    int e = g_tile_expert[blockIdx.y];
    if (e < 0) return;
    int row0 = blockIdx.y * BM;
    int n0   = blockIdx.x * 128;

    extern __shared__ __align__(1024) char smem[];
    uint32_t sb = smem_u32(smem);

    int tid  = threadIdx.x;
    int lane = tid & 31;
    int wid  = tid >> 5;
    int wm   = wid >> 2;
    int wn   = wid & 3;

    size_t aoff = (size_t)row0*HH;
    size_t woff = ((size_t)e*DD + n0)*HH;
    const __half* s0 = g_h      + aoff;
    const __half* s1 = g_w2t_hi + woff;
    const __half* s2 = g_w2t_lo + woff;

    #define G2_LOAD(stage, it) do { \
        uint32_t bs = sb + (uint32_t)(stage)*(3*TILEB); \
        int k0 = (it)*32; \
        _Pragma("unroll") \
        for (int half = 0; half < 2; half++) { \
            int idx = half*256 + tid; \
            int row = idx >> 2, kc = idx & 3; \
            uint32_t so = (uint32_t)row*STRB + kc*16; \
            size_t gi = (size_t)row*HH + k0 + kc*8; \
            cpasync16(bs + 0*TILEB + so, s0 + gi); \
            cpasync16(bs + 1*TILEB + so, s1 + gi); \
            cpasync16(bs + 2*TILEB + so, s2 + gi); \
        } \
    } while (0)

    float acc[4][4][4];
    #pragma unroll
    for (int i = 0; i < 4; i++)
        #pragma unroll
        for (int j = 0; j < 4; j++)
            #pragma unroll
            for (int q = 0; q < 4; q++) acc[i][j][q] = 0.f;

    int lr = (lane & 7) + 8*((lane >> 3) & 1);
    int lk = (lane >> 4) * 16;

    const int NIT = HH/32;   // 64
    G2_LOAD(0, 0); CP_COMMIT();
    G2_LOAD(1, 1); CP_COMMIT();

    for (int it = 0; it < NIT; it++) {
        if (it + 2 < NIT) G2_LOAD((it+2)%3, it+2);
        CP_COMMIT();
        CP_WAIT2();
        __syncthreads();

        uint32_t bs = sb + (uint32_t)(it%3)*(3*TILEB);
        uint32_t aA = bs + 0*TILEB + (uint32_t)(wm*64 + lr)*STRB + lk;
        uint32_t aB =      (uint32_t)(wn*32 + lr)*STRB + lk;

        #pragma unroll
        for (int h16 = 0; h16 < 2; h16++) {
            uint32_t ko = h16*32;
            uint32_t Ah[4][4], As[4][4];
            #pragma unroll
            for (int mt = 0; mt < 4; mt++) {
                ldmx4(Ah[mt], aA + mt*(16*STRB) + ko);
                #pragma unroll
                for (int q = 0; q < 4; q++) As[mt][q] = hscale(Ah[mt][q]);
            }
            #pragma unroll
            for (int np = 0; np < 2; np++) {
                uint32_t bh[4], bl[4];
                ldmx4(bh, bs + 1*TILEB + aB + np*(16*STRB) + ko);
                ldmx4(bl, bs + 2*TILEB + aB + np*(16*STRB) + ko);
                #pragma unroll
                for (int s = 0; s < 2; s++) {
                    int nt = np*2 + s;
                    #pragma unroll
                    for (int mt = 0; mt < 4; mt++) {
                        mma16816(acc[mt][nt], Ah[mt], bh[s], bh[2+s]);
                        mma16816(acc[mt][nt], As[mt], bl[s], bl[2+s]);
                    }
                }
            }
        }
        __syncthreads();
    }

    // epilogue: (acc + b2) * route_w
    int qrow = lane >> 2, qcol = lane & 3;
    #pragma unroll
    for (int mt = 0; mt < 4; mt++) {
        #pragma unroll
        for (int hrow = 0; hrow < 2; hrow++) {
            int r = row0 + wm*64 + mt*16 + qrow + hrow*8;
            float wv = g_pair_w[r];
            #pragma unroll
            for (int nt = 0; nt < 4; nt++) {
                int col = n0 + wn*32 + nt*8 + qcol*2;
                float2 bb = *(const float2*)(b2 + e*DD + col);
                float2 o;
                o.x = (acc[mt][nt][2*hrow]   + bb.x) * wv;
                o.y = (acc[mt][nt][2*hrow+1] + bb.y) * wv;
                *(float2*)(g_eo + (size_t)r*DD + col) = o;
            }
        }
    }
}

// ---------------- combine ----------------
__global__ void combine_kernel(float* __restrict__ out) {
    int idx = blockIdx.x*blockDim.x + threadIdx.x;
    int n = idx >> 8;
    int q = idx & 255;
    if (n >= NTOK) return;
    int p0 = g_pair_slot[2*n];
    int p1 = g_pair_slot[2*n+1];
    const float4* eo = (const float4*)g_eo;
    float4 a = eo[(size_t)p0*256 + q];
    float4 b = eo[(size_t)p1*256 + q];
    ((float4*)out)[idx] = make_float4(a.x+b.x, a.y+b.y, a.z+b.z, a.w+b.w);
}

// ---------------- aux loss ----------------
__global__ void aux_kernel(float* __restrict__ out, int has_aux) {
    __shared__ float red[64];
    int tid = threadIdx.x;
    int e = tid & 7;
    float p = 0.f;
    for (int n = tid >> 3; n < NTOK; n += 8) p += g_scores[(size_t)n*EE + e];
    red[tid] = p;
    __syncthreads();
    for (int s = 32; s >= 8; s >>= 1) {
        if (tid < s) red[tid] += red[tid + s];
        __syncthreads();
    }
    if (tid == 0 && has_aux) {
        float aux = 0.f;
        for (int ee = 0; ee < EE; ee++) {
            float f = (float)g_counts[ee] / (float)(NTOK*KTOP);
            float P = red[ee] / (float)NTOK;
            aux += f*P;
        }
        out[(size_t)NTOK*DD] = 0.01f * (float)EE * aux;
    }
}

// ---------------- launch ----------------
extern "C" void kernel_launch(void* const* d_in, const int* in_sizes, int n_in,
                              void* d_out, int out_size) {
    const float* x  = (const float*)d_in[0];
    const float* Wg = (const float*)d_in[1];
    const float* W1 = (const float*)d_in[2];
    const float* b1 = (const float*)d_in[3];
    const float* W2 = (const float*)d_in[4];
    const float* b2 = (const float*)d_in[5];
    const float* W3 = (const float*)d_in[6];
    const float* b3 = (const float*)d_in[7];
    float* out = (float*)d_out;

    const int G1_SMEM = 3*5*TILEB;   // 153600
    const int G2_SMEM = 3*3*TILEB;   // 92160
    cudaFuncSetAttribute(gemm1_kernel, cudaFuncAttributeMaxDynamicSharedMemorySize, G1_SMEM);
    cudaFuncSetAttribute(gemm2_kernel, cudaFuncAttributeMaxDynamicSharedMemorySize, G2_SMEM);

    init_kernel<<<(MAXPAD + 255)/256, 256>>>();
    gate_kernel<<<NTOK/8, 256>>>(x, Wg);
    setup_kernel<<<1, 1>>>();
    assign_kernel<<<NTOK/256, 256>>>();
    gatherx_kernel<<<MAXPAD, 256>>>(x);
    convw13_kernel<<<dim3(HH/32, DD/32, EE*2), dim3(32, 8)>>>(W1, W3);
    convw2_kernel<<<dim3(DD/32, HH/32, EE), dim3(32, 8)>>>(W2);
    gemm1_kernel<<<dim3(HH/128, MAXTILES), 256, G1_SMEM>>>(b1, b3);
    gemm2_kernel<<<dim3(DD/128, MAXTILES), 256, G2_SMEM>>>(b2);
    combine_kernel<<<(NTOK*(DD/4))/256, 256>>>(out);
    aux_kernel<<<1, 64>>>(out, out_size > NTOK*DD ? 1 : 0);
}

// round 5
// speedup vs baseline: 4.1109x; 1.5453x over previous
#include <cuda_runtime.h>
#include <cuda_bf16.h>
#include <cuda_fp16.h>
#include <math.h>
#include <stdint.h>

#define DD     1024
#define HH     2048
#define EE     8
#define NTOK   8192
#define KTOP   2
#define NP     (NTOK*KTOP)      // 16384
#define BM     128
#define MAXPAD (NP + EE*BM)     // 17408
#define MAXTILES (MAXPAD/BM)    // 136

#define STRB   80               // smem row stride bytes (32 fp16 = 64B data + 16B pad)
#define TILEB  (128*STRB)       // 10240 bytes per 128-row tile

// ---------------- device scratch ----------------
__device__ int   g_pair_tok[MAXPAD];
__device__ float g_pair_w[MAXPAD];
__device__ int   g_pair_slot[NP];
__device__ int   g_topk_idx[NP];
__device__ float g_topk_val[NP];
__device__ float g_scores[NTOK*EE];
__device__ int   g_counts[EE];
__device__ int   g_cursor[EE];
__device__ int   g_pstart[EE+1];
__device__ int   g_tile_expert[MAXTILES];

__device__ __align__(16) __half g_xg [(size_t)MAXPAD*DD];      // fp16 x (gathered)
__device__ __align__(16) __half g_w1t[(size_t)EE*HH*DD];       // [E][H][D]
__device__ __align__(16) __half g_w3t[(size_t)EE*HH*DD];
__device__ __align__(16) __half g_w2t[(size_t)EE*DD*HH];       // [E][D][H]
__device__ __align__(16) __half g_h  [(size_t)MAXPAD*HH];      // fp16 h
__device__ __align__(16) float  g_eo [(size_t)MAXPAD*DD];

// ---------------- PTX helpers (baseline PTX only: sm_80-class) ----------------
__device__ __forceinline__ uint32_t smem_u32(const void* p){
    uint32_t a;
    asm("{ .reg .u64 t; cvta.to.shared.u64 t, %1; cvt.u32.u64 %0, t; }" : "=r"(a) : "l"(p));
    return a;
}
__device__ __forceinline__ void cpasync16(uint32_t dst, const void* src){
    asm volatile("cp.async.cg.shared.global [%0], [%1], 16;" :: "r"(dst), "l"(src));
}
#define CP_COMMIT() asm volatile("cp.async.commit_group;" ::: "memory")
#define CP_WAIT2()  asm volatile("cp.async.wait_group 2;" ::: "memory")

__device__ __forceinline__ void ldmx4(uint32_t (&r)[4], uint32_t addr){
    asm volatile("ldmatrix.sync.aligned.m8n8.x4.shared.b16 {%0,%1,%2,%3}, [%4];"
        : "=r"(r[0]), "=r"(r[1]), "=r"(r[2]), "=r"(r[3]) : "r"(addr));
}
__device__ __forceinline__ void mma16816(float (&c)[4], const uint32_t (&a)[4],
                                         uint32_t b0, uint32_t b1){
    asm volatile(
        "mma.sync.aligned.m16n8k16.row.col.f32.f16.f16.f32 "
        "{%0,%1,%2,%3}, {%4,%5,%6,%7}, {%8,%9}, {%0,%1,%2,%3};"
        : "+f"(c[0]), "+f"(c[1]), "+f"(c[2]), "+f"(c[3])
        : "r"(a[0]), "r"(a[1]), "r"(a[2]), "r"(a[3]), "r"(b0), "r"(b1));
}

// ---------------- init ----------------
__global__ void init_kernel() {
    int i = blockIdx.x*blockDim.x + threadIdx.x;
    if (i < MAXPAD) { g_pair_tok[i] = -1; g_pair_w[i] = 0.f; }
    if (i < EE)     { g_counts[i] = 0; g_cursor[i] = 0; }
}

// ---------------- gating: one warp per token ----------------
__global__ void gate_kernel(const float* __restrict__ x, const float* __restrict__ Wg) {
    int warp = threadIdx.x >> 5;
    int lane = threadIdx.x & 31;
    int n = blockIdx.x*8 + warp;
    if (n >= NTOK) return;

    const float* xr = x + (size_t)n*DD;
    float sc[EE];
    #pragma unroll
    for (int e = 0; e < EE; e++) {
        const float* wr = Wg + (size_t)e*DD;
        float p = 0.f;
        for (int d = lane; d < DD; d += 32) p += xr[d]*wr[d];
        #pragma unroll
        for (int off = 16; off; off >>= 1) p += __shfl_xor_sync(0xffffffffu, p, off);
        sc[e] = p;
    }
    float m = sc[0];
    #pragma unroll
    for (int e = 1; e < EE; e++) m = fmaxf(m, sc[e]);
    float s = 0.f, pr[EE];
    #pragma unroll
    for (int e = 0; e < EE; e++) { pr[e] = __expf(sc[e]-m); s += pr[e]; }
    float inv = 1.f/s;
    #pragma unroll
    for (int e = 0; e < EE; e++) pr[e] *= inv;

    int i1 = 0; float v1 = pr[0];
    #pragma unroll
    for (int e = 1; e < EE; e++) if (pr[e] > v1) { v1 = pr[e]; i1 = e; }
    int i2 = -1; float v2 = -1.f;
    #pragma unroll
    for (int e = 0; e < EE; e++) if (e != i1 && pr[e] > v2) { v2 = pr[e]; i2 = e; }

    if (lane == 0) {
        #pragma unroll
        for (int e = 0; e < EE; e++) g_scores[(size_t)n*EE + e] = pr[e];
        g_topk_idx[2*n]   = i1; g_topk_val[2*n]   = v1;
        g_topk_idx[2*n+1] = i2; g_topk_val[2*n+1] = v2;
        atomicAdd(&g_counts[i1], 1);
        atomicAdd(&g_counts[i2], 1);
    }
}

// ---------------- setup ----------------
__global__ void setup_kernel() {
    int off = 0;
    for (int e = 0; e < EE; e++) {
        g_pstart[e] = off;
        off = (off + g_counts[e] + BM - 1)/BM*BM;
    }
    g_pstart[EE] = off;
    for (int t = 0; t < MAXTILES; t++) g_tile_expert[t] = -1;
    for (int e = 0; e < EE; e++) {
        int t0 = g_pstart[e]/BM;
        int t1 = (g_pstart[e] + g_counts[e] + BM - 1)/BM;
        for (int t = t0; t < t1; t++) g_tile_expert[t] = e;
    }
}

// ---------------- assign ----------------
__global__ void assign_kernel() {
    int n = blockIdx.x*blockDim.x + threadIdx.x;
    if (n >= NTOK) return;
    #pragma unroll
    for (int k = 0; k < KTOP; k++) {
        int e = g_topk_idx[2*n+k];
        int pos = atomicAdd(&g_cursor[e], 1);
        int slot = g_pstart[e] + pos;
        g_pair_tok[slot] = n;
        g_pair_w[slot]   = g_topk_val[2*n+k];
        g_pair_slot[2*n+k] = slot;
    }
}

// ---------------- gather x -> fp16 ----------------
__global__ void gatherx_kernel(const float* __restrict__ x) {
    int slot = blockIdx.x;
    int tok = g_pair_tok[slot];
    int t = threadIdx.x;               // 0..255, float4 index
    float4 v = make_float4(0.f,0.f,0.f,0.f);
    if (tok >= 0) v = ((const float4*)(x + (size_t)tok*DD))[t];
    __half2* dh = (__half2*)(g_xg + (size_t)slot*DD) + 2*t;
    dh[0] = __floats2half2_rn(v.x, v.y);
    dh[1] = __floats2half2_rn(v.z, v.w);
}

// ---------------- transpose-convert W1/W3: [E][D][H] -> [E][H][D] fp16 ----------------
__global__ void convw13_kernel(const float* __restrict__ W1, const float* __restrict__ W3) {
    __shared__ float t[32][33];
    int m = blockIdx.z & 1, e = blockIdx.z >> 1;
    const float* src = (m ? W3 : W1) + (size_t)e*DD*HH;
    __half* dst = (m ? g_w3t : g_w1t) + (size_t)e*HH*DD;
    int h0 = blockIdx.x*32, d0 = blockIdx.y*32;
    int tx = threadIdx.x, ty = threadIdx.y;   // 32x8
    #pragma unroll
    for (int k = 0; k < 32; k += 8)
        t[ty+k][tx] = src[(size_t)(d0+ty+k)*HH + h0 + tx];
    __syncthreads();
    #pragma unroll
    for (int k = 0; k < 32; k += 8)
        dst[(size_t)(h0+ty+k)*DD + d0 + tx] = __float2half_rn(t[tx][ty+k]);
}

// ---------------- transpose-convert W2: [E][H][D] -> [E][D][H] fp16 ----------------
__global__ void convw2_kernel(const float* __restrict__ W2) {
    __shared__ float t[32][33];
    int e = blockIdx.z;
    const float* src = W2 + (size_t)e*HH*DD;
    __half* dst = g_w2t + (size_t)e*DD*HH;
    int d0 = blockIdx.x*32, h0 = blockIdx.y*32;
    int tx = threadIdx.x, ty = threadIdx.y;
    #pragma unroll
    for (int k = 0; k < 32; k += 8)
        t[ty+k][tx] = src[(size_t)(h0+ty+k)*DD + d0 + tx];
    __syncthreads();
    #pragma unroll
    for (int k = 0; k < 32; k += 8)
        dst[(size_t)(d0+ty+k)*HH + h0 + tx] = __float2half_rn(t[tx][ty+k]);
}

// ============================================================================
// GEMM1 (mma.sync fp16): z1 = X @ W1t^T, z3 = X @ W3t^T; h = silu(z1+b1)*(z3+b3)
// CTA: 128(M) x 128(N of H), BK=32, 3-stage cp.async pipeline.
// 8 warps as 2(M) x 4(N); warp tile 64x32.
// smem tiles per stage (3): A, W1, W3; row stride 80B.
// ============================================================================
__global__ void __launch_bounds__(256) gemm1_kernel(const float* __restrict__ b1,
                                                    const float* __restrict__ b3) {
    int e = g_tile_expert[blockIdx.y];
    if (e < 0) return;
    int row0 = blockIdx.y * BM;
    int n0   = blockIdx.x * 128;

    extern __shared__ __align__(1024) char smem[];
    uint32_t sb = smem_u32(smem);

    int tid  = threadIdx.x;
    int lane = tid & 31;
    int wid  = tid >> 5;
    int wm   = wid >> 2;      // 0..1
    int wn   = wid & 3;       // 0..3

    size_t aoff = (size_t)row0*DD;
    size_t woff = ((size_t)e*HH + n0)*DD;
    const __half* s0 = g_xg  + aoff;
    const __half* s1 = g_w1t + woff;
    const __half* s2 = g_w3t + woff;

    #define G1_LOAD(stage, it) do { \
        uint32_t bs = sb + (uint32_t)(stage)*(3*TILEB); \
        int k0 = (it)*32; \
        _Pragma("unroll") \
        for (int half = 0; half < 2; half++) { \
            int idx = half*256 + tid; \
            int row = idx >> 2, kc = idx & 3; \
            uint32_t so = (uint32_t)row*STRB + kc*16; \
            size_t gi = (size_t)row*DD + k0 + kc*8; \
            cpasync16(bs + 0*TILEB + so, s0 + gi); \
            cpasync16(bs + 1*TILEB + so, s1 + gi); \
            cpasync16(bs + 2*TILEB + so, s2 + gi); \
        } \
    } while (0)

    float acc1[4][4][4], acc3[4][4][4];
    #pragma unroll
    for (int i = 0; i < 4; i++)
        #pragma unroll
        for (int j = 0; j < 4; j++)
            #pragma unroll
            for (int q = 0; q < 4; q++) { acc1[i][j][q] = 0.f; acc3[i][j][q] = 0.f; }

    int lr = (lane & 7) + 8*((lane >> 3) & 1);   // 0..15
    int lk = (lane >> 4) * 16;                   // 0 or 16 (bytes)

    const int NIT = DD/32;   // 32
    G1_LOAD(0, 0); CP_COMMIT();
    G1_LOAD(1, 1); CP_COMMIT();

    for (int it = 0; it < NIT; it++) {
        if (it + 2 < NIT) G1_LOAD((it+2)%3, it+2);
        CP_COMMIT();
        CP_WAIT2();
        __syncthreads();

        uint32_t bs = sb + (uint32_t)(it%3)*(3*TILEB);
        uint32_t aA = bs + 0*TILEB + (uint32_t)(wm*64 + lr)*STRB + lk;
        uint32_t aB =      (uint32_t)(wn*32 + lr)*STRB + lk;

        #pragma unroll
        for (int h16 = 0; h16 < 2; h16++) {
            uint32_t ko = h16*32;
            uint32_t Ah[4][4];
            #pragma unroll
            for (int mt = 0; mt < 4; mt++)
                ldmx4(Ah[mt], aA + mt*(16*STRB) + ko);
            // W1
            #pragma unroll
            for (int np = 0; np < 2; np++) {
                uint32_t bh[4];
                ldmx4(bh, bs + 1*TILEB + aB + np*(16*STRB) + ko);
                #pragma unroll
                for (int s = 0; s < 2; s++) {
                    int nt = np*2 + s;
                    #pragma unroll
                    for (int mt = 0; mt < 4; mt++)
                        mma16816(acc1[mt][nt], Ah[mt], bh[s], bh[2+s]);
                }
            }
            // W3
            #pragma unroll
            for (int np = 0; np < 2; np++) {
                uint32_t bh[4];
                ldmx4(bh, bs + 2*TILEB + aB + np*(16*STRB) + ko);
                #pragma unroll
                for (int s = 0; s < 2; s++) {
                    int nt = np*2 + s;
                    #pragma unroll
                    for (int mt = 0; mt < 4; mt++)
                        mma16816(acc3[mt][nt], Ah[mt], bh[s], bh[2+s]);
                }
            }
        }
        __syncthreads();
    }

    // epilogue: h = silu(z1+b1)*(z3+b3) -> fp16
    int qrow = lane >> 2, qcol = lane & 3;
    #pragma unroll
    for (int nt = 0; nt < 4; nt++) {
        int col = n0 + wn*32 + nt*8 + qcol*2;
        float2 bb1 = *(const float2*)(b1 + e*HH + col);
        float2 bb3 = *(const float2*)(b3 + e*HH + col);
        #pragma unroll
        for (int mt = 0; mt < 4; mt++) {
            #pragma unroll
            for (int hrow = 0; hrow < 2; hrow++) {
                int r = row0 + wm*64 + mt*16 + qrow + hrow*8;
                float z1a = acc1[mt][nt][2*hrow]   + bb1.x;
                float z1b = acc1[mt][nt][2*hrow+1] + bb1.y;
                float z3a = acc3[mt][nt][2*hrow]   + bb3.x;
                float z3b = acc3[mt][nt][2*hrow+1] + bb3.y;
                float ha = (z1a / (1.f + __expf(-z1a))) * z3a;
                float hb = (z1b / (1.f + __expf(-z1b))) * z3b;
                *reinterpret_cast<__half2*>(g_h + (size_t)r*HH + col) =
                    __floats2half2_rn(ha, hb);
            }
        }
    }
}

// ============================================================================
// GEMM2 (mma.sync fp16): eo = (h @ W2t^T + b2) * route_w
// CTA: 128 x 128(D), BK=32, 3-stage cp.async. Warp tile 64x32.
// smem tiles per stage (2): H, W2.
// ============================================================================
__global__ void __launch_bounds__(256) gemm2_kernel(const float* __restrict__ b2) {
    int e = g_tile_expert[blockIdx.y];
    if (e < 0) return;
    int row0 = blockIdx.y * BM;
    int n0   = blockIdx.x * 128;

    extern __shared__ __align__(1024) char smem[];
    uint32_t sb = smem_u32(smem);

    int tid  = threadIdx.x;
    int lane = tid & 31;
    int wid  = tid >> 5;
    int wm   = wid >> 2;
    int wn   = wid & 3;

    size_t aoff = (size_t)row0*HH;
    size_t woff = ((size_t)e*DD + n0)*HH;
    const __half* s0 = g_h   + aoff;
    const __half* s1 = g_w2t + woff;

    #define G2_LOAD(stage, it) do { \
        uint32_t bs = sb + (uint32_t)(stage)*(2*TILEB); \
        int k0 = (it)*32; \
        _Pragma("unroll") \
        for (int half = 0; half < 2; half++) { \
            int idx = half*256 + tid; \
            int row = idx >> 2, kc = idx & 3; \
            uint32_t so = (uint32_t)row*STRB + kc*16; \
            size_t gi = (size_t)row*HH + k0 + kc*8; \
            cpasync16(bs + 0*TILEB + so, s0 + gi); \
            cpasync16(bs + 1*TILEB + so, s1 + gi); \
        } \
    } while (0)

    float acc[4][4][4];
    #pragma unroll
    for (int i = 0; i < 4; i++)
        #pragma unroll
        for (int j = 0; j < 4; j++)
            #pragma unroll
            for (int q = 0; q < 4; q++) acc[i][j][q] = 0.f;

    int lr = (lane & 7) + 8*((lane >> 3) & 1);
    int lk = (lane >> 4) * 16;

    const int NIT = HH/32;   // 64
    G2_LOAD(0, 0); CP_COMMIT();
    G2_LOAD(1, 1); CP_COMMIT();

    for (int it = 0; it < NIT; it++) {
        if (it + 2 < NIT) G2_LOAD((it+2)%3, it+2);
        CP_COMMIT();
        CP_WAIT2();
        __syncthreads();

        uint32_t bs = sb + (uint32_t)(it%3)*(2*TILEB);
        uint32_t aA = bs + 0*TILEB + (uint32_t)(wm*64 + lr)*STRB + lk;
        uint32_t aB =      (uint32_t)(wn*32 + lr)*STRB + lk;

        #pragma unroll
        for (int h16 = 0; h16 < 2; h16++) {
            uint32_t ko = h16*32;
            uint32_t Ah[4][4];
            #pragma unroll
            for (int mt = 0; mt < 4; mt++)
                ldmx4(Ah[mt], aA + mt*(16*STRB) + ko);
            #pragma unroll
            for (int np = 0; np < 2; np++) {
                uint32_t bh[4];
                ldmx4(bh, bs + 1*TILEB + aB + np*(16*STRB) + ko);
                #pragma unroll
                for (int s = 0; s < 2; s++) {
                    int nt = np*2 + s;
                    #pragma unroll
                    for (int mt = 0; mt < 4; mt++)
                        mma16816(acc[mt][nt], Ah[mt], bh[s], bh[2+s]);
                }
            }
        }
        __syncthreads();
    }

    // epilogue: (acc + b2) * route_w
    int qrow = lane >> 2, qcol = lane & 3;
    #pragma unroll
    for (int mt = 0; mt < 4; mt++) {
        #pragma unroll
        for (int hrow = 0; hrow < 2; hrow++) {
            int r = row0 + wm*64 + mt*16 + qrow + hrow*8;
            float wv = g_pair_w[r];
            #pragma unroll
            for (int nt = 0; nt < 4; nt++) {
                int col = n0 + wn*32 + nt*8 + qcol*2;
                float2 bb = *(const float2*)(b2 + e*DD + col);
                float2 o;
                o.x = (acc[mt][nt][2*hrow]   + bb.x) * wv;
                o.y = (acc[mt][nt][2*hrow+1] + bb.y) * wv;
                *(float2*)(g_eo + (size_t)r*DD + col) = o;
            }
        }
    }
}

// ---------------- combine ----------------
__global__ void combine_kernel(float* __restrict__ out) {
    int idx = blockIdx.x*blockDim.x + threadIdx.x;
    int n = idx >> 8;
    int q = idx & 255;
    if (n >= NTOK) return;
    int p0 = g_pair_slot[2*n];
    int p1 = g_pair_slot[2*n+1];
    const float4* eo = (const float4*)g_eo;
    float4 a = eo[(size_t)p0*256 + q];
    float4 b = eo[(size_t)p1*256 + q];
    ((float4*)out)[idx] = make_float4(a.x+b.x, a.y+b.y, a.z+b.z, a.w+b.w);
}

// ---------------- aux loss ----------------
__global__ void aux_kernel(float* __restrict__ out, int has_aux) {
    __shared__ float red[64];
    int tid = threadIdx.x;
    int e = tid & 7;
    float p = 0.f;
    for (int n = tid >> 3; n < NTOK; n += 8) p += g_scores[(size_t)n*EE + e];
    red[tid] = p;
    __syncthreads();
    for (int s = 32; s >= 8; s >>= 1) {
        if (tid < s) red[tid] += red[tid + s];
        __syncthreads();
    }
    if (tid == 0 && has_aux) {
        float aux = 0.f;
        for (int ee = 0; ee < EE; ee++) {
            float f = (float)g_counts[ee] / (float)(NTOK*KTOP);
            float P = red[ee] / (float)NTOK;
            aux += f*P;
        }
        out[(size_t)NTOK*DD] = 0.01f * (float)EE * aux;
    }
}

// ---------------- launch ----------------
extern "C" void kernel_launch(void* const* d_in, const int* in_sizes, int n_in,
                              void* d_out, int out_size) {
    const float* x  = (const float*)d_in[0];
    const float* Wg = (const float*)d_in[1];
    const float* W1 = (const float*)d_in[2];
    const float* b1 = (const float*)d_in[3];
    const float* W2 = (const float*)d_in[4];
    const float* b2 = (const float*)d_in[5];
    const float* W3 = (const float*)d_in[6];
    const float* b3 = (const float*)d_in[7];
    float* out = (float*)d_out;

    const int G1_SMEM = 3*3*TILEB;   // 92160
    const int G2_SMEM = 3*2*TILEB;   // 61440
    cudaFuncSetAttribute(gemm1_kernel, cudaFuncAttributeMaxDynamicSharedMemorySize, G1_SMEM);
    cudaFuncSetAttribute(gemm2_kernel, cudaFuncAttributeMaxDynamicSharedMemorySize, G2_SMEM);

    init_kernel<<<(MAXPAD + 255)/256, 256>>>();
    gate_kernel<<<NTOK/8, 256>>>(x, Wg);
    setup_kernel<<<1, 1>>>();
    assign_kernel<<<NTOK/256, 256>>>();
    gatherx_kernel<<<MAXPAD, 256>>>(x);
    convw13_kernel<<<dim3(HH/32, DD/32, EE*2), dim3(32, 8)>>>(W1, W3);
    convw2_kernel<<<dim3(DD/32, HH/32, EE), dim3(32, 8)>>>(W2);
    gemm1_kernel<<<dim3(HH/128, MAXTILES), 256, G1_SMEM>>>(b1, b3);
    gemm2_kernel<<<dim3(DD/128, MAXTILES), 256, G2_SMEM>>>(b2);
    combine_kernel<<<(NTOK*(DD/4))/256, 256>>>(out);
    aux_kernel<<<1, 64>>>(out, out_size > NTOK*DD ? 1 : 0);
}

// round 6
// speedup vs baseline: 4.7994x; 1.1675x over previous
#include <cuda_runtime.h>
#include <cuda_bf16.h>
#include <cuda_fp16.h>
#include <math.h>
#include <stdint.h>

#define DD     1024
#define HH     2048
#define EE     8
#define NTOK   8192
#define KTOP   2
#define NP     (NTOK*KTOP)      // 16384
#define BM     128
#define MAXPAD (NP + EE*BM)     // 17408
#define MAXTILES (MAXPAD/BM)    // 136

#define STRA   80               // A smem row stride (32 fp16 = 64B + 16B pad)
#define TILEA  (128*STRA)       // 10240
#define STRB   272              // B smem row stride (128 fp16 = 256B + 16B pad)
#define TILEW  (32*STRB)        // 8704

// ---------------- device scratch ----------------
__device__ int   g_pair_tok[MAXPAD];
__device__ float g_pair_w[MAXPAD];
__device__ int   g_pair_slot[NP];
__device__ int   g_topk_idx[NP];
__device__ float g_topk_val[NP];
__device__ float g_scores[NTOK*EE];
__device__ int   g_counts[EE];
__device__ int   g_cursor[EE];
__device__ int   g_pstart[EE+1];
__device__ int   g_tile_expert[MAXTILES];

__device__ __align__(16) __half g_xg [(size_t)MAXPAD*DD];      // fp16 x (gathered)
__device__ __align__(16) __half g_w1 [(size_t)EE*DD*HH];       // fp16 W1, SAME layout [E][D][H]
__device__ __align__(16) __half g_w3 [(size_t)EE*DD*HH];
__device__ __align__(16) __half g_w2 [(size_t)EE*HH*DD];       // fp16 W2, [E][H][D]
__device__ __align__(16) __half g_h  [(size_t)MAXPAD*HH];      // fp16 h
__device__ __align__(16) float  g_eo [(size_t)MAXPAD*DD];

// ---------------- PTX helpers (baseline PTX only: sm_80-class) ----------------
__device__ __forceinline__ uint32_t smem_u32(const void* p){
    uint32_t a;
    asm("{ .reg .u64 t; cvta.to.shared.u64 t, %1; cvt.u32.u64 %0, t; }" : "=r"(a) : "l"(p));
    return a;
}
__device__ __forceinline__ void cpasync16(uint32_t dst, const void* src){
    asm volatile("cp.async.cg.shared.global [%0], [%1], 16;" :: "r"(dst), "l"(src));
}
#define CP_COMMIT() asm volatile("cp.async.commit_group;" ::: "memory")
#define CP_WAIT2()  asm volatile("cp.async.wait_group 2;" ::: "memory")

__device__ __forceinline__ void ldmx4(uint32_t (&r)[4], uint32_t addr){
    asm volatile("ldmatrix.sync.aligned.m8n8.x4.shared.b16 {%0,%1,%2,%3}, [%4];"
        : "=r"(r[0]), "=r"(r[1]), "=r"(r[2]), "=r"(r[3]) : "r"(addr));
}
__device__ __forceinline__ void ldmx4t(uint32_t (&r)[4], uint32_t addr){
    asm volatile("ldmatrix.sync.aligned.m8n8.x4.trans.shared.b16 {%0,%1,%2,%3}, [%4];"
        : "=r"(r[0]), "=r"(r[1]), "=r"(r[2]), "=r"(r[3]) : "r"(addr));
}
__device__ __forceinline__ void mma16816(float (&c)[4], const uint32_t (&a)[4],
                                         uint32_t b0, uint32_t b1){
    asm volatile(
        "mma.sync.aligned.m16n8k16.row.col.f32.f16.f16.f32 "
        "{%0,%1,%2,%3}, {%4,%5,%6,%7}, {%8,%9}, {%0,%1,%2,%3};"
        : "+f"(c[0]), "+f"(c[1]), "+f"(c[2]), "+f"(c[3])
        : "r"(a[0]), "r"(a[1]), "r"(a[2]), "r"(a[3]), "r"(b0), "r"(b1));
}

// ---------------- init ----------------
__global__ void init_kernel() {
    int i = blockIdx.x*blockDim.x + threadIdx.x;
    if (i < MAXPAD) { g_pair_tok[i] = -1; g_pair_w[i] = 0.f; }
    if (i < EE)     { g_counts[i] = 0; g_cursor[i] = 0; }
}

// ---------------- gating: Wg staged in smem, x in registers ----------------
__global__ void __launch_bounds__(256) gate_kernel(const float* __restrict__ x,
                                                   const float* __restrict__ Wg) {
    __shared__ float sWg[EE*DD];
    for (int i = threadIdx.x; i < EE*DD/4; i += 256)
        ((float4*)sWg)[i] = ((const float4*)Wg)[i];
    __syncthreads();

    int warp = threadIdx.x >> 5;
    int lane = threadIdx.x & 31;
    int n = blockIdx.x*8 + warp;
    if (n >= NTOK) return;

    const float4* xr = (const float4*)(x + (size_t)n*DD);
    float4 xv[8];
    #pragma unroll
    for (int q = 0; q < 8; q++) xv[q] = xr[lane + q*32];

    float pr[EE];
    #pragma unroll
    for (int e = 0; e < EE; e++) {
        const float4* wr = (const float4*)(sWg + e*DD);
        float p = 0.f;
        #pragma unroll
        for (int q = 0; q < 8; q++) {
            float4 w = wr[lane + q*32];
            p += xv[q].x*w.x + xv[q].y*w.y + xv[q].z*w.z + xv[q].w*w.w;
        }
        #pragma unroll
        for (int off = 16; off; off >>= 1) p += __shfl_xor_sync(0xffffffffu, p, off);
        pr[e] = p;
    }
    float m = pr[0];
    #pragma unroll
    for (int e = 1; e < EE; e++) m = fmaxf(m, pr[e]);
    float s = 0.f;
    #pragma unroll
    for (int e = 0; e < EE; e++) { pr[e] = __expf(pr[e]-m); s += pr[e]; }
    float inv = 1.f/s;
    #pragma unroll
    for (int e = 0; e < EE; e++) pr[e] *= inv;

    int i1 = 0; float v1 = pr[0];
    #pragma unroll
    for (int e = 1; e < EE; e++) if (pr[e] > v1) { v1 = pr[e]; i1 = e; }
    int i2 = -1; float v2 = -1.f;
    #pragma unroll
    for (int e = 0; e < EE; e++) if (e != i1 && pr[e] > v2) { v2 = pr[e]; i2 = e; }

    if (lane == 0) {
        #pragma unroll
        for (int e = 0; e < EE; e++) g_scores[(size_t)n*EE + e] = pr[e];
        g_topk_idx[2*n]   = i1; g_topk_val[2*n]   = v1;
        g_topk_idx[2*n+1] = i2; g_topk_val[2*n+1] = v2;
        atomicAdd(&g_counts[i1], 1);
        atomicAdd(&g_counts[i2], 1);
    }
}

// ---------------- setup (parallel, 1 block) ----------------
__global__ void setup_kernel() {
    __shared__ int ps[EE+1], cnt[EE];
    int tid = threadIdx.x;
    if (tid == 0) {
        int off = 0;
        for (int e = 0; e < EE; e++) {
            ps[e] = off;
            int c = g_counts[e];
            cnt[e] = c;
            off = (off + c + BM - 1)/BM*BM;
        }
        ps[EE] = off;
    }
    __syncthreads();
    if (tid <= EE) g_pstart[tid] = ps[tid];
    if (tid < MAXTILES) {
        int r0 = tid*BM, e = -1;
        #pragma unroll
        for (int ee = 0; ee < EE; ee++)
            if (r0 >= ps[ee] && r0 < ps[ee] + cnt[ee]) e = ee;
        g_tile_expert[tid] = e;
    }
}

// ---------------- assign ----------------
__global__ void assign_kernel() {
    int n = blockIdx.x*blockDim.x + threadIdx.x;
    if (n >= NTOK) return;
    #pragma unroll
    for (int k = 0; k < KTOP; k++) {
        int e = g_topk_idx[2*n+k];
        int pos = atomicAdd(&g_cursor[e], 1);
        int slot = g_pstart[e] + pos;
        g_pair_tok[slot] = n;
        g_pair_w[slot]   = g_topk_val[2*n+k];
        g_pair_slot[2*n+k] = slot;
    }
}

// ---------------- gather x -> fp16 ----------------
__global__ void gatherx_kernel(const float* __restrict__ x) {
    int slot = blockIdx.x;
    int tok = g_pair_tok[slot];
    int t = threadIdx.x;
    float4 v = make_float4(0.f,0.f,0.f,0.f);
    if (tok >= 0) v = ((const float4*)(x + (size_t)tok*DD))[t];
    __half2* dh = (__half2*)(g_xg + (size_t)slot*DD) + 2*t;
    dh[0] = __floats2half2_rn(v.x, v.y);
    dh[1] = __floats2half2_rn(v.z, v.w);
}

// ---------------- flat fp32->fp16 conversion of W1/W3/W2 (no transpose!) ----------------
__global__ void convall_kernel(const float* __restrict__ W1,
                               const float* __restrict__ W3,
                               const float* __restrict__ W2) {
    int a = blockIdx.z;
    const float* src = (a == 0) ? W1 : (a == 1) ? W3 : W2;
    __half* dst = (a == 0) ? g_w1 : (a == 1) ? g_w3 : g_w2;
    size_t i = ((size_t)blockIdx.x*256 + threadIdx.x)*8;
    float4 v0 = *(const float4*)(src + i);
    float4 v1 = *(const float4*)(src + i + 4);
    __half2 h[4];
    h[0] = __floats2half2_rn(v0.x, v0.y);
    h[1] = __floats2half2_rn(v0.z, v0.w);
    h[2] = __floats2half2_rn(v1.x, v1.y);
    h[3] = __floats2half2_rn(v1.z, v1.w);
    *(uint4*)(dst + i) = *(uint4*)h;
}

// ============================================================================
// GEMM1 (mma.sync fp16): z1 = X @ W1^T-ish, z3 = X @ W3; h = silu(z1+b1)*(z3+b3)
// B operand fed from k-major rows via ldmatrix.trans (weights NOT transposed).
// CTA: 128(M) x 128(N of H), BK=32, 3-stage cp.async. 8 warps 2(M)x4(N).
// smem per stage: A(128x80B) + W1(32x272B) + W3(32x272B) = 27648 B.
// ============================================================================
__global__ void __launch_bounds__(256) gemm1_kernel(const float* __restrict__ b1,
                                                    const float* __restrict__ b3) {
    int e = g_tile_expert[blockIdx.y];
    if (e < 0) return;
    int row0 = blockIdx.y * BM;
    int n0   = blockIdx.x * 128;

    extern __shared__ __align__(1024) char smem[];
    uint32_t sb = smem_u32(smem);

    int tid  = threadIdx.x;
    int lane = tid & 31;
    int wid  = tid >> 5;
    int wm   = wid >> 2;      // 0..1
    int wn   = wid & 3;       // 0..3

    const __half* sA  = g_xg + (size_t)row0*DD;
    const __half* sW1 = g_w1 + (size_t)e*DD*HH + n0;
    const __half* sW3 = g_w3 + (size_t)e*DD*HH + n0;

    #define G1_LOAD(stage, it) do { \
        uint32_t bs = sb + (uint32_t)(stage)*(TILEA + 2*TILEW); \
        int k0 = (it)*32; \
        _Pragma("unroll") \
        for (int hf = 0; hf < 2; hf++) { \
            int idx = hf*256 + tid; \
            int ar = idx >> 2, ac = idx & 3; \
            cpasync16(bs + (uint32_t)ar*STRA + ac*16, sA + (size_t)ar*DD + k0 + ac*8); \
            int wr = idx >> 4, wc = idx & 15; \
            size_t gw = (size_t)(k0 + wr)*HH + wc*8; \
            uint32_t sw = (uint32_t)wr*STRB + wc*16; \
            cpasync16(bs + TILEA + sw, sW1 + gw); \
            cpasync16(bs + TILEA + TILEW + sw, sW3 + gw); \
        } \
    } while (0)

    float acc1[4][4][4], acc3[4][4][4];
    #pragma unroll
    for (int i = 0; i < 4; i++)
        #pragma unroll
        for (int j = 0; j < 4; j++)
            #pragma unroll
            for (int q = 0; q < 4; q++) { acc1[i][j][q] = 0.f; acc3[i][j][q] = 0.f; }

    int lr = (lane & 7) + 8*((lane >> 3) & 1);   // A row selector (0..15)
    int lk = (lane >> 4) * 16;                   // A k-halves (0/16 bytes)
    // B (trans) lane address: group g -> (k + 8*(g&1), n + 8*(g>>1))
    int bg = lane >> 3, br = lane & 7;
    uint32_t laneB = (uint32_t)((bg & 1)*8 + br)*STRB + (uint32_t)(bg >> 1)*16;

    const int NIT = DD/32;   // 32
    G1_LOAD(0, 0); CP_COMMIT();
    G1_LOAD(1, 1); CP_COMMIT();

    for (int it = 0; it < NIT; it++) {
        if (it + 2 < NIT) G1_LOAD((it+2)%3, it+2);
        CP_COMMIT();
        CP_WAIT2();
        __syncthreads();

        uint32_t bs  = sb + (uint32_t)(it%3)*(TILEA + 2*TILEW);
        uint32_t aA  = bs + (uint32_t)(wm*64 + lr)*STRA + lk;
        uint32_t bW1 = bs + TILEA + laneB + (uint32_t)(wn*32)*2;
        uint32_t bW3 = bW1 + TILEW;

        #pragma unroll
        for (int h16 = 0; h16 < 2; h16++) {
            uint32_t koA = h16*32;            // bytes along k in A rows
            uint32_t koB = (uint32_t)(h16*16)*STRB;  // 16 k-rows in B tile
            uint32_t Ah[4][4];
            #pragma unroll
            for (int mt = 0; mt < 4; mt++)
                ldmx4(Ah[mt], aA + mt*(16*STRA) + koA);
            #pragma unroll
            for (int np = 0; np < 2; np++) {
                uint32_t bh[4];
                ldmx4t(bh, bW1 + koB + np*32);
                #pragma unroll
                for (int s = 0; s < 2; s++) {
                    int nt = np*2 + s;
                    #pragma unroll
                    for (int mt = 0; mt < 4; mt++)
                        mma16816(acc1[mt][nt], Ah[mt], bh[2*s], bh[2*s+1]);
                }
            }
            #pragma unroll
            for (int np = 0; np < 2; np++) {
                uint32_t bh[4];
                ldmx4t(bh, bW3 + koB + np*32);
                #pragma unroll
                for (int s = 0; s < 2; s++) {
                    int nt = np*2 + s;
                    #pragma unroll
                    for (int mt = 0; mt < 4; mt++)
                        mma16816(acc3[mt][nt], Ah[mt], bh[2*s], bh[2*s+1]);
                }
            }
        }
        __syncthreads();
    }

    // epilogue: h = silu(z1+b1)*(z3+b3) -> fp16
    int qrow = lane >> 2, qcol = lane & 3;
    #pragma unroll
    for (int nt = 0; nt < 4; nt++) {
        int col = n0 + wn*32 + nt*8 + qcol*2;
        float2 bb1 = *(const float2*)(b1 + e*HH + col);
        float2 bb3 = *(const float2*)(b3 + e*HH + col);
        #pragma unroll
        for (int mt = 0; mt < 4; mt++) {
            #pragma unroll
            for (int hrow = 0; hrow < 2; hrow++) {
                int r = row0 + wm*64 + mt*16 + qrow + hrow*8;
                float z1a = acc1[mt][nt][2*hrow]   + bb1.x;
                float z1b = acc1[mt][nt][2*hrow+1] + bb1.y;
                float z3a = acc3[mt][nt][2*hrow]   + bb3.x;
                float z3b = acc3[mt][nt][2*hrow+1] + bb3.y;
                float ha = (z1a / (1.f + __expf(-z1a))) * z3a;
                float hb = (z1b / (1.f + __expf(-z1b))) * z3b;
                *reinterpret_cast<__half2*>(g_h + (size_t)r*HH + col) =
                    __floats2half2_rn(ha, hb);
            }
        }
    }
}

// ============================================================================
// GEMM2 (mma.sync fp16): eo = (h @ W2 + b2) * route_w  (W2 [E][H][D], trans-B)
// CTA: 128 x 128(D), BK=32, 3-stage. smem per stage: A(10240)+W2(8704)=18944.
// ============================================================================
__global__ void __launch_bounds__(256) gemm2_kernel(const float* __restrict__ b2) {
    int e = g_tile_expert[blockIdx.y];
    if (e < 0) return;
    int row0 = blockIdx.y * BM;
    int n0   = blockIdx.x * 128;

    extern __shared__ __align__(1024) char smem[];
    uint32_t sb = smem_u32(smem);

    int tid  = threadIdx.x;
    int lane = tid & 31;
    int wid  = tid >> 5;
    int wm   = wid >> 2;
    int wn   = wid & 3;

    const __half* sA = g_h  + (size_t)row0*HH;
    const __half* sW = g_w2 + (size_t)e*HH*DD + n0;

    #define G2_LOAD(stage, it) do { \
        uint32_t bs = sb + (uint32_t)(stage)*(TILEA + TILEW); \
        int k0 = (it)*32; \
        _Pragma("unroll") \
        for (int hf = 0; hf < 2; hf++) { \
            int idx = hf*256 + tid; \
            int ar = idx >> 2, ac = idx & 3; \
            cpasync16(bs + (uint32_t)ar*STRA + ac*16, sA + (size_t)ar*HH + k0 + ac*8); \
            int wr = idx >> 4, wc = idx & 15; \
            cpasync16(bs + TILEA + (uint32_t)wr*STRB + wc*16, \
                      sW + (size_t)(k0 + wr)*DD + wc*8); \
        } \
    } while (0)

    float acc[4][4][4];
    #pragma unroll
    for (int i = 0; i < 4; i++)
        #pragma unroll
        for (int j = 0; j < 4; j++)
            #pragma unroll
            for (int q = 0; q < 4; q++) acc[i][j][q] = 0.f;

    int lr = (lane & 7) + 8*((lane >> 3) & 1);
    int lk = (lane >> 4) * 16;
    int bg = lane >> 3, br = lane & 7;
    uint32_t laneB = (uint32_t)((bg & 1)*8 + br)*STRB + (uint32_t)(bg >> 1)*16;

    const int NIT = HH/32;   // 64
    G2_LOAD(0, 0); CP_COMMIT();
    G2_LOAD(1, 1); CP_COMMIT();

    for (int it = 0; it < NIT; it++) {
        if (it + 2 < NIT) G2_LOAD((it+2)%3, it+2);
        CP_COMMIT();
        CP_WAIT2();
        __syncthreads();

        uint32_t bs = sb + (uint32_t)(it%3)*(TILEA + TILEW);
        uint32_t aA = bs + (uint32_t)(wm*64 + lr)*STRA + lk;
        uint32_t bW = bs + TILEA + laneB + (uint32_t)(wn*32)*2;

        #pragma unroll
        for (int h16 = 0; h16 < 2; h16++) {
            uint32_t koA = h16*32;
            uint32_t koB = (uint32_t)(h16*16)*STRB;
            uint32_t Ah[4][4];
            #pragma unroll
            for (int mt = 0; mt < 4; mt++)
                ldmx4(Ah[mt], aA + mt*(16*STRA) + koA);
            #pragma unroll
            for (int np = 0; np < 2; np++) {
                uint32_t bh[4];
                ldmx4t(bh, bW + koB + np*32);
                #pragma unroll
                for (int s = 0; s < 2; s++) {
                    int nt = np*2 + s;
                    #pragma unroll
                    for (int mt = 0; mt < 4; mt++)
                        mma16816(acc[mt][nt], Ah[mt], bh[2*s], bh[2*s+1]);
                }
            }
        }
        __syncthreads();
    }

    // epilogue: (acc + b2) * route_w
    int qrow = lane >> 2, qcol = lane & 3;
    #pragma unroll
    for (int mt = 0; mt < 4; mt++) {
        #pragma unroll
        for (int hrow = 0; hrow < 2; hrow++) {
            int r = row0 + wm*64 + mt*16 + qrow + hrow*8;
            float wv = g_pair_w[r];
            #pragma unroll
            for (int nt = 0; nt < 4; nt++) {
                int col = n0 + wn*32 + nt*8 + qcol*2;
                float2 bb = *(const float2*)(b2 + e*DD + col);
                float2 o;
                o.x = (acc[mt][nt][2*hrow]   + bb.x) * wv;
                o.y = (acc[mt][nt][2*hrow+1] + bb.y) * wv;
                *(float2*)(g_eo + (size_t)r*DD + col) = o;
            }
        }
    }
}

// ---------------- combine ----------------
__global__ void combine_kernel(float* __restrict__ out) {
    int idx = blockIdx.x*blockDim.x + threadIdx.x;
    int n = idx >> 8;
    int q = idx & 255;
    if (n >= NTOK) return;
    int p0 = g_pair_slot[2*n];
    int p1 = g_pair_slot[2*n+1];
    const float4* eo = (const float4*)g_eo;
    float4 a = eo[(size_t)p0*256 + q];
    float4 b = eo[(size_t)p1*256 + q];
    ((float4*)out)[idx] = make_float4(a.x+b.x, a.y+b.y, a.z+b.z, a.w+b.w);
}

// ---------------- aux loss ----------------
__global__ void aux_kernel(float* __restrict__ out, int has_aux) {
    __shared__ float red[64];
    int tid = threadIdx.x;
    int e = tid & 7;
    float p = 0.f;
    for (int n = tid >> 3; n < NTOK; n += 8) p += g_scores[(size_t)n*EE + e];
    red[tid] = p;
    __syncthreads();
    for (int s = 32; s >= 8; s >>= 1) {
        if (tid < s) red[tid] += red[tid + s];
        __syncthreads();
    }
    if (tid == 0 && has_aux) {
        float aux = 0.f;
        for (int ee = 0; ee < EE; ee++) {
            float f = (float)g_counts[ee] / (float)(NTOK*KTOP);
            float P = red[ee] / (float)NTOK;
            aux += f*P;
        }
        out[(size_t)NTOK*DD] = 0.01f * (float)EE * aux;
    }
}

// ---------------- launch ----------------
extern "C" void kernel_launch(void* const* d_in, const int* in_sizes, int n_in,
                              void* d_out, int out_size) {
    const float* x  = (const float*)d_in[0];
    const float* Wg = (const float*)d_in[1];
    const float* W1 = (const float*)d_in[2];
    const float* b1 = (const float*)d_in[3];
    const float* W2 = (const float*)d_in[4];
    const float* b2 = (const float*)d_in[5];
    const float* W3 = (const float*)d_in[6];
    const float* b3 = (const float*)d_in[7];
    float* out = (float*)d_out;

    const int G1_SMEM = 3*(TILEA + 2*TILEW);   // 82944
    const int G2_SMEM = 3*(TILEA + TILEW);     // 56832
    cudaFuncSetAttribute(gemm1_kernel, cudaFuncAttributeMaxDynamicSharedMemorySize, G1_SMEM);
    cudaFuncSetAttribute(gemm2_kernel, cudaFuncAttributeMaxDynamicSharedMemorySize, G2_SMEM);

    init_kernel<<<(MAXPAD + 255)/256, 256>>>();
    gate_kernel<<<NTOK/8, 256>>>(x, Wg);
    setup_kernel<<<1, 256>>>();
    assign_kernel<<<NTOK/256, 256>>>();
    gatherx_kernel<<<MAXPAD, 256>>>(x);
    convall_kernel<<<dim3((EE*DD*HH)/(256*8), 1, 3), 256>>>(W1, W3, W2);
    gemm1_kernel<<<dim3(HH/128, MAXTILES), 256, G1_SMEM>>>(b1, b3);
    gemm2_kernel<<<dim3(DD/128, MAXTILES), 256, G2_SMEM>>>(b2);
    combine_kernel<<<(NTOK*(DD/4))/256, 256>>>(out);
    aux_kernel<<<1, 64>>>(out, out_size > NTOK*DD ? 1 : 0);
}

// round 7
// speedup vs baseline: 4.8419x; 1.0089x over previous
#include <cuda_runtime.h>
#include <cuda_bf16.h>
#include <cuda_fp16.h>
#include <math.h>
#include <stdint.h>

#define DD     1024
#define HH     2048
#define EE     8
#define NTOK   8192
#define KTOP   2
#define NP     (NTOK*KTOP)      // 16384
#define BM     128
#define MAXPAD (NP + EE*BM)     // 17408
#define MAXTILES (MAXPAD/BM)    // 136

#define STRA   80               // A smem row stride (32 fp16 = 64B + 16B pad)
#define TILEA  (128*STRA)       // 10240
#define STRB   272              // B smem row stride (128 fp16 = 256B + 16B pad)
#define TILEW  (32*STRB)        // 8704

// ---------------- device scratch ----------------
__device__ float g_pair_w[MAXPAD];
__device__ int   g_pair_slot[NP];
__device__ int   g_topk_idx[NP];
__device__ float g_topk_val[NP];
__device__ float g_scores[NTOK*EE];
__device__ int   g_counts[EE];
__device__ int   g_cursor[EE];
__device__ int   g_pstart[EE+1];
__device__ int   g_tile_expert[MAXTILES];

__device__ __align__(16) __half g_xg [(size_t)MAXPAD*DD];      // fp16 x (gathered)
__device__ __align__(16) __half g_w1 [(size_t)EE*DD*HH];       // fp16 W1 [E][D][H]
__device__ __align__(16) __half g_w3 [(size_t)EE*DD*HH];
__device__ __align__(16) __half g_w2 [(size_t)EE*HH*DD];       // fp16 W2 [E][H][D]
__device__ __align__(16) __half g_h  [(size_t)MAXPAD*HH];      // fp16 h
__device__ __align__(16) float  g_eo [(size_t)MAXPAD*DD];

// ---------------- PTX helpers (baseline PTX only: sm_80-class) ----------------
__device__ __forceinline__ uint32_t smem_u32(const void* p){
    uint32_t a;
    asm("{ .reg .u64 t; cvta.to.shared.u64 t, %1; cvt.u32.u64 %0, t; }" : "=r"(a) : "l"(p));
    return a;
}
__device__ __forceinline__ void cpasync16(uint32_t dst, const void* src){
    asm volatile("cp.async.cg.shared.global [%0], [%1], 16;" :: "r"(dst), "l"(src));
}
#define CP_COMMIT() asm volatile("cp.async.commit_group;" ::: "memory")
#define CP_WAIT2()  asm volatile("cp.async.wait_group 2;" ::: "memory")

__device__ __forceinline__ void ldmx4(uint32_t (&r)[4], uint32_t addr){
    asm volatile("ldmatrix.sync.aligned.m8n8.x4.shared.b16 {%0,%1,%2,%3}, [%4];"
        : "=r"(r[0]), "=r"(r[1]), "=r"(r[2]), "=r"(r[3]) : "r"(addr));
}
__device__ __forceinline__ void ldmx4t(uint32_t (&r)[4], uint32_t addr){
    asm volatile("ldmatrix.sync.aligned.m8n8.x4.trans.shared.b16 {%0,%1,%2,%3}, [%4];"
        : "=r"(r[0]), "=r"(r[1]), "=r"(r[2]), "=r"(r[3]) : "r"(addr));
}
__device__ __forceinline__ void mma16816(float (&c)[4], const uint32_t (&a)[4],
                                         uint32_t b0, uint32_t b1){
    asm volatile(
        "mma.sync.aligned.m16n8k16.row.col.f32.f16.f16.f32 "
        "{%0,%1,%2,%3}, {%4,%5,%6,%7}, {%8,%9}, {%0,%1,%2,%3};"
        : "+f"(c[0]), "+f"(c[1]), "+f"(c[2]), "+f"(c[3])
        : "r"(a[0]), "r"(a[1]), "r"(a[2]), "r"(a[3]), "r"(b0), "r"(b1));
}

// ---------------- init: only the counters ----------------
__global__ void init_kernel() {
    int i = threadIdx.x;
    if (i < EE) { g_counts[i] = 0; g_cursor[i] = 0; }
}

// ---------------- gating: Wg staged in smem, x in registers ----------------
__global__ void __launch_bounds__(256) gate_kernel(const float* __restrict__ x,
                                                   const float* __restrict__ Wg) {
    __shared__ float sWg[EE*DD];
    for (int i = threadIdx.x; i < EE*DD/4; i += 256)
        ((float4*)sWg)[i] = ((const float4*)Wg)[i];
    __syncthreads();

    int warp = threadIdx.x >> 5;
    int lane = threadIdx.x & 31;
    int n = blockIdx.x*8 + warp;
    if (n >= NTOK) return;

    const float4* xr = (const float4*)(x + (size_t)n*DD);
    float4 xv[8];
    #pragma unroll
    for (int q = 0; q < 8; q++) xv[q] = xr[lane + q*32];

    float pr[EE];
    #pragma unroll
    for (int e = 0; e < EE; e++) {
        const float4* wr = (const float4*)(sWg + e*DD);
        float p = 0.f;
        #pragma unroll
        for (int q = 0; q < 8; q++) {
            float4 w = wr[lane + q*32];
            p += xv[q].x*w.x + xv[q].y*w.y + xv[q].z*w.z + xv[q].w*w.w;
        }
        #pragma unroll
        for (int off = 16; off; off >>= 1) p += __shfl_xor_sync(0xffffffffu, p, off);
        pr[e] = p;
    }
    float m = pr[0];
    #pragma unroll
    for (int e = 1; e < EE; e++) m = fmaxf(m, pr[e]);
    float s = 0.f;
    #pragma unroll
    for (int e = 0; e < EE; e++) { pr[e] = __expf(pr[e]-m); s += pr[e]; }
    float inv = 1.f/s;
    #pragma unroll
    for (int e = 0; e < EE; e++) pr[e] *= inv;

    int i1 = 0; float v1 = pr[0];
    #pragma unroll
    for (int e = 1; e < EE; e++) if (pr[e] > v1) { v1 = pr[e]; i1 = e; }
    int i2 = -1; float v2 = -1.f;
    #pragma unroll
    for (int e = 0; e < EE; e++) if (e != i1 && pr[e] > v2) { v2 = pr[e]; i2 = e; }

    if (lane == 0) {
        #pragma unroll
        for (int e = 0; e < EE; e++) g_scores[(size_t)n*EE + e] = pr[e];
        g_topk_idx[2*n]   = i1; g_topk_val[2*n]   = v1;
        g_topk_idx[2*n+1] = i2; g_topk_val[2*n+1] = v2;
        atomicAdd(&g_counts[i1], 1);
        atomicAdd(&g_counts[i2], 1);
    }
}

// ---------------- setup (parallel, 1 block) ----------------
__global__ void setup_kernel() {
    __shared__ int ps[EE+1], cnt[EE];
    int tid = threadIdx.x;
    if (tid == 0) {
        int off = 0;
        for (int e = 0; e < EE; e++) {
            ps[e] = off;
            int c = g_counts[e];
            cnt[e] = c;
            off = (off + c + BM - 1)/BM*BM;
        }
        ps[EE] = off;
    }
    __syncthreads();
    if (tid <= EE) g_pstart[tid] = ps[tid];
    if (tid < MAXTILES) {
        int r0 = tid*BM, e = -1;
        #pragma unroll
        for (int ee = 0; ee < EE; ee++)
            if (r0 >= ps[ee] && r0 < ps[ee] + cnt[ee]) e = ee;
        g_tile_expert[tid] = e;
    }
}

// ---------------- fused assign + gather (one warp per pair) ----------------
__global__ void __launch_bounds__(256) assign_gather_kernel(const float* __restrict__ x) {
    int warp = threadIdx.x >> 5;
    int lane = threadIdx.x & 31;
    int p = blockIdx.x*8 + warp;       // pair index
    if (p >= NP) return;
    int n = p >> 1;

    int slot;
    if (lane == 0) {
        int e = g_topk_idx[p];
        int pos = atomicAdd(&g_cursor[e], 1);
        slot = g_pstart[e] + pos;
        g_pair_w[slot]  = g_topk_val[p];
        g_pair_slot[p]  = slot;
    }
    slot = __shfl_sync(0xffffffffu, slot, 0);

    const float4* xr = (const float4*)(x + (size_t)n*DD);
    __half2* dh = (__half2*)(g_xg + (size_t)slot*DD);
    #pragma unroll
    for (int q = 0; q < 8; q++) {
        float4 v = xr[lane + q*32];
        dh[2*(lane + q*32)]     = __floats2half2_rn(v.x, v.y);
        dh[2*(lane + q*32) + 1] = __floats2half2_rn(v.z, v.w);
    }
}

// ---------------- flat fp32->fp16 conversions (side stream) ----------------
__global__ void conv13_kernel(const float* __restrict__ W1, const float* __restrict__ W3) {
    const float* src = blockIdx.z ? W3 : W1;
    __half* dst = blockIdx.z ? g_w3 : g_w1;
    size_t i = ((size_t)blockIdx.x*256 + threadIdx.x)*8;
    float4 v0 = *(const float4*)(src + i);
    float4 v1 = *(const float4*)(src + i + 4);
    __half2 h[4];
    h[0] = __floats2half2_rn(v0.x, v0.y);
    h[1] = __floats2half2_rn(v0.z, v0.w);
    h[2] = __floats2half2_rn(v1.x, v1.y);
    h[3] = __floats2half2_rn(v1.z, v1.w);
    *(uint4*)(dst + i) = *(uint4*)h;
}
__global__ void conv2_kernel(const float* __restrict__ W2) {
    size_t i = ((size_t)blockIdx.x*256 + threadIdx.x)*8;
    float4 v0 = *(const float4*)(W2 + i);
    float4 v1 = *(const float4*)(W2 + i + 4);
    __half2 h[4];
    h[0] = __floats2half2_rn(v0.x, v0.y);
    h[1] = __floats2half2_rn(v0.z, v0.w);
    h[2] = __floats2half2_rn(v1.x, v1.y);
    h[3] = __floats2half2_rn(v1.z, v1.w);
    *(uint4*)(g_w2 + i) = *(uint4*)h;
}

// ============================================================================
// GEMM1 (mma.sync fp16): z1 = X@W1, z3 = X@W3 (trans-B from k-major rows);
// h = silu(z1+b1)*(z3+b3). CTA 128x128, BK=32, 3-stage. 8 warps 2x4.
// ============================================================================
__global__ void __launch_bounds__(256) gemm1_kernel(const float* __restrict__ b1,
                                                    const float* __restrict__ b3) {
    int e = g_tile_expert[blockIdx.y];
    if (e < 0) return;
    int row0 = blockIdx.y * BM;
    int n0   = blockIdx.x * 128;

    extern __shared__ __align__(1024) char smem[];
    uint32_t sb = smem_u32(smem);

    int tid  = threadIdx.x;
    int lane = tid & 31;
    int wid  = tid >> 5;
    int wm   = wid >> 2;
    int wn   = wid & 3;

    const __half* sA  = g_xg + (size_t)row0*DD;
    const __half* sW1 = g_w1 + (size_t)e*DD*HH + n0;
    const __half* sW3 = g_w3 + (size_t)e*DD*HH + n0;

    #define G1_LOAD(stage, it) do { \
        uint32_t bs = sb + (uint32_t)(stage)*(TILEA + 2*TILEW); \
        int k0 = (it)*32; \
        _Pragma("unroll") \
        for (int hf = 0; hf < 2; hf++) { \
            int idx = hf*256 + tid; \
            int ar = idx >> 2, ac = idx & 3; \
            cpasync16(bs + (uint32_t)ar*STRA + ac*16, sA + (size_t)ar*DD + k0 + ac*8); \
            int wr = idx >> 4, wc = idx & 15; \
            size_t gw = (size_t)(k0 + wr)*HH + wc*8; \
            uint32_t sw = (uint32_t)wr*STRB + wc*16; \
            cpasync16(bs + TILEA + sw, sW1 + gw); \
            cpasync16(bs + TILEA + TILEW + sw, sW3 + gw); \
        } \
    } while (0)

    float acc1[4][4][4], acc3[4][4][4];
    #pragma unroll
    for (int i = 0; i < 4; i++)
        #pragma unroll
        for (int j = 0; j < 4; j++)
            #pragma unroll
            for (int q = 0; q < 4; q++) { acc1[i][j][q] = 0.f; acc3[i][j][q] = 0.f; }

    int lr = (lane & 7) + 8*((lane >> 3) & 1);
    int lk = (lane >> 4) * 16;
    int bg = lane >> 3, br = lane & 7;
    uint32_t laneB = (uint32_t)((bg & 1)*8 + br)*STRB + (uint32_t)(bg >> 1)*16;

    const int NIT = DD/32;   // 32
    G1_LOAD(0, 0); CP_COMMIT();
    G1_LOAD(1, 1); CP_COMMIT();

    for (int it = 0; it < NIT; it++) {
        if (it + 2 < NIT) G1_LOAD((it+2)%3, it+2);
        CP_COMMIT();
        CP_WAIT2();
        __syncthreads();

        uint32_t bs  = sb + (uint32_t)(it%3)*(TILEA + 2*TILEW);
        uint32_t aA  = bs + (uint32_t)(wm*64 + lr)*STRA + lk;
        uint32_t bW1 = bs + TILEA + laneB + (uint32_t)(wn*32)*2;
        uint32_t bW3 = bW1 + TILEW;

        #pragma unroll
        for (int h16 = 0; h16 < 2; h16++) {
            uint32_t koA = h16*32;
            uint32_t koB = (uint32_t)(h16*16)*STRB;
            uint32_t Ah[4][4];
            #pragma unroll
            for (int mt = 0; mt < 4; mt++)
                ldmx4(Ah[mt], aA + mt*(16*STRA) + koA);
            #pragma unroll
            for (int np = 0; np < 2; np++) {
                uint32_t bh[4];
                ldmx4t(bh, bW1 + koB + np*32);
                #pragma unroll
                for (int s = 0; s < 2; s++) {
                    int nt = np*2 + s;
                    #pragma unroll
                    for (int mt = 0; mt < 4; mt++)
                        mma16816(acc1[mt][nt], Ah[mt], bh[2*s], bh[2*s+1]);
                }
            }
            #pragma unroll
            for (int np = 0; np < 2; np++) {
                uint32_t bh[4];
                ldmx4t(bh, bW3 + koB + np*32);
                #pragma unroll
                for (int s = 0; s < 2; s++) {
                    int nt = np*2 + s;
                    #pragma unroll
                    for (int mt = 0; mt < 4; mt++)
                        mma16816(acc3[mt][nt], Ah[mt], bh[2*s], bh[2*s+1]);
                }
            }
        }
        __syncthreads();
    }

    int qrow = lane >> 2, qcol = lane & 3;
    #pragma unroll
    for (int nt = 0; nt < 4; nt++) {
        int col = n0 + wn*32 + nt*8 + qcol*2;
        float2 bb1 = *(const float2*)(b1 + e*HH + col);
        float2 bb3 = *(const float2*)(b3 + e*HH + col);
        #pragma unroll
        for (int mt = 0; mt < 4; mt++) {
            #pragma unroll
            for (int hrow = 0; hrow < 2; hrow++) {
                int r = row0 + wm*64 + mt*16 + qrow + hrow*8;
                float z1a = acc1[mt][nt][2*hrow]   + bb1.x;
                float z1b = acc1[mt][nt][2*hrow+1] + bb1.y;
                float z3a = acc3[mt][nt][2*hrow]   + bb3.x;
                float z3b = acc3[mt][nt][2*hrow+1] + bb3.y;
                float ha = (z1a / (1.f + __expf(-z1a))) * z3a;
                float hb = (z1b / (1.f + __expf(-z1b))) * z3b;
                *reinterpret_cast<__half2*>(g_h + (size_t)r*HH + col) =
                    __floats2half2_rn(ha, hb);
            }
        }
    }
}

// ============================================================================
// GEMM2 (mma.sync fp16): eo = (h @ W2 + b2) * route_w; 2 CTAs/SM target.
// ============================================================================
__global__ void __launch_bounds__(256, 2) gemm2_kernel(const float* __restrict__ b2) {
    int e = g_tile_expert[blockIdx.y];
    if (e < 0) return;
    int row0 = blockIdx.y * BM;
    int n0   = blockIdx.x * 128;

    extern __shared__ __align__(1024) char smem[];
    uint32_t sb = smem_u32(smem);

    int tid  = threadIdx.x;
    int lane = tid & 31;
    int wid  = tid >> 5;
    int wm   = wid >> 2;
    int wn   = wid & 3;

    const __half* sA = g_h  + (size_t)row0*HH;
    const __half* sW = g_w2 + (size_t)e*HH*DD + n0;

    #define G2_LOAD(stage, it) do { \
        uint32_t bs = sb + (uint32_t)(stage)*(TILEA + TILEW); \
        int k0 = (it)*32; \
        _Pragma("unroll") \
        for (int hf = 0; hf < 2; hf++) { \
            int idx = hf*256 + tid; \
            int ar = idx >> 2, ac = idx & 3; \
            cpasync16(bs + (uint32_t)ar*STRA + ac*16, sA + (size_t)ar*HH + k0 + ac*8); \
            int wr = idx >> 4, wc = idx & 15; \
            cpasync16(bs + TILEA + (uint32_t)wr*STRB + wc*16, \
                      sW + (size_t)(k0 + wr)*DD + wc*8); \
        } \
    } while (0)

    float acc[4][4][4];
    #pragma unroll
    for (int i = 0; i < 4; i++)
        #pragma unroll
        for (int j = 0; j < 4; j++)
            #pragma unroll
            for (int q = 0; q < 4; q++) acc[i][j][q] = 0.f;

    int lr = (lane & 7) + 8*((lane >> 3) & 1);
    int lk = (lane >> 4) * 16;
    int bg = lane >> 3, br = lane & 7;
    uint32_t laneB = (uint32_t)((bg & 1)*8 + br)*STRB + (uint32_t)(bg >> 1)*16;

    const int NIT = HH/32;   // 64
    G2_LOAD(0, 0); CP_COMMIT();
    G2_LOAD(1, 1); CP_COMMIT();

    for (int it = 0; it < NIT; it++) {
        if (it + 2 < NIT) G2_LOAD((it+2)%3, it+2);
        CP_COMMIT();
        CP_WAIT2();
        __syncthreads();

        uint32_t bs = sb + (uint32_t)(it%3)*(TILEA + TILEW);
        uint32_t aA = bs + (uint32_t)(wm*64 + lr)*STRA + lk;
        uint32_t bW = bs + TILEA + laneB + (uint32_t)(wn*32)*2;

        #pragma unroll
        for (int h16 = 0; h16 < 2; h16++) {
            uint32_t koA = h16*32;
            uint32_t koB = (uint32_t)(h16*16)*STRB;
            uint32_t Ah[4][4];
            #pragma unroll
            for (int mt = 0; mt < 4; mt++)
                ldmx4(Ah[mt], aA + mt*(16*STRA) + koA);
            #pragma unroll
            for (int np = 0; np < 2; np++) {
                uint32_t bh[4];
                ldmx4t(bh, bW + koB + np*32);
                #pragma unroll
                for (int s = 0; s < 2; s++) {
                    int nt = np*2 + s;
                    #pragma unroll
                    for (int mt = 0; mt < 4; mt++)
                        mma16816(acc[mt][nt], Ah[mt], bh[2*s], bh[2*s+1]);
                }
            }
        }
        __syncthreads();
    }

    int qrow = lane >> 2, qcol = lane & 3;
    #pragma unroll
    for (int mt = 0; mt < 4; mt++) {
        #pragma unroll
        for (int hrow = 0; hrow < 2; hrow++) {
            int r = row0 + wm*64 + mt*16 + qrow + hrow*8;
            float wv = g_pair_w[r];
            #pragma unroll
            for (int nt = 0; nt < 4; nt++) {
                int col = n0 + wn*32 + nt*8 + qcol*2;
                float2 bb = *(const float2*)(b2 + e*DD + col);
                float2 o;
                o.x = (acc[mt][nt][2*hrow]   + bb.x) * wv;
                o.y = (acc[mt][nt][2*hrow+1] + bb.y) * wv;
                *(float2*)(g_eo + (size_t)r*DD + col) = o;
            }
        }
    }
}

// ---------------- combine ----------------
__global__ void combine_kernel(float* __restrict__ out) {
    int idx = blockIdx.x*blockDim.x + threadIdx.x;
    int n = idx >> 8;
    int q = idx & 255;
    if (n >= NTOK) return;
    int p0 = g_pair_slot[2*n];
    int p1 = g_pair_slot[2*n+1];
    const float4* eo = (const float4*)g_eo;
    float4 a = eo[(size_t)p0*256 + q];
    float4 b = eo[(size_t)p1*256 + q];
    ((float4*)out)[idx] = make_float4(a.x+b.x, a.y+b.y, a.z+b.z, a.w+b.w);
}

// ---------------- aux loss ----------------
__global__ void aux_kernel(float* __restrict__ out, int has_aux) {
    __shared__ float red[64];
    int tid = threadIdx.x;
    int e = tid & 7;
    float p = 0.f;
    for (int n = tid >> 3; n < NTOK; n += 8) p += g_scores[(size_t)n*EE + e];
    red[tid] = p;
    __syncthreads();
    for (int s = 32; s >= 8; s >>= 1) {
        if (tid < s) red[tid] += red[tid + s];
        __syncthreads();
    }
    if (tid == 0 && has_aux) {
        float aux = 0.f;
        for (int ee = 0; ee < EE; ee++) {
            float f = (float)g_counts[ee] / (float)(NTOK*KTOP);
            float P = red[ee] / (float)NTOK;
            aux += f*P;
        }
        out[(size_t)NTOK*DD] = 0.01f * (float)EE * aux;
    }
}

// ---------------- launch (fork-join: conversions overlap routing/gemm1) ------
extern "C" void kernel_launch(void* const* d_in, const int* in_sizes, int n_in,
                              void* d_out, int out_size) {
    const float* x  = (const float*)d_in[0];
    const float* Wg = (const float*)d_in[1];
    const float* W1 = (const float*)d_in[2];
    const float* b1 = (const float*)d_in[3];
    const float* W2 = (const float*)d_in[4];
    const float* b2 = (const float*)d_in[5];
    const float* W3 = (const float*)d_in[6];
    const float* b3 = (const float*)d_in[7];
    float* out = (float*)d_out;

    const int G1_SMEM = 3*(TILEA + 2*TILEW);   // 82944
    const int G2_SMEM = 3*(TILEA + TILEW);     // 56832
    cudaFuncSetAttribute(gemm1_kernel, cudaFuncAttributeMaxDynamicSharedMemorySize, G1_SMEM);
    cudaFuncSetAttribute(gemm2_kernel, cudaFuncAttributeMaxDynamicSharedMemorySize, G2_SMEM);

    cudaStream_t s2 = 0;
    cudaEvent_t evFork = 0, evW13 = 0, evW2 = 0;
    bool forked = (cudaStreamCreateWithFlags(&s2, cudaStreamNonBlocking) == cudaSuccess)
               && (cudaEventCreateWithFlags(&evFork, cudaEventDisableTiming) == cudaSuccess)
               && (cudaEventCreateWithFlags(&evW13,  cudaEventDisableTiming) == cudaSuccess)
               && (cudaEventCreateWithFlags(&evW2,   cudaEventDisableTiming) == cudaSuccess);

    if (forked) {
        cudaEventRecord(evFork, 0);
        cudaStreamWaitEvent(s2, evFork, 0);
        conv13_kernel<<<dim3((EE*DD*HH)/(256*8), 1, 2), 256, 0, s2>>>(W1, W3);
        cudaEventRecord(evW13, s2);
        conv2_kernel<<<dim3((EE*DD*HH)/(256*8), 1, 1), 256, 0, s2>>>(W2);
        cudaEventRecord(evW2, s2);
    } else {
        conv13_kernel<<<dim3((EE*DD*HH)/(256*8), 1, 2), 256>>>(W1, W3);
        conv2_kernel<<<dim3((EE*DD*HH)/(256*8), 1, 1), 256>>>(W2);
    }

    init_kernel<<<1, 32>>>();
    gate_kernel<<<NTOK/8, 256>>>(x, Wg);
    setup_kernel<<<1, 256>>>();
    assign_gather_kernel<<<NP/8, 256>>>(x);

    if (forked) cudaStreamWaitEvent(0, evW13, 0);
    gemm1_kernel<<<dim3(HH/128, MAXTILES), 256, G1_SMEM>>>(b1, b3);
    if (forked) cudaStreamWaitEvent(0, evW2, 0);
    gemm2_kernel<<<dim3(DD/128, MAXTILES), 256, G2_SMEM>>>(b2);
    combine_kernel<<<(NTOK*(DD/4))/256, 256>>>(out);
    aux_kernel<<<1, 64>>>(out, out_size > NTOK*DD ? 1 : 0);
}

// round 8
// speedup vs baseline: 5.2653x; 1.0875x over previous
#include <cuda_runtime.h>
#include <cuda_bf16.h>
#include <cuda_fp16.h>
#include <math.h>
#include <stdint.h>

#define DD     1024
#define HH     2048
#define EE     8
#define NTOK   8192
#define KTOP   2
#define NP     (NTOK*KTOP)      // 16384
#define BM     128
#define MAXPAD (NP + EE*BM)     // 17408
#define MAXTILES (MAXPAD/BM)    // 136

#define STRA   80               // A smem row stride (32 fp16 = 64B + 16B pad)
#define TILEA  (128*STRA)       // 10240
#define STRB   272              // B smem row stride (128 fp16 = 256B + 16B pad)
#define TILEW  (32*STRB)        // 8704

// ---------------- device scratch ----------------
__device__ float g_pair_w[MAXPAD];
__device__ int   g_pair_slot[NP];
__device__ int   g_topk_idx[NP];
__device__ float g_topk_val[NP];
__device__ float g_scores[NTOK*EE];
__device__ int   g_counts[EE];
__device__ int   g_cursor[EE];
__device__ int   g_pstart[EE+1];
__device__ int   g_tile_expert[MAXTILES];

__device__ __align__(16) __half g_xg [(size_t)MAXPAD*DD];      // fp16 x (gathered)
__device__ __align__(16) __half g_w1 [(size_t)EE*DD*HH];       // fp16 W1 [E][D][H]
__device__ __align__(16) __half g_w3 [(size_t)EE*DD*HH];
__device__ __align__(16) __half g_w2 [(size_t)EE*HH*DD];       // fp16 W2 [E][H][D]
__device__ __align__(16) __half g_h  [(size_t)MAXPAD*HH];      // fp16 h
__device__ __align__(16) float  g_eo [(size_t)MAXPAD*DD];

// ---------------- PTX helpers (baseline PTX only: sm_80-class) ----------------
__device__ __forceinline__ uint32_t smem_u32(const void* p){
    uint32_t a;
    asm("{ .reg .u64 t; cvta.to.shared.u64 t, %1; cvt.u32.u64 %0, t; }" : "=r"(a) : "l"(p));
    return a;
}
__device__ __forceinline__ void cpasync16(uint32_t dst, const void* src){
    asm volatile("cp.async.cg.shared.global [%0], [%1], 16;" :: "r"(dst), "l"(src));
}
#define CP_COMMIT() asm volatile("cp.async.commit_group;" ::: "memory")
#define CP_WAIT3()  asm volatile("cp.async.wait_group 3;" ::: "memory")

__device__ __forceinline__ void ldmx4(uint32_t (&r)[4], uint32_t addr){
    asm volatile("ldmatrix.sync.aligned.m8n8.x4.shared.b16 {%0,%1,%2,%3}, [%4];"
        : "=r"(r[0]), "=r"(r[1]), "=r"(r[2]), "=r"(r[3]) : "r"(addr));
}
__device__ __forceinline__ void ldmx4t(uint32_t (&r)[4], uint32_t addr){
    asm volatile("ldmatrix.sync.aligned.m8n8.x4.trans.shared.b16 {%0,%1,%2,%3}, [%4];"
        : "=r"(r[0]), "=r"(r[1]), "=r"(r[2]), "=r"(r[3]) : "r"(addr));
}
__device__ __forceinline__ void mma16816(float (&c)[4], const uint32_t (&a)[4],
                                         uint32_t b0, uint32_t b1){
    asm volatile(
        "mma.sync.aligned.m16n8k16.row.col.f32.f16.f16.f32 "
        "{%0,%1,%2,%3}, {%4,%5,%6,%7}, {%8,%9}, {%0,%1,%2,%3};"
        : "+f"(c[0]), "+f"(c[1]), "+f"(c[2]), "+f"(c[3])
        : "r"(a[0]), "r"(a[1]), "r"(a[2]), "r"(a[3]), "r"(b0), "r"(b1));
}

// ---------------- init: only the counters ----------------
__global__ void init_kernel() {
    int i = threadIdx.x;
    if (i < EE) { g_counts[i] = 0; g_cursor[i] = 0; }
}

// ---------------- gating: Wg staged in smem, x in registers ----------------
__global__ void __launch_bounds__(256) gate_kernel(const float* __restrict__ x,
                                                   const float* __restrict__ Wg) {
    __shared__ float sWg[EE*DD];
    for (int i = threadIdx.x; i < EE*DD/4; i += 256)
        ((float4*)sWg)[i] = ((const float4*)Wg)[i];
    __syncthreads();

    int warp = threadIdx.x >> 5;
    int lane = threadIdx.x & 31;
    int n = blockIdx.x*8 + warp;
    if (n >= NTOK) return;

    const float4* xr = (const float4*)(x + (size_t)n*DD);
    float4 xv[8];
    #pragma unroll
    for (int q = 0; q < 8; q++) xv[q] = xr[lane + q*32];

    float pr[EE];
    #pragma unroll
    for (int e = 0; e < EE; e++) {
        const float4* wr = (const float4*)(sWg + e*DD);
        float p = 0.f;
        #pragma unroll
        for (int q = 0; q < 8; q++) {
            float4 w = wr[lane + q*32];
            p += xv[q].x*w.x + xv[q].y*w.y + xv[q].z*w.z + xv[q].w*w.w;
        }
        #pragma unroll
        for (int off = 16; off; off >>= 1) p += __shfl_xor_sync(0xffffffffu, p, off);
        pr[e] = p;
    }
    float m = pr[0];
    #pragma unroll
    for (int e = 1; e < EE; e++) m = fmaxf(m, pr[e]);
    float s = 0.f;
    #pragma unroll
    for (int e = 0; e < EE; e++) { pr[e] = __expf(pr[e]-m); s += pr[e]; }
    float inv = 1.f/s;
    #pragma unroll
    for (int e = 0; e < EE; e++) pr[e] *= inv;

    int i1 = 0; float v1 = pr[0];
    #pragma unroll
    for (int e = 1; e < EE; e++) if (pr[e] > v1) { v1 = pr[e]; i1 = e; }
    int i2 = -1; float v2 = -1.f;
    #pragma unroll
    for (int e = 0; e < EE; e++) if (e != i1 && pr[e] > v2) { v2 = pr[e]; i2 = e; }

    if (lane == 0) {
        #pragma unroll
        for (int e = 0; e < EE; e++) g_scores[(size_t)n*EE + e] = pr[e];
        g_topk_idx[2*n]   = i1; g_topk_val[2*n]   = v1;
        g_topk_idx[2*n+1] = i2; g_topk_val[2*n+1] = v2;
        atomicAdd(&g_counts[i1], 1);
        atomicAdd(&g_counts[i2], 1);
    }
}

// ---------------- setup (parallel, 1 block) ----------------
__global__ void setup_kernel() {
    __shared__ int ps[EE+1], cnt[EE];
    int tid = threadIdx.x;
    if (tid == 0) {
        int off = 0;
        for (int e = 0; e < EE; e++) {
            ps[e] = off;
            int c = g_counts[e];
            cnt[e] = c;
            off = (off + c + BM - 1)/BM*BM;
        }
        ps[EE] = off;
    }
    __syncthreads();
    if (tid <= EE) g_pstart[tid] = ps[tid];
    if (tid < MAXTILES) {
        int r0 = tid*BM, e = -1;
        #pragma unroll
        for (int ee = 0; ee < EE; ee++)
            if (r0 >= ps[ee] && r0 < ps[ee] + cnt[ee]) e = ee;
        g_tile_expert[tid] = e;
    }
}

// ---------------- fused assign + gather (one warp per TOKEN; row read once) --
__global__ void __launch_bounds__(256) assign_gather_kernel(const float* __restrict__ x) {
    int warp = threadIdx.x >> 5;
    int lane = threadIdx.x & 31;
    int n = blockIdx.x*8 + warp;
    if (n >= NTOK) return;

    int slot = 0;
    if (lane < 2) {
        int p = 2*n + lane;
        int e = g_topk_idx[p];
        int pos = atomicAdd(&g_cursor[e], 1);
        slot = g_pstart[e] + pos;
        g_pair_w[slot] = g_topk_val[p];
        g_pair_slot[p] = slot;
    }
    int slot0 = __shfl_sync(0xffffffffu, slot, 0);
    int slot1 = __shfl_sync(0xffffffffu, slot, 1);

    const float4* xr = (const float4*)(x + (size_t)n*DD);
    __half2* d0 = (__half2*)(g_xg + (size_t)slot0*DD);
    __half2* d1 = (__half2*)(g_xg + (size_t)slot1*DD);
    #pragma unroll
    for (int q = 0; q < 8; q++) {
        float4 v = xr[lane + q*32];
        __half2 a = __floats2half2_rn(v.x, v.y);
        __half2 b = __floats2half2_rn(v.z, v.w);
        d0[2*(lane + q*32)]     = a;
        d0[2*(lane + q*32) + 1] = b;
        d1[2*(lane + q*32)]     = a;
        d1[2*(lane + q*32) + 1] = b;
    }
}

// ---------------- flat fp32->fp16 conversions (side stream) ----------------
__global__ void conv13_kernel(const float* __restrict__ W1, const float* __restrict__ W3) {
    const float* src = blockIdx.z ? W3 : W1;
    __half* dst = blockIdx.z ? g_w3 : g_w1;
    size_t i = ((size_t)blockIdx.x*256 + threadIdx.x)*8;
    float4 v0 = *(const float4*)(src + i);
    float4 v1 = *(const float4*)(src + i + 4);
    __half2 h[4];
    h[0] = __floats2half2_rn(v0.x, v0.y);
    h[1] = __floats2half2_rn(v0.z, v0.w);
    h[2] = __floats2half2_rn(v1.x, v1.y);
    h[3] = __floats2half2_rn(v1.z, v1.w);
    *(uint4*)(dst + i) = *(uint4*)h;
}
__global__ void conv2_kernel(const float* __restrict__ W2) {
    size_t i = ((size_t)blockIdx.x*256 + threadIdx.x)*8;
    float4 v0 = *(const float4*)(W2 + i);
    float4 v1 = *(const float4*)(W2 + i + 4);
    __half2 h[4];
    h[0] = __floats2half2_rn(v0.x, v0.y);
    h[1] = __floats2half2_rn(v0.z, v0.w);
    h[2] = __floats2half2_rn(v1.x, v1.y);
    h[3] = __floats2half2_rn(v1.z, v1.w);
    *(uint4*)(g_w2 + i) = *(uint4*)h;
}

// ============================================================================
// GEMM1 (mma.sync fp16): z1 = X@W1, z3 = X@W3 (trans-B); h = silu(z1+b1)*(z3+b3)
// CTA 128x128, BK=32, 4-stage cp.async (prefetch distance 3). 8 warps 2x4.
// ============================================================================
__global__ void __launch_bounds__(256) gemm1_kernel(const float* __restrict__ b1,
                                                    const float* __restrict__ b3) {
    int e = g_tile_expert[blockIdx.y];
    if (e < 0) return;
    int row0 = blockIdx.y * BM;
    int n0   = blockIdx.x * 128;

    extern __shared__ __align__(1024) char smem[];
    uint32_t sb = smem_u32(smem);

    int tid  = threadIdx.x;
    int lane = tid & 31;
    int wid  = tid >> 5;
    int wm   = wid >> 2;
    int wn   = wid & 3;

    const __half* sA  = g_xg + (size_t)row0*DD;
    const __half* sW1 = g_w1 + (size_t)e*DD*HH + n0;
    const __half* sW3 = g_w3 + (size_t)e*DD*HH + n0;

    #define G1_LOAD(stage, it) do { \
        uint32_t bs = sb + (uint32_t)(stage)*(TILEA + 2*TILEW); \
        int k0 = (it)*32; \
        _Pragma("unroll") \
        for (int hf = 0; hf < 2; hf++) { \
            int idx = hf*256 + tid; \
            int ar = idx >> 2, ac = idx & 3; \
            cpasync16(bs + (uint32_t)ar*STRA + ac*16, sA + (size_t)ar*DD + k0 + ac*8); \
            int wr = idx >> 4, wc = idx & 15; \
            size_t gw = (size_t)(k0 + wr)*HH + wc*8; \
            uint32_t sw = (uint32_t)wr*STRB + wc*16; \
            cpasync16(bs + TILEA + sw, sW1 + gw); \
            cpasync16(bs + TILEA + TILEW + sw, sW3 + gw); \
        } \
    } while (0)

    float acc1[4][4][4], acc3[4][4][4];
    #pragma unroll
    for (int i = 0; i < 4; i++)
        #pragma unroll
        for (int j = 0; j < 4; j++)
            #pragma unroll
            for (int q = 0; q < 4; q++) { acc1[i][j][q] = 0.f; acc3[i][j][q] = 0.f; }

    int lr = (lane & 7) + 8*((lane >> 3) & 1);
    int lk = (lane >> 4) * 16;
    int bg = lane >> 3, br = lane & 7;
    uint32_t laneB = (uint32_t)((bg & 1)*8 + br)*STRB + (uint32_t)(bg >> 1)*16;

    const int NIT = DD/32;   // 32
    G1_LOAD(0, 0); CP_COMMIT();
    G1_LOAD(1, 1); CP_COMMIT();
    G1_LOAD(2, 2); CP_COMMIT();

    for (int it = 0; it < NIT; it++) {
        if (it + 3 < NIT) G1_LOAD((it+3)&3, it+3);
        CP_COMMIT();
        CP_WAIT3();
        __syncthreads();

        uint32_t bs  = sb + (uint32_t)(it&3)*(TILEA + 2*TILEW);
        uint32_t aA  = bs + (uint32_t)(wm*64 + lr)*STRA + lk;
        uint32_t bW1 = bs + TILEA + laneB + (uint32_t)(wn*32)*2;
        uint32_t bW3 = bW1 + TILEW;

        #pragma unroll
        for (int h16 = 0; h16 < 2; h16++) {
            uint32_t koA = h16*32;
            uint32_t koB = (uint32_t)(h16*16)*STRB;
            uint32_t Ah[4][4];
            #pragma unroll
            for (int mt = 0; mt < 4; mt++)
                ldmx4(Ah[mt], aA + mt*(16*STRA) + koA);
            #pragma unroll
            for (int np = 0; np < 2; np++) {
                uint32_t bh[4];
                ldmx4t(bh, bW1 + koB + np*32);
                #pragma unroll
                for (int s = 0; s < 2; s++) {
                    int nt = np*2 + s;
                    #pragma unroll
                    for (int mt = 0; mt < 4; mt++)
                        mma16816(acc1[mt][nt], Ah[mt], bh[2*s], bh[2*s+1]);
                }
            }
            #pragma unroll
            for (int np = 0; np < 2; np++) {
                uint32_t bh[4];
                ldmx4t(bh, bW3 + koB + np*32);
                #pragma unroll
                for (int s = 0; s < 2; s++) {
                    int nt = np*2 + s;
                    #pragma unroll
                    for (int mt = 0; mt < 4; mt++)
                        mma16816(acc3[mt][nt], Ah[mt], bh[2*s], bh[2*s+1]);
                }
            }
        }
        __syncthreads();
    }

    int qrow = lane >> 2, qcol = lane & 3;
    #pragma unroll
    for (int nt = 0; nt < 4; nt++) {
        int col = n0 + wn*32 + nt*8 + qcol*2;
        float2 bb1 = *(const float2*)(b1 + e*HH + col);
        float2 bb3 = *(const float2*)(b3 + e*HH + col);
        #pragma unroll
        for (int mt = 0; mt < 4; mt++) {
            #pragma unroll
            for (int hrow = 0; hrow < 2; hrow++) {
                int r = row0 + wm*64 + mt*16 + qrow + hrow*8;
                float z1a = acc1[mt][nt][2*hrow]   + bb1.x;
                float z1b = acc1[mt][nt][2*hrow+1] + bb1.y;
                float z3a = acc3[mt][nt][2*hrow]   + bb3.x;
                float z3b = acc3[mt][nt][2*hrow+1] + bb3.y;
                float ha = (z1a / (1.f + __expf(-z1a))) * z3a;
                float hb = (z1b / (1.f + __expf(-z1b))) * z3b;
                *reinterpret_cast<__half2*>(g_h + (size_t)r*HH + col) =
                    __floats2half2_rn(ha, hb);
            }
        }
    }
}

// ============================================================================
// GEMM2 (mma.sync fp16): eo = (h @ W2 + b2) * route_w; 4-stage, 2 CTAs/SM.
// ============================================================================
__global__ void __launch_bounds__(256, 2) gemm2_kernel(const float* __restrict__ b2) {
    int e = g_tile_expert[blockIdx.y];
    if (e < 0) return;
    int row0 = blockIdx.y * BM;
    int n0   = blockIdx.x * 128;

    extern __shared__ __align__(1024) char smem[];
    uint32_t sb = smem_u32(smem);

    int tid  = threadIdx.x;
    int lane = tid & 31;
    int wid  = tid >> 5;
    int wm   = wid >> 2;
    int wn   = wid & 3;

    const __half* sA = g_h  + (size_t)row0*HH;
    const __half* sW = g_w2 + (size_t)e*HH*DD + n0;

    #define G2_LOAD(stage, it) do { \
        uint32_t bs = sb + (uint32_t)(stage)*(TILEA + TILEW); \
        int k0 = (it)*32; \
        _Pragma("unroll") \
        for (int hf = 0; hf < 2; hf++) { \
            int idx = hf*256 + tid; \
            int ar = idx >> 2, ac = idx & 3; \
            cpasync16(bs + (uint32_t)ar*STRA + ac*16, sA + (size_t)ar*HH + k0 + ac*8); \
            int wr = idx >> 4, wc = idx & 15; \
            cpasync16(bs + TILEA + (uint32_t)wr*STRB + wc*16, \
                      sW + (size_t)(k0 + wr)*DD + wc*8); \
        } \
    } while (0)

    float acc[4][4][4];
    #pragma unroll
    for (int i = 0; i < 4; i++)
        #pragma unroll
        for (int j = 0; j < 4; j++)
            #pragma unroll
            for (int q = 0; q < 4; q++) acc[i][j][q] = 0.f;

    int lr = (lane & 7) + 8*((lane >> 3) & 1);
    int lk = (lane >> 4) * 16;
    int bg = lane >> 3, br = lane & 7;
    uint32_t laneB = (uint32_t)((bg & 1)*8 + br)*STRB + (uint32_t)(bg >> 1)*16;

    const int NIT = HH/32;   // 64
    G2_LOAD(0, 0); CP_COMMIT();
    G2_LOAD(1, 1); CP_COMMIT();
    G2_LOAD(2, 2); CP_COMMIT();

    for (int it = 0; it < NIT; it++) {
        if (it + 3 < NIT) G2_LOAD((it+3)&3, it+3);
        CP_COMMIT();
        CP_WAIT3();
        __syncthreads();

        uint32_t bs = sb + (uint32_t)(it&3)*(TILEA + TILEW);
        uint32_t aA = bs + (uint32_t)(wm*64 + lr)*STRA + lk;
        uint32_t bW = bs + TILEA + laneB + (uint32_t)(wn*32)*2;

        #pragma unroll
        for (int h16 = 0; h16 < 2; h16++) {
            uint32_t koA = h16*32;
            uint32_t koB = (uint32_t)(h16*16)*STRB;
            uint32_t Ah[4][4];
            #pragma unroll
            for (int mt = 0; mt < 4; mt++)
                ldmx4(Ah[mt], aA + mt*(16*STRA) + koA);
            #pragma unroll
            for (int np = 0; np < 2; np++) {
                uint32_t bh[4];
                ldmx4t(bh, bW + koB + np*32);
                #pragma unroll
                for (int s = 0; s < 2; s++) {
                    int nt = np*2 + s;
                    #pragma unroll
                    for (int mt = 0; mt < 4; mt++)
                        mma16816(acc[mt][nt], Ah[mt], bh[2*s], bh[2*s+1]);
                }
            }
        }
        __syncthreads();
    }

    int qrow = lane >> 2, qcol = lane & 3;
    #pragma unroll
    for (int mt = 0; mt < 4; mt++) {
        #pragma unroll
        for (int hrow = 0; hrow < 2; hrow++) {
            int r = row0 + wm*64 + mt*16 + qrow + hrow*8;
            float wv = g_pair_w[r];
            #pragma unroll
            for (int nt = 0; nt < 4; nt++) {
                int col = n0 + wn*32 + nt*8 + qcol*2;
                float2 bb = *(const float2*)(b2 + e*DD + col);
                float2 o;
                o.x = (acc[mt][nt][2*hrow]   + bb.x) * wv;
                o.y = (acc[mt][nt][2*hrow+1] + bb.y) * wv;
                *(float2*)(g_eo + (size_t)r*DD + col) = o;
            }
        }
    }
}

// ---------------- combine ----------------
__global__ void combine_kernel(float* __restrict__ out) {
    int idx = blockIdx.x*blockDim.x + threadIdx.x;
    int n = idx >> 8;
    int q = idx & 255;
    if (n >= NTOK) return;
    int p0 = g_pair_slot[2*n];
    int p1 = g_pair_slot[2*n+1];
    const float4* eo = (const float4*)g_eo;
    float4 a = eo[(size_t)p0*256 + q];
    float4 b = eo[(size_t)p1*256 + q];
    ((float4*)out)[idx] = make_float4(a.x+b.x, a.y+b.y, a.z+b.z, a.w+b.w);
}

// ---------------- aux loss (1024 threads, fixed-order reduction) -------------
__global__ void __launch_bounds__(1024) aux_kernel(float* __restrict__ out, int has_aux) {
    __shared__ float red[1024];
    int tid = threadIdx.x;
    int e = tid & 7;
    float p = 0.f;
    for (int n = tid >> 3; n < NTOK; n += 128) p += g_scores[(size_t)n*EE + e];
    red[tid] = p;
    __syncthreads();
    for (int s = 512; s >= 8; s >>= 1) {
        if (tid < s) red[tid] += red[tid + s];
        __syncthreads();
    }
    if (tid == 0 && has_aux) {
        float aux = 0.f;
        for (int ee = 0; ee < EE; ee++) {
            float f = (float)g_counts[ee] / (float)(NTOK*KTOP);
            float P = red[ee] / (float)NTOK;
            aux += f*P;
        }
        out[(size_t)NTOK*DD] = 0.01f * (float)EE * aux;
    }
}

// ---------------- launch (fork-join: conversions overlap routing) ------------
extern "C" void kernel_launch(void* const* d_in, const int* in_sizes, int n_in,
                              void* d_out, int out_size) {
    const float* x  = (const float*)d_in[0];
    const float* Wg = (const float*)d_in[1];
    const float* W1 = (const float*)d_in[2];
    const float* b1 = (const float*)d_in[3];
    const float* W2 = (const float*)d_in[4];
    const float* b2 = (const float*)d_in[5];
    const float* W3 = (const float*)d_in[6];
    const float* b3 = (const float*)d_in[7];
    float* out = (float*)d_out;

    const int G1_SMEM = 4*(TILEA + 2*TILEW);   // 110592
    const int G2_SMEM = 4*(TILEA + TILEW);     // 75776
    cudaFuncSetAttribute(gemm1_kernel, cudaFuncAttributeMaxDynamicSharedMemorySize, G1_SMEM);
    cudaFuncSetAttribute(gemm2_kernel, cudaFuncAttributeMaxDynamicSharedMemorySize, G2_SMEM);

    cudaStream_t s2 = 0;
    cudaEvent_t evFork = 0, evW13 = 0, evW2 = 0;
    bool forked = (cudaStreamCreateWithFlags(&s2, cudaStreamNonBlocking) == cudaSuccess)
               && (cudaEventCreateWithFlags(&evFork, cudaEventDisableTiming) == cudaSuccess)
               && (cudaEventCreateWithFlags(&evW13,  cudaEventDisableTiming) == cudaSuccess)
               && (cudaEventCreateWithFlags(&evW2,   cudaEventDisableTiming) == cudaSuccess);

    if (forked) {
        cudaEventRecord(evFork, 0);
        cudaStreamWaitEvent(s2, evFork, 0);
        conv13_kernel<<<dim3((EE*DD*HH)/(256*8), 1, 2), 256, 0, s2>>>(W1, W3);
        cudaEventRecord(evW13, s2);
        conv2_kernel<<<dim3((EE*DD*HH)/(256*8), 1, 1), 256, 0, s2>>>(W2);
        cudaEventRecord(evW2, s2);
    } else {
        conv13_kernel<<<dim3((EE*DD*HH)/(256*8), 1, 2), 256>>>(W1, W3);
        conv2_kernel<<<dim3((EE*DD*HH)/(256*8), 1, 1), 256>>>(W2);
    }

    init_kernel<<<1, 32>>>();
    gate_kernel<<<NTOK/8, 256>>>(x, Wg);
    setup_kernel<<<1, 256>>>();
    assign_gather_kernel<<<NTOK/8, 256>>>(x);

    if (forked) cudaStreamWaitEvent(0, evW13, 0);
    gemm1_kernel<<<dim3(HH/128, MAXTILES), 256, G1_SMEM>>>(b1, b3);
    if (forked) cudaStreamWaitEvent(0, evW2, 0);
    gemm2_kernel<<<dim3(DD/128, MAXTILES), 256, G2_SMEM>>>(b2);
    combine_kernel<<<(NTOK*(DD/4))/256, 256>>>(out);
    aux_kernel<<<1, 1024>>>(out, out_size > NTOK*DD ? 1 : 0);
}

// round 9
// speedup vs baseline: 5.2829x; 1.0033x over previous
#include <cuda_runtime.h>
#include <cuda_bf16.h>
#include <cuda_fp16.h>
#include <math.h>
#include <stdint.h>

#define DD     1024
#define HH     2048
#define EE     8
#define NTOK   8192
#define KTOP   2
#define NP     (NTOK*KTOP)      // 16384
#define BM     128
#define MAXPAD (NP + EE*BM)     // 17408
#define MAXTILES (MAXPAD/BM)    // 136

#define STRA   80               // A smem row stride (32 fp16 = 64B + 16B pad)
#define TILEA  (128*STRA)       // 10240
#define STRB   272              // B smem row stride (128 fp16 = 256B + 16B pad)
#define TILEW  (32*STRB)        // 8704

// ---------------- device scratch ----------------
__device__ float g_pair_w[MAXPAD];
__device__ int   g_slot_tok[MAXPAD];   // slot -> token (-1 = pad)
__device__ int   g_topk_idx[NP];
__device__ float g_topk_val[NP];
__device__ float g_scores[NTOK*EE];
__device__ int   g_counts[EE];
__device__ int   g_cursor[EE];
__device__ int   g_pstart[EE+1];
__device__ int   g_tile_expert[MAXTILES];

__device__ __align__(16) __half g_xg [(size_t)MAXPAD*DD];      // fp16 x (gathered)
__device__ __align__(16) __half g_w1 [(size_t)EE*DD*HH];       // fp16 W1 [E][D][H]
__device__ __align__(16) __half g_w3 [(size_t)EE*DD*HH];
__device__ __align__(16) __half g_w2 [(size_t)EE*HH*DD];       // fp16 W2 [E][H][D]
__device__ __align__(16) __half g_h  [(size_t)MAXPAD*HH];      // fp16 h

// ---------------- PTX helpers (baseline PTX only) ----------------
__device__ __forceinline__ uint32_t smem_u32(const void* p){
    uint32_t a;
    asm("{ .reg .u64 t; cvta.to.shared.u64 t, %1; cvt.u32.u64 %0, t; }" : "=r"(a) : "l"(p));
    return a;
}
__device__ __forceinline__ void cpasync16(uint32_t dst, const void* src){
    asm volatile("cp.async.cg.shared.global [%0], [%1], 16;" :: "r"(dst), "l"(src));
}
#define CP_COMMIT() asm volatile("cp.async.commit_group;" ::: "memory")
#define CP_WAIT3()  asm volatile("cp.async.wait_group 3;" ::: "memory")

__device__ __forceinline__ void ldmx4(uint32_t (&r)[4], uint32_t addr){
    asm volatile("ldmatrix.sync.aligned.m8n8.x4.shared.b16 {%0,%1,%2,%3}, [%4];"
        : "=r"(r[0]), "=r"(r[1]), "=r"(r[2]), "=r"(r[3]) : "r"(addr));
}
__device__ __forceinline__ void ldmx4t(uint32_t (&r)[4], uint32_t addr){
    asm volatile("ldmatrix.sync.aligned.m8n8.x4.trans.shared.b16 {%0,%1,%2,%3}, [%4];"
        : "=r"(r[0]), "=r"(r[1]), "=r"(r[2]), "=r"(r[3]) : "r"(addr));
}
__device__ __forceinline__ void mma16816(float (&c)[4], const uint32_t (&a)[4],
                                         uint32_t b0, uint32_t b1){
    asm volatile(
        "mma.sync.aligned.m16n8k16.row.col.f32.f16.f16.f32 "
        "{%0,%1,%2,%3}, {%4,%5,%6,%7}, {%8,%9}, {%0,%1,%2,%3};"
        : "+f"(c[0]), "+f"(c[1]), "+f"(c[2]), "+f"(c[3])
        : "r"(a[0]), "r"(a[1]), "r"(a[2]), "r"(a[3]), "r"(b0), "r"(b1));
}
__device__ __forceinline__ void redadd2(float* p, float a, float b){
    asm volatile("red.global.add.v2.f32 [%0], {%1, %2};"
        :: "l"(p), "f"(a), "f"(b) : "memory");
}

// ---------------- init: counters + slot_tok pads ----------------
__global__ void init_kernel() {
    int i = blockIdx.x*blockDim.x + threadIdx.x;
    if (i < MAXPAD) g_slot_tok[i] = -1;
    if (i < EE) { g_counts[i] = 0; g_cursor[i] = 0; }
}

// ---------------- zero the output (side stream) ----------------
__global__ void zeroout_kernel(float* __restrict__ out, int n4, int ntail) {
    int i = blockIdx.x*blockDim.x + threadIdx.x;
    if (i < n4) ((float4*)out)[i] = make_float4(0.f,0.f,0.f,0.f);
    if (i < ntail) out[(size_t)n4*4 + i] = 0.f;
}

// ---------------- gating: 4 tokens per warp, Wg staged once per block --------
__global__ void __launch_bounds__(256) gate_kernel(const float* __restrict__ x,
                                                   const float* __restrict__ Wg) {
    __shared__ float sWg[EE*DD];
    for (int i = threadIdx.x; i < EE*DD/4; i += 256)
        ((float4*)sWg)[i] = ((const float4*)Wg)[i];
    __syncthreads();

    int warp = threadIdx.x >> 5;
    int lane = threadIdx.x & 31;

    for (int t = 0; t < 4; t++) {
        int n = blockIdx.x*32 + warp*4 + t;

        const float4* xr = (const float4*)(x + (size_t)n*DD);
        float4 xv[8];
        #pragma unroll
        for (int q = 0; q < 8; q++) xv[q] = xr[lane + q*32];

        float pr[EE];
        #pragma unroll
        for (int e = 0; e < EE; e++) {
            const float4* wr = (const float4*)(sWg + e*DD);
            float p = 0.f;
            #pragma unroll
            for (int q = 0; q < 8; q++) {
                float4 w = wr[lane + q*32];
                p += xv[q].x*w.x + xv[q].y*w.y + xv[q].z*w.z + xv[q].w*w.w;
            }
            #pragma unroll
            for (int off = 16; off; off >>= 1) p += __shfl_xor_sync(0xffffffffu, p, off);
            pr[e] = p;
        }
        float m = pr[0];
        #pragma unroll
        for (int e = 1; e < EE; e++) m = fmaxf(m, pr[e]);
        float s = 0.f;
        #pragma unroll
        for (int e = 0; e < EE; e++) { pr[e] = __expf(pr[e]-m); s += pr[e]; }
        float inv = 1.f/s;
        #pragma unroll
        for (int e = 0; e < EE; e++) pr[e] *= inv;

        int i1 = 0; float v1 = pr[0];
        #pragma unroll
        for (int e = 1; e < EE; e++) if (pr[e] > v1) { v1 = pr[e]; i1 = e; }
        int i2 = -1; float v2 = -1.f;
        #pragma unroll
        for (int e = 0; e < EE; e++) if (e != i1 && pr[e] > v2) { v2 = pr[e]; i2 = e; }

        if (lane == 0) {
            #pragma unroll
            for (int e = 0; e < EE; e++) g_scores[(size_t)n*EE + e] = pr[e];
            g_topk_idx[2*n]   = i1; g_topk_val[2*n]   = v1;
            g_topk_idx[2*n+1] = i2; g_topk_val[2*n+1] = v2;
            atomicAdd(&g_counts[i1], 1);
            atomicAdd(&g_counts[i2], 1);
        }
    }
}

// ---------------- setup (parallel, 1 block) ----------------
__global__ void setup_kernel() {
    __shared__ int ps[EE+1], cnt[EE];
    int tid = threadIdx.x;
    if (tid == 0) {
        int off = 0;
        for (int e = 0; e < EE; e++) {
            ps[e] = off;
            int c = g_counts[e];
            cnt[e] = c;
            off = (off + c + BM - 1)/BM*BM;
        }
        ps[EE] = off;
    }
    __syncthreads();
    if (tid <= EE) g_pstart[tid] = ps[tid];
    if (tid < MAXTILES) {
        int r0 = tid*BM, e = -1;
        #pragma unroll
        for (int ee = 0; ee < EE; ee++)
            if (r0 >= ps[ee] && r0 < ps[ee] + cnt[ee]) e = ee;
        g_tile_expert[tid] = e;
    }
}

// ---------------- fused assign + gather (one warp per TOKEN) ----------------
__global__ void __launch_bounds__(256) assign_gather_kernel(const float* __restrict__ x) {
    int warp = threadIdx.x >> 5;
    int lane = threadIdx.x & 31;
    int n = blockIdx.x*8 + warp;
    if (n >= NTOK) return;

    int slot = 0;
    if (lane < 2) {
        int p = 2*n + lane;
        int e = g_topk_idx[p];
        int pos = atomicAdd(&g_cursor[e], 1);
        slot = g_pstart[e] + pos;
        g_pair_w[slot]   = g_topk_val[p];
        g_slot_tok[slot] = n;
    }
    int slot0 = __shfl_sync(0xffffffffu, slot, 0);
    int slot1 = __shfl_sync(0xffffffffu, slot, 1);

    const float4* xr = (const float4*)(x + (size_t)n*DD);
    __half2* d0 = (__half2*)(g_xg + (size_t)slot0*DD);
    __half2* d1 = (__half2*)(g_xg + (size_t)slot1*DD);
    #pragma unroll
    for (int q = 0; q < 8; q++) {
        float4 v = xr[lane + q*32];
        __half2 a = __floats2half2_rn(v.x, v.y);
        __half2 b = __floats2half2_rn(v.z, v.w);
        d0[2*(lane + q*32)]     = a;
        d0[2*(lane + q*32) + 1] = b;
        d1[2*(lane + q*32)]     = a;
        d1[2*(lane + q*32) + 1] = b;
    }
}

// ---------------- flat fp32->fp16 conversions (side stream) ----------------
__global__ void conv13_kernel(const float* __restrict__ W1, const float* __restrict__ W3) {
    const float* src = blockIdx.z ? W3 : W1;
    __half* dst = blockIdx.z ? g_w3 : g_w1;
    size_t i = ((size_t)blockIdx.x*256 + threadIdx.x)*8;
    float4 v0 = *(const float4*)(src + i);
    float4 v1 = *(const float4*)(src + i + 4);
    __half2 h[4];
    h[0] = __floats2half2_rn(v0.x, v0.y);
    h[1] = __floats2half2_rn(v0.z, v0.w);
    h[2] = __floats2half2_rn(v1.x, v1.y);
    h[3] = __floats2half2_rn(v1.z, v1.w);
    *(uint4*)(dst + i) = *(uint4*)h;
}
__global__ void conv2_kernel(const float* __restrict__ W2) {
    size_t i = ((size_t)blockIdx.x*256 + threadIdx.x)*8;
    float4 v0 = *(const float4*)(W2 + i);
    float4 v1 = *(const float4*)(W2 + i + 4);
    __half2 h[4];
    h[0] = __floats2half2_rn(v0.x, v0.y);
    h[1] = __floats2half2_rn(v0.z, v0.w);
    h[2] = __floats2half2_rn(v1.x, v1.y);
    h[3] = __floats2half2_rn(v1.z, v1.w);
    *(uint4*)(g_w2 + i) = *(uint4*)h;
}

// ============================================================================
// GEMM1 (mma.sync fp16): z1 = X@W1, z3 = X@W3 (trans-B); h = silu(z1+b1)*(z3+b3)
// CTA 128x128, BK=32, 4-stage cp.async. 8 warps 2x4.
// ============================================================================
__global__ void __launch_bounds__(256) gemm1_kernel(const float* __restrict__ b1,
                                                    const float* __restrict__ b3) {
    int e = g_tile_expert[blockIdx.y];
    if (e < 0) return;
    int row0 = blockIdx.y * BM;
    int n0   = blockIdx.x * 128;

    extern __shared__ __align__(1024) char smem[];
    uint32_t sb = smem_u32(smem);

    int tid  = threadIdx.x;
    int lane = tid & 31;
    int wid  = tid >> 5;
    int wm   = wid >> 2;
    int wn   = wid & 3;

    const __half* sA  = g_xg + (size_t)row0*DD;
    const __half* sW1 = g_w1 + (size_t)e*DD*HH + n0;
    const __half* sW3 = g_w3 + (size_t)e*DD*HH + n0;

    #define G1_LOAD(stage, it) do { \
        uint32_t bs = sb + (uint32_t)(stage)*(TILEA + 2*TILEW); \
        int k0 = (it)*32; \
        _Pragma("unroll") \
        for (int hf = 0; hf < 2; hf++) { \
            int idx = hf*256 + tid; \
            int ar = idx >> 2, ac = idx & 3; \
            cpasync16(bs + (uint32_t)ar*STRA + ac*16, sA + (size_t)ar*DD + k0 + ac*8); \
            int wr = idx >> 4, wc = idx & 15; \
            size_t gw = (size_t)(k0 + wr)*HH + wc*8; \
            uint32_t sw = (uint32_t)wr*STRB + wc*16; \
            cpasync16(bs + TILEA + sw, sW1 + gw); \
            cpasync16(bs + TILEA + TILEW + sw, sW3 + gw); \
        } \
    } while (0)

    float acc1[4][4][4], acc3[4][4][4];
    #pragma unroll
    for (int i = 0; i < 4; i++)
        #pragma unroll
        for (int j = 0; j < 4; j++)
            #pragma unroll
            for (int q = 0; q < 4; q++) { acc1[i][j][q] = 0.f; acc3[i][j][q] = 0.f; }

    int lr = (lane & 7) + 8*((lane >> 3) & 1);
    int lk = (lane >> 4) * 16;
    int bg = lane >> 3, br = lane & 7;
    uint32_t laneB = (uint32_t)((bg & 1)*8 + br)*STRB + (uint32_t)(bg >> 1)*16;

    const int NIT = DD/32;   // 32
    G1_LOAD(0, 0); CP_COMMIT();
    G1_LOAD(1, 1); CP_COMMIT();
    G1_LOAD(2, 2); CP_COMMIT();

    for (int it = 0; it < NIT; it++) {
        if (it + 3 < NIT) G1_LOAD((it+3)&3, it+3);
        CP_COMMIT();
        CP_WAIT3();
        __syncthreads();

        uint32_t bs  = sb + (uint32_t)(it&3)*(TILEA + 2*TILEW);
        uint32_t aA  = bs + (uint32_t)(wm*64 + lr)*STRA + lk;
        uint32_t bW1 = bs + TILEA + laneB + (uint32_t)(wn*32)*2;
        uint32_t bW3 = bW1 + TILEW;

        #pragma unroll
        for (int h16 = 0; h16 < 2; h16++) {
            uint32_t koA = h16*32;
            uint32_t koB = (uint32_t)(h16*16)*STRB;
            uint32_t Ah[4][4];
            #pragma unroll
            for (int mt = 0; mt < 4; mt++)
                ldmx4(Ah[mt], aA + mt*(16*STRA) + koA);
            #pragma unroll
            for (int np = 0; np < 2; np++) {
                uint32_t bh[4];
                ldmx4t(bh, bW1 + koB + np*32);
                #pragma unroll
                for (int s = 0; s < 2; s++) {
                    int nt = np*2 + s;
                    #pragma unroll
                    for (int mt = 0; mt < 4; mt++)
                        mma16816(acc1[mt][nt], Ah[mt], bh[2*s], bh[2*s+1]);
                }
            }
            #pragma unroll
            for (int np = 0; np < 2; np++) {
                uint32_t bh[4];
                ldmx4t(bh, bW3 + koB + np*32);
                #pragma unroll
                for (int s = 0; s < 2; s++) {
                    int nt = np*2 + s;
                    #pragma unroll
                    for (int mt = 0; mt < 4; mt++)
                        mma16816(acc3[mt][nt], Ah[mt], bh[2*s], bh[2*s+1]);
                }
            }
        }
        __syncthreads();
    }

    int qrow = lane >> 2, qcol = lane & 3;
    #pragma unroll
    for (int nt = 0; nt < 4; nt++) {
        int col = n0 + wn*32 + nt*8 + qcol*2;
        float2 bb1 = *(const float2*)(b1 + e*HH + col);
        float2 bb3 = *(const float2*)(b3 + e*HH + col);
        #pragma unroll
        for (int mt = 0; mt < 4; mt++) {
            #pragma unroll
            for (int hrow = 0; hrow < 2; hrow++) {
                int r = row0 + wm*64 + mt*16 + qrow + hrow*8;
                float z1a = acc1[mt][nt][2*hrow]   + bb1.x;
                float z1b = acc1[mt][nt][2*hrow+1] + bb1.y;
                float z3a = acc3[mt][nt][2*hrow]   + bb3.x;
                float z3b = acc3[mt][nt][2*hrow+1] + bb3.y;
                float ha = (z1a / (1.f + __expf(-z1a))) * z3a;
                float hb = (z1b / (1.f + __expf(-z1b))) * z3b;
                *reinterpret_cast<__half2*>(g_h + (size_t)r*HH + col) =
                    __floats2half2_rn(ha, hb);
            }
        }
    }
}

// ============================================================================
// GEMM2 (mma.sync fp16): out[tok] += (h @ W2 + b2) * route_w  via red.add.v2
// 4-stage, 2 CTAs/SM. Pad rows (slot_tok<0) skipped.
// ============================================================================
__global__ void __launch_bounds__(256, 2) gemm2_kernel(const float* __restrict__ b2,
                                                       float* __restrict__ out) {
    int e = g_tile_expert[blockIdx.y];
    if (e < 0) return;
    int row0 = blockIdx.y * BM;
    int n0   = blockIdx.x * 128;

    extern __shared__ __align__(1024) char smem[];
    uint32_t sb = smem_u32(smem);

    int tid  = threadIdx.x;
    int lane = tid & 31;
    int wid  = tid >> 5;
    int wm   = wid >> 2;
    int wn   = wid & 3;

    const __half* sA = g_h  + (size_t)row0*HH;
    const __half* sW = g_w2 + (size_t)e*HH*DD + n0;

    #define G2_LOAD(stage, it) do { \
        uint32_t bs = sb + (uint32_t)(stage)*(TILEA + TILEW); \
        int k0 = (it)*32; \
        _Pragma("unroll") \
        for (int hf = 0; hf < 2; hf++) { \
            int idx = hf*256 + tid; \
            int ar = idx >> 2, ac = idx & 3; \
            cpasync16(bs + (uint32_t)ar*STRA + ac*16, sA + (size_t)ar*HH + k0 + ac*8); \
            int wr = idx >> 4, wc = idx & 15; \
            cpasync16(bs + TILEA + (uint32_t)wr*STRB + wc*16, \
                      sW + (size_t)(k0 + wr)*DD + wc*8); \
        } \
    } while (0)

    float acc[4][4][4];
    #pragma unroll
    for (int i = 0; i < 4; i++)
        #pragma unroll
        for (int j = 0; j < 4; j++)
            #pragma unroll
            for (int q = 0; q < 4; q++) acc[i][j][q] = 0.f;

    int lr = (lane & 7) + 8*((lane >> 3) & 1);
    int lk = (lane >> 4) * 16;
    int bg = lane >> 3, br = lane & 7;
    uint32_t laneB = (uint32_t)((bg & 1)*8 + br)*STRB + (uint32_t)(bg >> 1)*16;

    const int NIT = HH/32;   // 64
    G2_LOAD(0, 0); CP_COMMIT();
    G2_LOAD(1, 1); CP_COMMIT();
    G2_LOAD(2, 2); CP_COMMIT();

    for (int it = 0; it < NIT; it++) {
        if (it + 3 < NIT) G2_LOAD((it+3)&3, it+3);
        CP_COMMIT();
        CP_WAIT3();
        __syncthreads();

        uint32_t bs = sb + (uint32_t)(it&3)*(TILEA + TILEW);
        uint32_t aA = bs + (uint32_t)(wm*64 + lr)*STRA + lk;
        uint32_t bW = bs + TILEA + laneB + (uint32_t)(wn*32)*2;

        #pragma unroll
        for (int h16 = 0; h16 < 2; h16++) {
            uint32_t koA = h16*32;
            uint32_t koB = (uint32_t)(h16*16)*STRB;
            uint32_t Ah[4][4];
            #pragma unroll
            for (int mt = 0; mt < 4; mt++)
                ldmx4(Ah[mt], aA + mt*(16*STRA) + koA);
            #pragma unroll
            for (int np = 0; np < 2; np++) {
                uint32_t bh[4];
                ldmx4t(bh, bW + koB + np*32);
                #pragma unroll
                for (int s = 0; s < 2; s++) {
                    int nt = np*2 + s;
                    #pragma unroll
                    for (int mt = 0; mt < 4; mt++)
                        mma16816(acc[mt][nt], Ah[mt], bh[2*s], bh[2*s+1]);
                }
            }
        }
        __syncthreads();
    }

    // epilogue: atomically accumulate (acc + b2) * w into out[tok]
    int qrow = lane >> 2, qcol = lane & 3;
    #pragma unroll
    for (int mt = 0; mt < 4; mt++) {
        #pragma unroll
        for (int hrow = 0; hrow < 2; hrow++) {
            int r = row0 + wm*64 + mt*16 + qrow + hrow*8;
            int tok = g_slot_tok[r];
            if (tok < 0) continue;
            float wv = g_pair_w[r];
            float* orow = out + (size_t)tok*DD;
            #pragma unroll
            for (int nt = 0; nt < 4; nt++) {
                int col = n0 + wn*32 + nt*8 + qcol*2;
                float2 bb = *(const float2*)(b2 + e*DD + col);
                redadd2(orow + col,
                        (acc[mt][nt][2*hrow]   + bb.x) * wv,
                        (acc[mt][nt][2*hrow+1] + bb.y) * wv);
            }
        }
    }
}

// ---------------- aux loss (1024 threads, fixed-order reduction) -------------
__global__ void __launch_bounds__(1024) aux_kernel(float* __restrict__ out, int has_aux) {
    __shared__ float red[1024];
    int tid = threadIdx.x;
    int e = tid & 7;
    float p = 0.f;
    for (int n = tid >> 3; n < NTOK; n += 128) p += g_scores[(size_t)n*EE + e];
    red[tid] = p;
    __syncthreads();
    for (int s = 512; s >= 8; s >>= 1) {
        if (tid < s) red[tid] += red[tid + s];
        __syncthreads();
    }
    if (tid == 0 && has_aux) {
        float aux = 0.f;
        for (int ee = 0; ee < EE; ee++) {
            float f = (float)g_counts[ee] / (float)(NTOK*KTOP);
            float P = red[ee] / (float)NTOK;
            aux += f*P;
        }
        out[(size_t)NTOK*DD] = 0.01f * (float)EE * aux;
    }
}

// ---------------- launch (fork-join: conversions + zeroout overlap) ----------
extern "C" void kernel_launch(void* const* d_in, const int* in_sizes, int n_in,
                              void* d_out, int out_size) {
    const float* x  = (const float*)d_in[0];
    const float* Wg = (const float*)d_in[1];
    const float* W1 = (const float*)d_in[2];
    const float* b1 = (const float*)d_in[3];
    const float* W2 = (const float*)d_in[4];
    const float* b2 = (const float*)d_in[5];
    const float* W3 = (const float*)d_in[6];
    const float* b3 = (const float*)d_in[7];
    float* out = (float*)d_out;

    const int G1_SMEM = 4*(TILEA + 2*TILEW);   // 110592
    const int G2_SMEM = 4*(TILEA + TILEW);     // 75776
    cudaFuncSetAttribute(gemm1_kernel, cudaFuncAttributeMaxDynamicSharedMemorySize, G1_SMEM);
    cudaFuncSetAttribute(gemm2_kernel, cudaFuncAttributeMaxDynamicSharedMemorySize, G2_SMEM);

    int n4 = out_size/4;
    int ntail = out_size - n4*4;
    int zgrid = (n4 + 255)/256;

    cudaStream_t s2 = 0;
    cudaEvent_t evFork = 0, evW13 = 0, evW2 = 0;
    bool forked = (cudaStreamCreateWithFlags(&s2, cudaStreamNonBlocking) == cudaSuccess)
               && (cudaEventCreateWithFlags(&evFork, cudaEventDisableTiming) == cudaSuccess)
               && (cudaEventCreateWithFlags(&evW13,  cudaEventDisableTiming) == cudaSuccess)
               && (cudaEventCreateWithFlags(&evW2,   cudaEventDisableTiming) == cudaSuccess);

    if (forked) {
        cudaEventRecord(evFork, 0);
        cudaStreamWaitEvent(s2, evFork, 0);
        conv13_kernel<<<dim3((EE*DD*HH)/(256*8), 1, 2), 256, 0, s2>>>(W1, W3);
        cudaEventRecord(evW13, s2);
        zeroout_kernel<<<zgrid, 256, 0, s2>>>(out, n4, ntail);
        conv2_kernel<<<dim3((EE*DD*HH)/(256*8), 1, 1), 256, 0, s2>>>(W2);
        cudaEventRecord(evW2, s2);
    } else {
        conv13_kernel<<<dim3((EE*DD*HH)/(256*8), 1, 2), 256>>>(W1, W3);
        zeroout_kernel<<<zgrid, 256>>>(out, n4, ntail);
        conv2_kernel<<<dim3((EE*DD*HH)/(256*8), 1, 1), 256>>>(W2);
    }

    init_kernel<<<(MAXPAD + 255)/256, 256>>>();
    gate_kernel<<<NTOK/32, 256>>>(x, Wg);
    setup_kernel<<<1, 256>>>();
    assign_gather_kernel<<<NTOK/8, 256>>>(x);

    if (forked) cudaStreamWaitEvent(0, evW13, 0);
    gemm1_kernel<<<dim3(HH/128, MAXTILES), 256, G1_SMEM>>>(b1, b3);
    if (forked) cudaStreamWaitEvent(0, evW2, 0);
    gemm2_kernel<<<dim3(DD/128, MAXTILES), 256, G2_SMEM>>>(b2, out);
    aux_kernel<<<1, 1024>>>(out, out_size > NTOK*DD ? 1 : 0);
}

// round 10
// speedup vs baseline: 5.4534x; 1.0323x over previous
#include <cuda_runtime.h>
#include <cuda_bf16.h>
#include <cuda_fp16.h>
#include <math.h>
#include <stdint.h>

#define DD     1024
#define HH     2048
#define EE     8
#define NTOK   8192
#define KTOP   2
#define NP     (NTOK*KTOP)      // 16384
#define BM     128
#define MAXPAD (NP + EE*BM)     // 17408
#define MAXTILES (MAXPAD/BM)    // 136

#define STRA   80               // A smem row stride (32 fp16 = 64B + 16B pad)
#define TILEA  (128*STRA)       // 10240
#define STRB   272              // B smem row stride (128 fp16 = 256B + 16B pad)
#define TILEW  (32*STRB)        // 8704

// ---------------- device scratch ----------------
__device__ float g_pair_w[MAXPAD];
__device__ int   g_slot_tok[MAXPAD];   // slot -> token (-1 = pad)
__device__ int   g_topk_idx[NP];
__device__ float g_topk_val[NP];
__device__ float g_scores[NTOK*EE];
__device__ int   g_counts[EE];
__device__ int   g_cursor[EE];
__device__ int   g_pstart[EE+1];
__device__ int   g_tile_expert[MAXTILES];

__device__ __align__(16) __half g_xg [(size_t)MAXPAD*DD];      // fp16 x (gathered)
__device__ __align__(16) __half g_w1 [(size_t)EE*DD*HH];       // fp16 W1 [E][D][H]
__device__ __align__(16) __half g_w3 [(size_t)EE*DD*HH];
__device__ __align__(16) __half g_w2 [(size_t)EE*HH*DD];       // fp16 W2 [E][H][D]
__device__ __align__(16) __half g_h  [(size_t)MAXPAD*HH];      // fp16 h

// ---------------- PTX helpers (baseline PTX only) ----------------
__device__ __forceinline__ uint32_t smem_u32(const void* p){
    uint32_t a;
    asm("{ .reg .u64 t; cvta.to.shared.u64 t, %1; cvt.u32.u64 %0, t; }" : "=r"(a) : "l"(p));
    return a;
}
__device__ __forceinline__ void cpasync16(uint32_t dst, const void* src){
    asm volatile("cp.async.cg.shared.global [%0], [%1], 16;" :: "r"(dst), "l"(src));
}
#define CP_COMMIT() asm volatile("cp.async.commit_group;" ::: "memory")
#define CP_WAIT2()  asm volatile("cp.async.wait_group 2;" ::: "memory")

__device__ __forceinline__ void ldmx4(uint32_t (&r)[4], uint32_t addr){
    asm volatile("ldmatrix.sync.aligned.m8n8.x4.shared.b16 {%0,%1,%2,%3}, [%4];"
        : "=r"(r[0]), "=r"(r[1]), "=r"(r[2]), "=r"(r[3]) : "r"(addr));
}
__device__ __forceinline__ void ldmx4t(uint32_t (&r)[4], uint32_t addr){
    asm volatile("ldmatrix.sync.aligned.m8n8.x4.trans.shared.b16 {%0,%1,%2,%3}, [%4];"
        : "=r"(r[0]), "=r"(r[1]), "=r"(r[2]), "=r"(r[3]) : "r"(addr));
}
__device__ __forceinline__ void mma16816(float (&c)[4], const uint32_t (&a)[4],
                                         uint32_t b0, uint32_t b1){
    asm volatile(
        "mma.sync.aligned.m16n8k16.row.col.f32.f16.f16.f32 "
        "{%0,%1,%2,%3}, {%4,%5,%6,%7}, {%8,%9}, {%0,%1,%2,%3};"
        : "+f"(c[0]), "+f"(c[1]), "+f"(c[2]), "+f"(c[3])
        : "r"(a[0]), "r"(a[1]), "r"(a[2]), "r"(a[3]), "r"(b0), "r"(b1));
}
__device__ __forceinline__ void redadd2(float* p, float a, float b){
    asm volatile("red.global.add.v2.f32 [%0], {%1, %2};"
        :: "l"(p), "f"(a), "f"(b) : "memory");
}

// ---------------- init: counters + slot_tok pads ----------------
__global__ void init_kernel() {
    int i = blockIdx.x*blockDim.x + threadIdx.x;
    if (i < MAXPAD) g_slot_tok[i] = -1;
    if (i < EE) { g_counts[i] = 0; g_cursor[i] = 0; }
}

// ---------------- zero the output (side stream) ----------------
__global__ void zeroout_kernel(float* __restrict__ out, int n4, int ntail) {
    int i = blockIdx.x*blockDim.x + threadIdx.x;
    if (i < n4) ((float4*)out)[i] = make_float4(0.f,0.f,0.f,0.f);
    if (i < ntail) out[(size_t)n4*4 + i] = 0.f;
}

// ---------------- gating: 4 tokens per warp, Wg staged once per block --------
__global__ void __launch_bounds__(256) gate_kernel(const float* __restrict__ x,
                                                   const float* __restrict__ Wg) {
    __shared__ float sWg[EE*DD];
    for (int i = threadIdx.x; i < EE*DD/4; i += 256)
        ((float4*)sWg)[i] = ((const float4*)Wg)[i];
    __syncthreads();

    int warp = threadIdx.x >> 5;
    int lane = threadIdx.x & 31;

    for (int t = 0; t < 4; t++) {
        int n = blockIdx.x*32 + warp*4 + t;

        const float4* xr = (const float4*)(x + (size_t)n*DD);
        float4 xv[8];
        #pragma unroll
        for (int q = 0; q < 8; q++) xv[q] = xr[lane + q*32];

        float pr[EE];
        #pragma unroll
        for (int e = 0; e < EE; e++) {
            const float4* wr = (const float4*)(sWg + e*DD);
            float p = 0.f;
            #pragma unroll
            for (int q = 0; q < 8; q++) {
                float4 w = wr[lane + q*32];
                p += xv[q].x*w.x + xv[q].y*w.y + xv[q].z*w.z + xv[q].w*w.w;
            }
            #pragma unroll
            for (int off = 16; off; off >>= 1) p += __shfl_xor_sync(0xffffffffu, p, off);
            pr[e] = p;
        }
        float m = pr[0];
        #pragma unroll
        for (int e = 1; e < EE; e++) m = fmaxf(m, pr[e]);
        float s = 0.f;
        #pragma unroll
        for (int e = 0; e < EE; e++) { pr[e] = __expf(pr[e]-m); s += pr[e]; }
        float inv = 1.f/s;
        #pragma unroll
        for (int e = 0; e < EE; e++) pr[e] *= inv;

        int i1 = 0; float v1 = pr[0];
        #pragma unroll
        for (int e = 1; e < EE; e++) if (pr[e] > v1) { v1 = pr[e]; i1 = e; }
        int i2 = -1; float v2 = -1.f;
        #pragma unroll
        for (int e = 0; e < EE; e++) if (e != i1 && pr[e] > v2) { v2 = pr[e]; i2 = e; }

        if (lane == 0) {
            #pragma unroll
            for (int e = 0; e < EE; e++) g_scores[(size_t)n*EE + e] = pr[e];
            g_topk_idx[2*n]   = i1; g_topk_val[2*n]   = v1;
            g_topk_idx[2*n+1] = i2; g_topk_val[2*n+1] = v2;
            atomicAdd(&g_counts[i1], 1);
            atomicAdd(&g_counts[i2], 1);
        }
    }
}

// ---------------- setup (parallel, 1 block) ----------------
__global__ void setup_kernel() {
    __shared__ int ps[EE+1], cnt[EE];
    int tid = threadIdx.x;
    if (tid == 0) {
        int off = 0;
        for (int e = 0; e < EE; e++) {
            ps[e] = off;
            int c = g_counts[e];
            cnt[e] = c;
            off = (off + c + BM - 1)/BM*BM;
        }
        ps[EE] = off;
    }
    __syncthreads();
    if (tid <= EE) g_pstart[tid] = ps[tid];
    if (tid < MAXTILES) {
        int r0 = tid*BM, e = -1;
        #pragma unroll
        for (int ee = 0; ee < EE; ee++)
            if (r0 >= ps[ee] && r0 < ps[ee] + cnt[ee]) e = ee;
        g_tile_expert[tid] = e;
    }
}

// ---------------- fused assign + gather (one warp per TOKEN) ----------------
__global__ void __launch_bounds__(256) assign_gather_kernel(const float* __restrict__ x) {
    int warp = threadIdx.x >> 5;
    int lane = threadIdx.x & 31;
    int n = blockIdx.x*8 + warp;
    if (n >= NTOK) return;

    int slot = 0;
    if (lane < 2) {
        int p = 2*n + lane;
        int e = g_topk_idx[p];
        int pos = atomicAdd(&g_cursor[e], 1);
        slot = g_pstart[e] + pos;
        g_pair_w[slot]   = g_topk_val[p];
        g_slot_tok[slot] = n;
    }
    int slot0 = __shfl_sync(0xffffffffu, slot, 0);
    int slot1 = __shfl_sync(0xffffffffu, slot, 1);

    const float4* xr = (const float4*)(x + (size_t)n*DD);
    __half2* d0 = (__half2*)(g_xg + (size_t)slot0*DD);
    __half2* d1 = (__half2*)(g_xg + (size_t)slot1*DD);
    #pragma unroll
    for (int q = 0; q < 8; q++) {
        float4 v = xr[lane + q*32];
        __half2 a = __floats2half2_rn(v.x, v.y);
        __half2 b = __floats2half2_rn(v.z, v.w);
        d0[2*(lane + q*32)]     = a;
        d0[2*(lane + q*32) + 1] = b;
        d1[2*(lane + q*32)]     = a;
        d1[2*(lane + q*32) + 1] = b;
    }
}

// ---------------- flat fp32->fp16 conversions (side stream) ----------------
__global__ void conv13_kernel(const float* __restrict__ W1, const float* __restrict__ W3) {
    const float* src = blockIdx.z ? W3 : W1;
    __half* dst = blockIdx.z ? g_w3 : g_w1;
    size_t i = ((size_t)blockIdx.x*256 + threadIdx.x)*8;
    float4 v0 = *(const float4*)(src + i);
    float4 v1 = *(const float4*)(src + i + 4);
    __half2 h[4];
    h[0] = __floats2half2_rn(v0.x, v0.y);
    h[1] = __floats2half2_rn(v0.z, v0.w);
    h[2] = __floats2half2_rn(v1.x, v1.y);
    h[3] = __floats2half2_rn(v1.z, v1.w);
    *(uint4*)(dst + i) = *(uint4*)h;
}
__global__ void conv2_kernel(const float* __restrict__ W2) {
    size_t i = ((size_t)blockIdx.x*256 + threadIdx.x)*8;
    float4 v0 = *(const float4*)(W2 + i);
    float4 v1 = *(const float4*)(W2 + i + 4);
    __half2 h[4];
    h[0] = __floats2half2_rn(v0.x, v0.y);
    h[1] = __floats2half2_rn(v0.z, v0.w);
    h[2] = __floats2half2_rn(v1.x, v1.y);
    h[3] = __floats2half2_rn(v1.z, v1.w);
    *(uint4*)(g_w2 + i) = *(uint4*)h;
}

// ============================================================================
// GEMM1 (mma.sync fp16): z1 = X@W1, z3 = X@W3 (trans-B); h = silu(z1+b1)*(z3+b3)
// CTA 128x128, BK=32, 4-stage cp.async, ONE sync/iter (loads issued post-sync).
// All 12 ldsm hoisted per h16 group.
// ============================================================================
__global__ void __launch_bounds__(256) gemm1_kernel(const float* __restrict__ b1,
                                                    const float* __restrict__ b3) {
    int e = g_tile_expert[blockIdx.y];
    if (e < 0) return;
    int row0 = blockIdx.y * BM;
    int n0   = blockIdx.x * 128;

    extern __shared__ __align__(1024) char smem[];
    uint32_t sb = smem_u32(smem);

    int tid  = threadIdx.x;
    int lane = tid & 31;
    int wid  = tid >> 5;
    int wm   = wid >> 2;
    int wn   = wid & 3;

    const __half* sA  = g_xg + (size_t)row0*DD;
    const __half* sW1 = g_w1 + (size_t)e*DD*HH + n0;
    const __half* sW3 = g_w3 + (size_t)e*DD*HH + n0;

    #define G1_LOAD(stage, it) do { \
        uint32_t bs = sb + (uint32_t)(stage)*(TILEA + 2*TILEW); \
        int k0 = (it)*32; \
        _Pragma("unroll") \
        for (int hf = 0; hf < 2; hf++) { \
            int idx = hf*256 + tid; \
            int ar = idx >> 2, ac = idx & 3; \
            cpasync16(bs + (uint32_t)ar*STRA + ac*16, sA + (size_t)ar*DD + k0 + ac*8); \
            int wr = idx >> 4, wc = idx & 15; \
            size_t gw = (size_t)(k0 + wr)*HH + wc*8; \
            uint32_t sw = (uint32_t)wr*STRB + wc*16; \
            cpasync16(bs + TILEA + sw, sW1 + gw); \
            cpasync16(bs + TILEA + TILEW + sw, sW3 + gw); \
        } \
    } while (0)

    float acc1[4][4][4], acc3[4][4][4];
    #pragma unroll
    for (int i = 0; i < 4; i++)
        #pragma unroll
        for (int j = 0; j < 4; j++)
            #pragma unroll
            for (int q = 0; q < 4; q++) { acc1[i][j][q] = 0.f; acc3[i][j][q] = 0.f; }

    int lr = (lane & 7) + 8*((lane >> 3) & 1);
    int lk = (lane >> 4) * 16;
    int bg = lane >> 3, br = lane & 7;
    uint32_t laneB = (uint32_t)((bg & 1)*8 + br)*STRB + (uint32_t)(bg >> 1)*16;

    const int NIT = DD/32;   // 32
    G1_LOAD(0, 0); CP_COMMIT();
    G1_LOAD(1, 1); CP_COMMIT();
    G1_LOAD(2, 2); CP_COMMIT();

    for (int it = 0; it < NIT; it++) {
        CP_WAIT2();
        __syncthreads();
        if (it + 3 < NIT) G1_LOAD((it+3)&3, it+3);
        CP_COMMIT();

        uint32_t bs  = sb + (uint32_t)(it&3)*(TILEA + 2*TILEW);
        uint32_t aA  = bs + (uint32_t)(wm*64 + lr)*STRA + lk;
        uint32_t bW1 = bs + TILEA + laneB + (uint32_t)(wn*32)*2;
        uint32_t bW3 = bW1 + TILEW;

        #pragma unroll
        for (int h16 = 0; h16 < 2; h16++) {
            uint32_t koA = h16*32;
            uint32_t koB = (uint32_t)(h16*16)*STRB;
            uint32_t Ah[4][4], b1f[2][4], b3f[2][4];
            #pragma unroll
            for (int mt = 0; mt < 4; mt++)
                ldmx4(Ah[mt], aA + mt*(16*STRA) + koA);
            #pragma unroll
            for (int np = 0; np < 2; np++) {
                ldmx4t(b1f[np], bW1 + koB + np*32);
                ldmx4t(b3f[np], bW3 + koB + np*32);
            }
            #pragma unroll
            for (int np = 0; np < 2; np++)
                #pragma unroll
                for (int s = 0; s < 2; s++) {
                    int nt = np*2 + s;
                    #pragma unroll
                    for (int mt = 0; mt < 4; mt++) {
                        mma16816(acc1[mt][nt], Ah[mt], b1f[np][2*s], b1f[np][2*s+1]);
                        mma16816(acc3[mt][nt], Ah[mt], b3f[np][2*s], b3f[np][2*s+1]);
                    }
                }
        }
    }

    int qrow = lane >> 2, qcol = lane & 3;
    #pragma unroll
    for (int nt = 0; nt < 4; nt++) {
        int col = n0 + wn*32 + nt*8 + qcol*2;
        float2 bb1 = *(const float2*)(b1 + e*HH + col);
        float2 bb3 = *(const float2*)(b3 + e*HH + col);
        #pragma unroll
        for (int mt = 0; mt < 4; mt++) {
            #pragma unroll
            for (int hrow = 0; hrow < 2; hrow++) {
                int r = row0 + wm*64 + mt*16 + qrow + hrow*8;
                float z1a = acc1[mt][nt][2*hrow]   + bb1.x;
                float z1b = acc1[mt][nt][2*hrow+1] + bb1.y;
                float z3a = acc3[mt][nt][2*hrow]   + bb3.x;
                float z3b = acc3[mt][nt][2*hrow+1] + bb3.y;
                float ha = (z1a / (1.f + __expf(-z1a))) * z3a;
                float hb = (z1b / (1.f + __expf(-z1b))) * z3b;
                *reinterpret_cast<__half2*>(g_h + (size_t)r*HH + col) =
                    __floats2half2_rn(ha, hb);
            }
        }
    }
}

// ============================================================================
// GEMM2 (mma.sync fp16): out[tok] += (h @ W2 + b2) * route_w  via red.add.v2
// 4-stage, 2 CTAs/SM, one sync/iter, ldsm hoisted.
// ============================================================================
__global__ void __launch_bounds__(256, 2) gemm2_kernel(const float* __restrict__ b2,
                                                       float* __restrict__ out) {
    int e = g_tile_expert[blockIdx.y];
    if (e < 0) return;
    int row0 = blockIdx.y * BM;
    int n0   = blockIdx.x * 128;

    extern __shared__ __align__(1024) char smem[];
    uint32_t sb = smem_u32(smem);

    int tid  = threadIdx.x;
    int lane = tid & 31;
    int wid  = tid >> 5;
    int wm   = wid >> 2;
    int wn   = wid & 3;

    const __half* sA = g_h  + (size_t)row0*HH;
    const __half* sW = g_w2 + (size_t)e*HH*DD + n0;

    #define G2_LOAD(stage, it) do { \
        uint32_t bs = sb + (uint32_t)(stage)*(TILEA + TILEW); \
        int k0 = (it)*32; \
        _Pragma("unroll") \
        for (int hf = 0; hf < 2; hf++) { \
            int idx = hf*256 + tid; \
            int ar = idx >> 2, ac = idx & 3; \
            cpasync16(bs + (uint32_t)ar*STRA + ac*16, sA + (size_t)ar*HH + k0 + ac*8); \
            int wr = idx >> 4, wc = idx & 15; \
            cpasync16(bs + TILEA + (uint32_t)wr*STRB + wc*16, \
                      sW + (size_t)(k0 + wr)*DD + wc*8); \
        } \
    } while (0)

    float acc[4][4][4];
    #pragma unroll
    for (int i = 0; i < 4; i++)
        #pragma unroll
        for (int j = 0; j < 4; j++)
            #pragma unroll
            for (int q = 0; q < 4; q++) acc[i][j][q] = 0.f;

    int lr = (lane & 7) + 8*((lane >> 3) & 1);
    int lk = (lane >> 4) * 16;
    int bg = lane >> 3, br = lane & 7;
    uint32_t laneB = (uint32_t)((bg & 1)*8 + br)*STRB + (uint32_t)(bg >> 1)*16;

    const int NIT = HH/32;   // 64
    G2_LOAD(0, 0); CP_COMMIT();
    G2_LOAD(1, 1); CP_COMMIT();
    G2_LOAD(2, 2); CP_COMMIT();

    for (int it = 0; it < NIT; it++) {
        CP_WAIT2();
        __syncthreads();
        if (it + 3 < NIT) G2_LOAD((it+3)&3, it+3);
        CP_COMMIT();

        uint32_t bs = sb + (uint32_t)(it&3)*(TILEA + TILEW);
        uint32_t aA = bs + (uint32_t)(wm*64 + lr)*STRA + lk;
        uint32_t bW = bs + TILEA + laneB + (uint32_t)(wn*32)*2;

        #pragma unroll
        for (int h16 = 0; h16 < 2; h16++) {
            uint32_t koA = h16*32;
            uint32_t koB = (uint32_t)(h16*16)*STRB;
            uint32_t Ah[4][4], bf[2][4];
            #pragma unroll
            for (int mt = 0; mt < 4; mt++)
                ldmx4(Ah[mt], aA + mt*(16*STRA) + koA);
            #pragma unroll
            for (int np = 0; np < 2; np++)
                ldmx4t(bf[np], bW + koB + np*32);
            #pragma unroll
            for (int np = 0; np < 2; np++)
                #pragma unroll
                for (int s = 0; s < 2; s++) {
                    int nt = np*2 + s;
                    #pragma unroll
                    for (int mt = 0; mt < 4; mt++)
                        mma16816(acc[mt][nt], Ah[mt], bf[np][2*s], bf[np][2*s+1]);
                }
        }
    }

    // epilogue: atomically accumulate (acc + b2) * w into out[tok]
    int qrow = lane >> 2, qcol = lane & 3;
    #pragma unroll
    for (int mt = 0; mt < 4; mt++) {
        #pragma unroll
        for (int hrow = 0; hrow < 2; hrow++) {
            int r = row0 + wm*64 + mt*16 + qrow + hrow*8;
            int tok = g_slot_tok[r];
            if (tok < 0) continue;
            float wv = g_pair_w[r];
            float* orow = out + (size_t)tok*DD;
            #pragma unroll
            for (int nt = 0; nt < 4; nt++) {
                int col = n0 + wn*32 + nt*8 + qcol*2;
                float2 bb = *(const float2*)(b2 + e*DD + col);
                redadd2(orow + col,
                        (acc[mt][nt][2*hrow]   + bb.x) * wv,
                        (acc[mt][nt][2*hrow+1] + bb.y) * wv);
            }
        }
    }
}

// ---------------- aux loss (1024 threads, fixed-order reduction) -------------
__global__ void __launch_bounds__(1024) aux_kernel(float* __restrict__ out, int has_aux) {
    __shared__ float red[1024];
    int tid = threadIdx.x;
    int e = tid & 7;
    float p = 0.f;
    for (int n = tid >> 3; n < NTOK; n += 128) p += g_scores[(size_t)n*EE + e];
    red[tid] = p;
    __syncthreads();
    for (int s = 512; s >= 8; s >>= 1) {
        if (tid < s) red[tid] += red[tid + s];
        __syncthreads();
    }
    if (tid == 0 && has_aux) {
        float aux = 0.f;
        for (int ee = 0; ee < EE; ee++) {
            float f = (float)g_counts[ee] / (float)(NTOK*KTOP);
            float P = red[ee] / (float)NTOK;
            aux += f*P;
        }
        out[(size_t)NTOK*DD] = 0.01f * (float)EE * aux;
    }
}

// ---------------- launch (fork-join: conversions + zeroout overlap) ----------
extern "C" void kernel_launch(void* const* d_in, const int* in_sizes, int n_in,
                              void* d_out, int out_size) {
    const float* x  = (const float*)d_in[0];
    const float* Wg = (const float*)d_in[1];
    const float* W1 = (const float*)d_in[2];
    const float* b1 = (const float*)d_in[3];
    const float* W2 = (const float*)d_in[4];
    const float* b2 = (const float*)d_in[5];
    const float* W3 = (const float*)d_in[6];
    const float* b3 = (const float*)d_in[7];
    float* out = (float*)d_out;

    const int G1_SMEM = 4*(TILEA + 2*TILEW);   // 110592
    const int G2_SMEM = 4*(TILEA + TILEW);     // 75776
    cudaFuncSetAttribute(gemm1_kernel, cudaFuncAttributeMaxDynamicSharedMemorySize, G1_SMEM);
    cudaFuncSetAttribute(gemm2_kernel, cudaFuncAttributeMaxDynamicSharedMemorySize, G2_SMEM);

    int n4 = out_size/4;
    int ntail = out_size - n4*4;
    int zgrid = (n4 + 255)/256;

    cudaStream_t s2 = 0;
    cudaEvent_t evFork = 0, evW13 = 0, evW2 = 0;
    bool forked = (cudaStreamCreateWithFlags(&s2, cudaStreamNonBlocking) == cudaSuccess)
               && (cudaEventCreateWithFlags(&evFork, cudaEventDisableTiming) == cudaSuccess)
               && (cudaEventCreateWithFlags(&evW13,  cudaEventDisableTiming) == cudaSuccess)
               && (cudaEventCreateWithFlags(&evW2,   cudaEventDisableTiming) == cudaSuccess);

    if (forked) {
        cudaEventRecord(evFork, 0);
        cudaStreamWaitEvent(s2, evFork, 0);
        conv13_kernel<<<dim3((EE*DD*HH)/(256*8), 1, 2), 256, 0, s2>>>(W1, W3);
        cudaEventRecord(evW13, s2);
        zeroout_kernel<<<zgrid, 256, 0, s2>>>(out, n4, ntail);
        conv2_kernel<<<dim3((EE*DD*HH)/(256*8), 1, 1), 256, 0, s2>>>(W2);
        cudaEventRecord(evW2, s2);
    } else {
        conv13_kernel<<<dim3((EE*DD*HH)/(256*8), 1, 2), 256>>>(W1, W3);
        zeroout_kernel<<<zgrid, 256>>>(out, n4, ntail);
        conv2_kernel<<<dim3((EE*DD*HH)/(256*8), 1, 1), 256>>>(W2);
    }

    init_kernel<<<(MAXPAD + 255)/256, 256>>>();
    gate_kernel<<<NTOK/32, 256>>>(x, Wg);
    setup_kernel<<<1, 256>>>();
    assign_gather_kernel<<<NTOK/8, 256>>>(x);

    if (forked) cudaStreamWaitEvent(0, evW13, 0);
    gemm1_kernel<<<dim3(HH/128, MAXTILES), 256, G1_SMEM>>>(b1, b3);
    if (forked) cudaStreamWaitEvent(0, evW2, 0);
    gemm2_kernel<<<dim3(DD/128, MAXTILES), 256, G2_SMEM>>>(b2, out);
    aux_kernel<<<1, 1024>>>(out, out_size > NTOK*DD ? 1 : 0);
}

// round 11
// speedup vs baseline: 6.3694x; 1.1680x over previous
#include <cuda_runtime.h>
#include <cuda_bf16.h>
#include <cuda_fp16.h>
#include <math.h>
#include <stdint.h>

#define DD     1024
#define HH     2048
#define EE     8
#define NTOK   8192
#define KTOP   2
#define NP     (NTOK*KTOP)      // 16384
#define BM     128
#define MAXPAD (NP + EE*BM)     // 17408
#define MAXTILES (MAXPAD/BM)    // 136

#define STRA   80               // A smem row stride (32 fp16 = 64B + 16B pad)
#define TILEA  (128*STRA)       // 10240
#define STRB   272              // GEMM2 B smem row stride (128 fp16 + pad)
#define TILEW  (32*STRB)        // 8704
#define STRB1  144               // GEMM1 B smem row stride (64 fp16 + pad)
#define TILEW1 (32*STRB1)        // 4608

// ---------------- device scratch ----------------
__device__ float g_pair_w[MAXPAD];
__device__ int   g_slot_tok[MAXPAD];   // slot -> token (-1 = pad)
__device__ int   g_topk_idx[NP];
__device__ float g_topk_val[NP];
__device__ float g_scores[NTOK*EE];
__device__ int   g_counts[EE];
__device__ int   g_cursor[EE];
__device__ int   g_pstart[EE+1];
__device__ int   g_tile_expert[MAXTILES];

__device__ __align__(16) __half g_xg [(size_t)MAXPAD*DD];      // fp16 x (gathered)
__device__ __align__(16) __half g_w1 [(size_t)EE*DD*HH];       // fp16 W1 [E][D][H]
__device__ __align__(16) __half g_w3 [(size_t)EE*DD*HH];
__device__ __align__(16) __half g_w2 [(size_t)EE*HH*DD];       // fp16 W2 [E][H][D]
__device__ __align__(16) __half g_h  [(size_t)MAXPAD*HH];      // fp16 h

// ---------------- PTX helpers (baseline PTX only) ----------------
__device__ __forceinline__ uint32_t smem_u32(const void* p){
    uint32_t a;
    asm("{ .reg .u64 t; cvta.to.shared.u64 t, %1; cvt.u32.u64 %0, t; }" : "=r"(a) : "l"(p));
    return a;
}
__device__ __forceinline__ void cpasync16(uint32_t dst, const void* src){
    asm volatile("cp.async.cg.shared.global [%0], [%1], 16;" :: "r"(dst), "l"(src));
}
#define CP_COMMIT() asm volatile("cp.async.commit_group;" ::: "memory")
#define CP_WAIT2()  asm volatile("cp.async.wait_group 2;" ::: "memory")

__device__ __forceinline__ void ldmx4(uint32_t (&r)[4], uint32_t addr){
    asm volatile("ldmatrix.sync.aligned.m8n8.x4.shared.b16 {%0,%1,%2,%3}, [%4];"
        : "=r"(r[0]), "=r"(r[1]), "=r"(r[2]), "=r"(r[3]) : "r"(addr));
}
__device__ __forceinline__ void ldmx4t(uint32_t (&r)[4], uint32_t addr){
    asm volatile("ldmatrix.sync.aligned.m8n8.x4.trans.shared.b16 {%0,%1,%2,%3}, [%4];"
        : "=r"(r[0]), "=r"(r[1]), "=r"(r[2]), "=r"(r[3]) : "r"(addr));
}
__device__ __forceinline__ void mma16816(float (&c)[4], const uint32_t (&a)[4],
                                         uint32_t b0, uint32_t b1){
    asm volatile(
        "mma.sync.aligned.m16n8k16.row.col.f32.f16.f16.f32 "
        "{%0,%1,%2,%3}, {%4,%5,%6,%7}, {%8,%9}, {%0,%1,%2,%3};"
        : "+f"(c[0]), "+f"(c[1]), "+f"(c[2]), "+f"(c[3])
        : "r"(a[0]), "r"(a[1]), "r"(a[2]), "r"(a[3]), "r"(b0), "r"(b1));
}
__device__ __forceinline__ void redadd2(float* p, float a, float b){
    asm volatile("red.global.add.v2.f32 [%0], {%1, %2};"
        :: "l"(p), "f"(a), "f"(b) : "memory");
}

// ---------------- init: counters + slot_tok pads ----------------
__global__ void init_kernel() {
    int i = blockIdx.x*blockDim.x + threadIdx.x;
    if (i < MAXPAD) g_slot_tok[i] = -1;
    if (i < EE) { g_counts[i] = 0; g_cursor[i] = 0; }
}

// ---------------- zero the output (side stream) ----------------
__global__ void zeroout_kernel(float* __restrict__ out, int n4, int ntail) {
    int i = blockIdx.x*blockDim.x + threadIdx.x;
    if (i < n4) ((float4*)out)[i] = make_float4(0.f,0.f,0.f,0.f);
    if (i < ntail) out[(size_t)n4*4 + i] = 0.f;
}

// ---------------- gating: 4 tokens per warp, Wg staged once per block --------
__global__ void __launch_bounds__(256) gate_kernel(const float* __restrict__ x,
                                                   const float* __restrict__ Wg) {
    __shared__ float sWg[EE*DD];
    for (int i = threadIdx.x; i < EE*DD/4; i += 256)
        ((float4*)sWg)[i] = ((const float4*)Wg)[i];
    __syncthreads();

    int warp = threadIdx.x >> 5;
    int lane = threadIdx.x & 31;

    for (int t = 0; t < 4; t++) {
        int n = blockIdx.x*32 + warp*4 + t;

        const float4* xr = (const float4*)(x + (size_t)n*DD);
        float4 xv[8];
        #pragma unroll
        for (int q = 0; q < 8; q++) xv[q] = xr[lane + q*32];

        float pr[EE];
        #pragma unroll
        for (int e = 0; e < EE; e++) {
            const float4* wr = (const float4*)(sWg + e*DD);
            float p = 0.f;
            #pragma unroll
            for (int q = 0; q < 8; q++) {
                float4 w = wr[lane + q*32];
                p += xv[q].x*w.x + xv[q].y*w.y + xv[q].z*w.z + xv[q].w*w.w;
            }
            #pragma unroll
            for (int off = 16; off; off >>= 1) p += __shfl_xor_sync(0xffffffffu, p, off);
            pr[e] = p;
        }
        float m = pr[0];
        #pragma unroll
        for (int e = 1; e < EE; e++) m = fmaxf(m, pr[e]);
        float s = 0.f;
        #pragma unroll
        for (int e = 0; e < EE; e++) { pr[e] = __expf(pr[e]-m); s += pr[e]; }
        float inv = 1.f/s;
        #pragma unroll
        for (int e = 0; e < EE; e++) pr[e] *= inv;

        int i1 = 0; float v1 = pr[0];
        #pragma unroll
        for (int e = 1; e < EE; e++) if (pr[e] > v1) { v1 = pr[e]; i1 = e; }
        int i2 = -1; float v2 = -1.f;
        #pragma unroll
        for (int e = 0; e < EE; e++) if (e != i1 && pr[e] > v2) { v2 = pr[e]; i2 = e; }

        if (lane == 0) {
            #pragma unroll
            for (int e = 0; e < EE; e++) g_scores[(size_t)n*EE + e] = pr[e];
            g_topk_idx[2*n]   = i1; g_topk_val[2*n]   = v1;
            g_topk_idx[2*n+1] = i2; g_topk_val[2*n+1] = v2;
            atomicAdd(&g_counts[i1], 1);
            atomicAdd(&g_counts[i2], 1);
        }
    }
}

// ---------------- setup (parallel, 1 block) ----------------
__global__ void setup_kernel() {
    __shared__ int ps[EE+1], cnt[EE];
    int tid = threadIdx.x;
    if (tid == 0) {
        int off = 0;
        for (int e = 0; e < EE; e++) {
            ps[e] = off;
            int c = g_counts[e];
            cnt[e] = c;
            off = (off + c + BM - 1)/BM*BM;
        }
        ps[EE] = off;
    }
    __syncthreads();
    if (tid <= EE) g_pstart[tid] = ps[tid];
    if (tid < MAXTILES) {
        int r0 = tid*BM, e = -1;
        #pragma unroll
        for (int ee = 0; ee < EE; ee++)
            if (r0 >= ps[ee] && r0 < ps[ee] + cnt[ee]) e = ee;
        g_tile_expert[tid] = e;
    }
}

// ---------------- fused assign + gather (one warp per TOKEN) ----------------
__global__ void __launch_bounds__(256) assign_gather_kernel(const float* __restrict__ x) {
    int warp = threadIdx.x >> 5;
    int lane = threadIdx.x & 31;
    int n = blockIdx.x*8 + warp;
    if (n >= NTOK) return;

    int slot = 0;
    if (lane < 2) {
        int p = 2*n + lane;
        int e = g_topk_idx[p];
        int pos = atomicAdd(&g_cursor[e], 1);
        slot = g_pstart[e] + pos;
        g_pair_w[slot]   = g_topk_val[p];
        g_slot_tok[slot] = n;
    }
    int slot0 = __shfl_sync(0xffffffffu, slot, 0);
    int slot1 = __shfl_sync(0xffffffffu, slot, 1);

    const float4* xr = (const float4*)(x + (size_t)n*DD);
    __half2* d0 = (__half2*)(g_xg + (size_t)slot0*DD);
    __half2* d1 = (__half2*)(g_xg + (size_t)slot1*DD);
    #pragma unroll
    for (int q = 0; q < 8; q++) {
        float4 v = xr[lane + q*32];
        __half2 a = __floats2half2_rn(v.x, v.y);
        __half2 b = __floats2half2_rn(v.z, v.w);
        d0[2*(lane + q*32)]     = a;
        d0[2*(lane + q*32) + 1] = b;
        d1[2*(lane + q*32)]     = a;
        d1[2*(lane + q*32) + 1] = b;
    }
}

// ---------------- flat fp32->fp16 conversions (side stream) ----------------
__global__ void conv13_kernel(const float* __restrict__ W1, const float* __restrict__ W3) {
    const float* src = blockIdx.z ? W3 : W1;
    __half* dst = blockIdx.z ? g_w3 : g_w1;
    size_t i = ((size_t)blockIdx.x*256 + threadIdx.x)*8;
    float4 v0 = *(const float4*)(src + i);
    float4 v1 = *(const float4*)(src + i + 4);
    __half2 h[4];
    h[0] = __floats2half2_rn(v0.x, v0.y);
    h[1] = __floats2half2_rn(v0.z, v0.w);
    h[2] = __floats2half2_rn(v1.x, v1.y);
    h[3] = __floats2half2_rn(v1.z, v1.w);
    *(uint4*)(dst + i) = *(uint4*)h;
}
__global__ void conv2_kernel(const float* __restrict__ W2) {
    size_t i = ((size_t)blockIdx.x*256 + threadIdx.x)*8;
    float4 v0 = *(const float4*)(W2 + i);
    float4 v1 = *(const float4*)(W2 + i + 4);
    __half2 h[4];
    h[0] = __floats2half2_rn(v0.x, v0.y);
    h[1] = __floats2half2_rn(v0.z, v0.w);
    h[2] = __floats2half2_rn(v1.x, v1.y);
    h[3] = __floats2half2_rn(v1.z, v1.w);
    *(uint4*)(g_w2 + i) = *(uint4*)h;
}

// ============================================================================
// GEMM1 (mma.sync fp16): z1 = X@W1, z3 = X@W3 (trans-B); h = silu(z1+b1)*(z3+b3)
// CTA 128(M)x64(N), BK=32, 4-stage cp.async, 2 CTAs/SM. 8 warps 4(M)x2(N),
// warp tile 32x32. One sync per iter; all ldsm hoisted per h16 group.
// ============================================================================
__global__ void __launch_bounds__(256, 2) gemm1_kernel(const float* __restrict__ b1,
                                                       const float* __restrict__ b3) {
    int e = g_tile_expert[blockIdx.y];
    if (e < 0) return;
    int row0 = blockIdx.y * BM;
    int n0   = blockIdx.x * 64;

    extern __shared__ __align__(1024) char smem[];
    uint32_t sb = smem_u32(smem);

    int tid  = threadIdx.x;
    int lane = tid & 31;
    int wid  = tid >> 5;
    int wm   = wid >> 1;      // 0..3
    int wn   = wid & 1;       // 0..1

    const __half* sA  = g_xg + (size_t)row0*DD;
    const __half* sW1 = g_w1 + (size_t)e*DD*HH + n0;
    const __half* sW3 = g_w3 + (size_t)e*DD*HH + n0;

    // per stage: A 128x32 (512 cp), W1 32x64 (256 cp), W3 32x64 (256 cp)
    #define G1_LOAD(stage, it) do { \
        uint32_t bs = sb + (uint32_t)(stage)*(TILEA + 2*TILEW1); \
        int k0 = (it)*32; \
        _Pragma("unroll") \
        for (int hf = 0; hf < 2; hf++) { \
            int idx = hf*256 + tid; \
            int ar = idx >> 2, ac = idx & 3; \
            cpasync16(bs + (uint32_t)ar*STRA + ac*16, sA + (size_t)ar*DD + k0 + ac*8); \
        } \
        { \
            int wr = tid >> 3, wc = tid & 7; \
            size_t gw = (size_t)(k0 + wr)*HH + wc*8; \
            uint32_t sw = (uint32_t)wr*STRB1 + wc*16; \
            cpasync16(bs + TILEA + sw, sW1 + gw); \
            cpasync16(bs + TILEA + TILEW1 + sw, sW3 + gw); \
        } \
    } while (0)

    float acc1[2][4][4], acc3[2][4][4];
    #pragma unroll
    for (int i = 0; i < 2; i++)
        #pragma unroll
        for (int j = 0; j < 4; j++)
            #pragma unroll
            for (int q = 0; q < 4; q++) { acc1[i][j][q] = 0.f; acc3[i][j][q] = 0.f; }

    int lr = (lane & 7) + 8*((lane >> 3) & 1);
    int lk = (lane >> 4) * 16;
    int bg = lane >> 3, br = lane & 7;
    uint32_t laneB = (uint32_t)((bg & 1)*8 + br)*STRB1 + (uint32_t)(bg >> 1)*16;

    const int NIT = DD/32;   // 32
    G1_LOAD(0, 0); CP_COMMIT();
    G1_LOAD(1, 1); CP_COMMIT();
    G1_LOAD(2, 2); CP_COMMIT();

    for (int it = 0; it < NIT; it++) {
        CP_WAIT2();
        __syncthreads();
        if (it + 3 < NIT) G1_LOAD((it+3)&3, it+3);
        CP_COMMIT();

        uint32_t bs  = sb + (uint32_t)(it&3)*(TILEA + 2*TILEW1);
        uint32_t aA  = bs + (uint32_t)(wm*32 + lr)*STRA + lk;
        uint32_t bW1 = bs + TILEA + laneB + (uint32_t)(wn*32)*2;
        uint32_t bW3 = bW1 + TILEW1;

        #pragma unroll
        for (int h16 = 0; h16 < 2; h16++) {
            uint32_t koA = h16*32;
            uint32_t koB = (uint32_t)(h16*16)*STRB1;
            uint32_t Ah[2][4], b1f[2][4], b3f[2][4];
            #pragma unroll
            for (int mt = 0; mt < 2; mt++)
                ldmx4(Ah[mt], aA + mt*(16*STRA) + koA);
            #pragma unroll
            for (int np = 0; np < 2; np++) {
                ldmx4t(b1f[np], bW1 + koB + np*32);
                ldmx4t(b3f[np], bW3 + koB + np*32);
            }
            #pragma unroll
            for (int np = 0; np < 2; np++)
                #pragma unroll
                for (int s = 0; s < 2; s++) {
                    int nt = np*2 + s;
                    #pragma unroll
                    for (int mt = 0; mt < 2; mt++) {
                        mma16816(acc1[mt][nt], Ah[mt], b1f[np][2*s], b1f[np][2*s+1]);
                        mma16816(acc3[mt][nt], Ah[mt], b3f[np][2*s], b3f[np][2*s+1]);
                    }
                }
        }
    }

    int qrow = lane >> 2, qcol = lane & 3;
    #pragma unroll
    for (int nt = 0; nt < 4; nt++) {
        int col = n0 + wn*32 + nt*8 + qcol*2;
        float2 bb1 = *(const float2*)(b1 + e*HH + col);
        float2 bb3 = *(const float2*)(b3 + e*HH + col);
        #pragma unroll
        for (int mt = 0; mt < 2; mt++) {
            #pragma unroll
            for (int hrow = 0; hrow < 2; hrow++) {
                int r = row0 + wm*32 + mt*16 + qrow + hrow*8;
                float z1a = acc1[mt][nt][2*hrow]   + bb1.x;
                float z1b = acc1[mt][nt][2*hrow+1] + bb1.y;
                float z3a = acc3[mt][nt][2*hrow]   + bb3.x;
                float z3b = acc3[mt][nt][2*hrow+1] + bb3.y;
                float ha = (z1a / (1.f + __expf(-z1a))) * z3a;
                float hb = (z1b / (1.f + __expf(-z1b))) * z3b;
                *reinterpret_cast<__half2*>(g_h + (size_t)r*HH + col) =
                    __floats2half2_rn(ha, hb);
            }
        }
    }
}

// ============================================================================
// GEMM2 (mma.sync fp16): out[tok] += (h @ W2 + b2) * route_w  via red.add.v2
// 4-stage, 2 CTAs/SM, one sync/iter, ldsm hoisted.
// ============================================================================
__global__ void __launch_bounds__(256, 2) gemm2_kernel(const float* __restrict__ b2,
                                                       float* __restrict__ out) {
    int e = g_tile_expert[blockIdx.y];
    if (e < 0) return;
    int row0 = blockIdx.y * BM;
    int n0   = blockIdx.x * 128;

    extern __shared__ __align__(1024) char smem[];
    uint32_t sb = smem_u32(smem);

    int tid  = threadIdx.x;
    int lane = tid & 31;
    int wid  = tid >> 5;
    int wm   = wid >> 2;
    int wn   = wid & 3;

    const __half* sA = g_h  + (size_t)row0*HH;
    const __half* sW = g_w2 + (size_t)e*HH*DD + n0;

    #define G2_LOAD(stage, it) do { \
        uint32_t bs = sb + (uint32_t)(stage)*(TILEA + TILEW); \
        int k0 = (it)*32; \
        _Pragma("unroll") \
        for (int hf = 0; hf < 2; hf++) { \
            int idx = hf*256 + tid; \
            int ar = idx >> 2, ac = idx & 3; \
            cpasync16(bs + (uint32_t)ar*STRA + ac*16, sA + (size_t)ar*HH + k0 + ac*8); \
            int wr = idx >> 4, wc = idx & 15; \
            cpasync16(bs + TILEA + (uint32_t)wr*STRB + wc*16, \
                      sW + (size_t)(k0 + wr)*DD + wc*8); \
        } \
    } while (0)

    float acc[4][4][4];
    #pragma unroll
    for (int i = 0; i < 4; i++)
        #pragma unroll
        for (int j = 0; j < 4; j++)
            #pragma unroll
            for (int q = 0; q < 4; q++) acc[i][j][q] = 0.f;

    int lr = (lane & 7) + 8*((lane >> 3) & 1);
    int lk = (lane >> 4) * 16;
    int bg = lane >> 3, br = lane & 7;
    uint32_t laneB = (uint32_t)((bg & 1)*8 + br)*STRB + (uint32_t)(bg >> 1)*16;

    const int NIT = HH/32;   // 64
    G2_LOAD(0, 0); CP_COMMIT();
    G2_LOAD(1, 1); CP_COMMIT();
    G2_LOAD(2, 2); CP_COMMIT();

    for (int it = 0; it < NIT; it++) {
        CP_WAIT2();
        __syncthreads();
        if (it + 3 < NIT) G2_LOAD((it+3)&3, it+3);
        CP_COMMIT();

        uint32_t bs = sb + (uint32_t)(it&3)*(TILEA + TILEW);
        uint32_t aA = bs + (uint32_t)(wm*64 + lr)*STRA + lk;
        uint32_t bW = bs + TILEA + laneB + (uint32_t)(wn*32)*2;

        #pragma unroll
        for (int h16 = 0; h16 < 2; h16++) {
            uint32_t koA = h16*32;
            uint32_t koB = (uint32_t)(h16*16)*STRB;
            uint32_t Ah[4][4], bf[2][4];
            #pragma unroll
            for (int mt = 0; mt < 4; mt++)
                ldmx4(Ah[mt], aA + mt*(16*STRA) + koA);
            #pragma unroll
            for (int np = 0; np < 2; np++)
                ldmx4t(bf[np], bW + koB + np*32);
            #pragma unroll
            for (int np = 0; np < 2; np++)
                #pragma unroll
                for (int s = 0; s < 2; s++) {
                    int nt = np*2 + s;
                    #pragma unroll
                    for (int mt = 0; mt < 4; mt++)
                        mma16816(acc[mt][nt], Ah[mt], bf[np][2*s], bf[np][2*s+1]);
                }
        }
    }

    // epilogue: atomically accumulate (acc + b2) * w into out[tok]
    int qrow = lane >> 2, qcol = lane & 3;
    #pragma unroll
    for (int mt = 0; mt < 4; mt++) {
        #pragma unroll
        for (int hrow = 0; hrow < 2; hrow++) {
            int r = row0 + wm*64 + mt*16 + qrow + hrow*8;
            int tok = g_slot_tok[r];
            if (tok < 0) continue;
            float wv = g_pair_w[r];
            float* orow = out + (size_t)tok*DD;
            #pragma unroll
            for (int nt = 0; nt < 4; nt++) {
                int col = n0 + wn*32 + nt*8 + qcol*2;
                float2 bb = *(const float2*)(b2 + e*DD + col);
                redadd2(orow + col,
                        (acc[mt][nt][2*hrow]   + bb.x) * wv,
                        (acc[mt][nt][2*hrow+1] + bb.y) * wv);
            }
        }
    }
}

// ---------------- aux loss (1024 threads, fixed-order reduction) -------------
__global__ void __launch_bounds__(1024) aux_kernel(float* __restrict__ out, int has_aux) {
    __shared__ float red[1024];
    int tid = threadIdx.x;
    int e = tid & 7;
    float p = 0.f;
    for (int n = tid >> 3; n < NTOK; n += 128) p += g_scores[(size_t)n*EE + e];
    red[tid] = p;
    __syncthreads();
    for (int s = 512; s >= 8; s >>= 1) {
        if (tid < s) red[tid] += red[tid + s];
        __syncthreads();
    }
    if (tid == 0 && has_aux) {
        float aux = 0.f;
        for (int ee = 0; ee < EE; ee++) {
            float f = (float)g_counts[ee] / (float)(NTOK*KTOP);
            float P = red[ee] / (float)NTOK;
            aux += f*P;
        }
        out[(size_t)NTOK*DD] = 0.01f * (float)EE * aux;
    }
}

// ---------------- launch (fork-join: conversions + zeroout overlap) ----------
extern "C" void kernel_launch(void* const* d_in, const int* in_sizes, int n_in,
                              void* d_out, int out_size) {
    const float* x  = (const float*)d_in[0];
    const float* Wg = (const float*)d_in[1];
    const float* W1 = (const float*)d_in[2];
    const float* b1 = (const float*)d_in[3];
    const float* W2 = (const float*)d_in[4];
    const float* b2 = (const float*)d_in[5];
    const float* W3 = (const float*)d_in[6];
    const float* b3 = (const float*)d_in[7];
    float* out = (float*)d_out;

    const int G1_SMEM = 4*(TILEA + 2*TILEW1);  // 77824
    const int G2_SMEM = 4*(TILEA + TILEW);     // 75776
    cudaFuncSetAttribute(gemm1_kernel, cudaFuncAttributeMaxDynamicSharedMemorySize, G1_SMEM);
    cudaFuncSetAttribute(gemm2_kernel, cudaFuncAttributeMaxDynamicSharedMemorySize, G2_SMEM);

    int n4 = out_size/4;
    int ntail = out_size - n4*4;
    int zgrid = (n4 + 255)/256;

    cudaStream_t s2 = 0;
    cudaEvent_t evFork = 0, evW13 = 0, evW2 = 0;
    bool forked = (cudaStreamCreateWithFlags(&s2, cudaStreamNonBlocking) == cudaSuccess)
               && (cudaEventCreateWithFlags(&evFork, cudaEventDisableTiming) == cudaSuccess)
               && (cudaEventCreateWithFlags(&evW13,  cudaEventDisableTiming) == cudaSuccess)
               && (cudaEventCreateWithFlags(&evW2,   cudaEventDisableTiming) == cudaSuccess);

    if (forked) {
        cudaEventRecord(evFork, 0);
        cudaStreamWaitEvent(s2, evFork, 0);
        conv13_kernel<<<dim3((EE*DD*HH)/(256*8), 1, 2), 256, 0, s2>>>(W1, W3);
        cudaEventRecord(evW13, s2);
        zeroout_kernel<<<zgrid, 256, 0, s2>>>(out, n4, ntail);
        conv2_kernel<<<dim3((EE*DD*HH)/(256*8), 1, 1), 256, 0, s2>>>(W2);
        cudaEventRecord(evW2, s2);
    } else {
        conv13_kernel<<<dim3((EE*DD*HH)/(256*8), 1, 2), 256>>>(W1, W3);
        zeroout_kernel<<<zgrid, 256>>>(out, n4, ntail);
        conv2_kernel<<<dim3((EE*DD*HH)/(256*8), 1, 1), 256>>>(W2);
    }

    init_kernel<<<(MAXPAD + 255)/256, 256>>>();
    gate_kernel<<<NTOK/32, 256>>>(x, Wg);
    setup_kernel<<<1, 256>>>();
    assign_gather_kernel<<<NTOK/8, 256>>>(x);

    if (forked) cudaStreamWaitEvent(0, evW13, 0);
    gemm1_kernel<<<dim3(HH/64, MAXTILES), 256, G1_SMEM>>>(b1, b3);
    if (forked) cudaStreamWaitEvent(0, evW2, 0);
    gemm2_kernel<<<dim3(DD/128, MAXTILES), 256, G2_SMEM>>>(b2, out);
    aux_kernel<<<1, 1024>>>(out, out_size > NTOK*DD ? 1 : 0);
}